// round 1
// baseline (speedup 1.0000x reference)
#include <cuda_runtime.h>
#include <math.h>

// Problem constants
constexpr int B  = 8;
constexpr int S  = 1024;
constexpr int H  = 8;
constexpr int DK = 64;
constexpr int D  = 512;
constexpr int BH  = B * H;     // 64
constexpr int BHS = BH * S;    // 65536
constexpr int MR  = B * S;     // 8192 rows in projection GEMMs

// ---------------- device scratch (static: no allocations allowed) ----------
__device__ float g_qm[BHS * DK];
__device__ float g_qc[BHS * DK];   // holds qc, then sqrt(clip(qc)) in-place
__device__ float g_km[BHS * DK];
__device__ float g_kc[BHS * DK];   // holds kc, then sqrt(clip(kc)) in-place
__device__ float g_vm[BHS * DK];
__device__ float g_vc[BHS * DK];
__device__ float g_q2[BHS];        // sum(qm^2) per row
__device__ float g_qcs[BHS];       // sum(qc) per row
__device__ float g_k2[BHS];
__device__ float g_kcs[BHS];
__device__ float g_att[(size_t)BH * S * S];  // scores, rewritten to probs in-place
__device__ float g_cm[(size_t)MR * D];
__device__ float g_cc[(size_t)MR * D];

// ---------------- SGEMM: C = A[M=8192,K=512] @ W[512,512] + bias -----------
// mode 0: scatter output into head-major [B,H,S,DK] layout
// mode 1: plain row-major [M,D] output
__global__ void __launch_bounds__(256) u_sgemm(const float* __restrict__ A,
                                               const float* __restrict__ W,
                                               const float* __restrict__ bias,
                                               float* __restrict__ out,
                                               int mode)
{
    __shared__ float As[8][128];
    __shared__ float Bs[8][128];
    const int tid = threadIdx.x;
    const int m0 = blockIdx.y * 128;
    const int n0 = blockIdx.x * 128;
    const int aRow = tid >> 1, aCol = (tid & 1) * 4;
    const int bRow = tid >> 5, bCol = (tid & 31) * 4;
    const int ty = tid >> 4, tx = tid & 15;

    float acc[8][8];
#pragma unroll
    for (int i = 0; i < 8; i++)
#pragma unroll
        for (int j = 0; j < 8; j++) acc[i][j] = 0.f;

    const float* Ap = A + (size_t)(m0 + aRow) * D + aCol;
    const float* Wp = W + (size_t)bRow * D + n0 + bCol;

    for (int k0 = 0; k0 < D; k0 += 8) {
        float4 av = *(const float4*)(Ap + k0);
        As[aCol + 0][aRow] = av.x;
        As[aCol + 1][aRow] = av.y;
        As[aCol + 2][aRow] = av.z;
        As[aCol + 3][aRow] = av.w;
        float4 bv = *(const float4*)(Wp + (size_t)k0 * D);
        *(float4*)&Bs[bRow][bCol] = bv;
        __syncthreads();
#pragma unroll
        for (int kk = 0; kk < 8; kk++) {
            float4 a0 = *(const float4*)&As[kk][ty * 8];
            float4 a1 = *(const float4*)&As[kk][ty * 8 + 4];
            float4 b0 = *(const float4*)&Bs[kk][tx * 8];
            float4 b1 = *(const float4*)&Bs[kk][tx * 8 + 4];
            float ra[8] = {a0.x, a0.y, a0.z, a0.w, a1.x, a1.y, a1.z, a1.w};
            float rb[8] = {b0.x, b0.y, b0.z, b0.w, b1.x, b1.y, b1.z, b1.w};
#pragma unroll
            for (int i = 0; i < 8; i++)
#pragma unroll
                for (int j = 0; j < 8; j++) acc[i][j] += ra[i] * rb[j];
        }
        __syncthreads();
    }

#pragma unroll
    for (int i = 0; i < 8; i++) {
        const int m = m0 + ty * 8 + i;
#pragma unroll
        for (int j = 0; j < 8; j++) {
            const int n = n0 + tx * 8 + j;
            const float v = acc[i][j] + bias[n];
            if (mode == 0) {
                const int b = m >> 10, s = m & (S - 1);
                const int h = n >> 6,  d = n & 63;
                out[(((size_t)(b * H + h)) * S + s) * DK + d] = v;
            } else {
                out[(size_t)m * D + n] = v;
            }
        }
    }
}

// ---------------- per-row stats over DK=64 --------------------------------
// mode 0: osum = sum(x^2)   (for qm/km)
// mode 1: osum = sum(x); x <- sqrt(max(x,1e-24))  (for qc/kc)
__global__ void u_rowstats(float* __restrict__ data, float* __restrict__ osum, int mode)
{
    const int row  = blockIdx.x * 8 + (threadIdx.x >> 5);
    const int lane = threadIdx.x & 31;
    float* p = data + (size_t)row * DK;
    const float a = p[lane], b = p[lane + 32];
    float v = (mode == 0) ? (a * a + b * b) : (a + b);
#pragma unroll
    for (int o = 16; o; o >>= 1) v += __shfl_xor_sync(~0u, v, o);
    if (lane == 0) osum[row] = v;
    if (mode == 1) {
        p[lane]      = sqrtf(fmaxf(a, 1e-24f));
        p[lane + 32] = sqrtf(fmaxf(b, 1e-24f));
    }
}

// ---------------- scores: -(wdist)/sqrt(DK), 64x64 tiles, causal-skipped ---
__global__ void __launch_bounds__(256) u_scores()
{
    const int bh = blockIdx.z;
    const int qb = blockIdx.y * 64, kb = blockIdx.x * 64;
    if (kb > qb + 63) return;   // fully above diagonal

    __shared__ float Qs[64][65];   // [d][q]
    __shared__ float Ks[64][65];   // [d][k]
    const int tx = threadIdx.x, ty = threadIdx.y;
    const int tid = ty * 16 + tx;
    const size_t base = (size_t)bh * S * DK;

    float d1[4][4], d2[4][4];
#pragma unroll
    for (int i = 0; i < 4; i++)
#pragma unroll
        for (int j = 0; j < 4; j++) { d1[i][j] = 0.f; d2[i][j] = 0.f; }

    // phase 1: mean gram  qm . km
    for (int idx = tid; idx < 4096; idx += 256) {
        const int r = idx >> 6, d = idx & 63;
        Qs[d][r] = g_qm[base + (size_t)(qb + r) * DK + d];
        Ks[d][r] = g_km[base + (size_t)(kb + r) * DK + d];
    }
    __syncthreads();
#pragma unroll 4
    for (int d = 0; d < 64; d++) {
        float aq[4], ak[4];
#pragma unroll
        for (int i = 0; i < 4; i++) aq[i] = Qs[d][ty * 4 + i];
#pragma unroll
        for (int j = 0; j < 4; j++) ak[j] = Ks[d][tx * 4 + j];
#pragma unroll
        for (int i = 0; i < 4; i++)
#pragma unroll
            for (int j = 0; j < 4; j++) d1[i][j] += aq[i] * ak[j];
    }
    __syncthreads();

    // phase 2: cov gram  sqrt(clip(qc)) . sqrt(clip(kc))  (stored in g_qc/g_kc)
    for (int idx = tid; idx < 4096; idx += 256) {
        const int r = idx >> 6, d = idx & 63;
        Qs[d][r] = g_qc[base + (size_t)(qb + r) * DK + d];
        Ks[d][r] = g_kc[base + (size_t)(kb + r) * DK + d];
    }
    __syncthreads();
#pragma unroll 4
    for (int d = 0; d < 64; d++) {
        float aq[4], ak[4];
#pragma unroll
        for (int i = 0; i < 4; i++) aq[i] = Qs[d][ty * 4 + i];
#pragma unroll
        for (int j = 0; j < 4; j++) ak[j] = Ks[d][tx * 4 + j];
#pragma unroll
        for (int i = 0; i < 4; i++)
#pragma unroll
            for (int j = 0; j < 4; j++) d2[i][j] += aq[i] * ak[j];
    }

    const float* q2  = g_q2  + bh * S;
    const float* qcs = g_qcs + bh * S;
    const float* k2  = g_k2  + bh * S;
    const float* kcs = g_kcs + bh * S;
#pragma unroll
    for (int i = 0; i < 4; i++) {
        const int q = qb + ty * 4 + i;
        const float tq = q2[q] + qcs[q];
#pragma unroll
        for (int j = 0; j < 4; j++) {
            const int k = kb + tx * 4 + j;
            const float tk = k2[k] + kcs[k];
            const float wd = tq + tk - 2.f * (d1[i][j] + d2[i][j]);
            g_att[((size_t)bh * S + q) * S + k] = -wd * 0.125f;  // 1/sqrt(64)
        }
    }
}

// ---------------- block reduction helpers (256 threads, 8 warps) ----------
__device__ __forceinline__ float u_blkmax(float v, float* red)
{
    const int lane = threadIdx.x & 31, wid = threadIdx.x >> 5;
#pragma unroll
    for (int o = 16; o; o >>= 1) v = fmaxf(v, __shfl_xor_sync(~0u, v, o));
    __syncthreads();
    if (lane == 0) red[wid] = v;
    __syncthreads();
    float r = red[0];
#pragma unroll
    for (int i = 1; i < 8; i++) r = fmaxf(r, red[i]);
    return r;
}
__device__ __forceinline__ float u_blksum(float v, float* red)
{
    const int lane = threadIdx.x & 31, wid = threadIdx.x >> 5;
#pragma unroll
    for (int o = 16; o; o >>= 1) v += __shfl_xor_sync(~0u, v, o);
    __syncthreads();
    if (lane == 0) red[wid] = v;
    __syncthreads();
    float r = red[0];
#pragma unroll
    for (int i = 1; i < 8; i++) r += red[i];
    return r;
}

// ---------------- fused row kernel: softmax -> cumsum -> decay -> softmax --
// One block (256 thr) per (bh, q) row. Rewrites g_att row in-place with final
// attention probabilities (zeros beyond causal boundary; row q=0 all zero).
__global__ void __launch_bounds__(256) u_decay(const float* __restrict__ gammas)
{
    const int q  = blockIdx.x;
    const int bh = blockIdx.y;
    const int L  = q + 1;
    const int tid  = threadIdx.x;
    const int lane = tid & 31, wid = tid >> 5;
    float* row = g_att + ((size_t)bh * S + q) * S;

    const float g = gammas[bh & (H - 1)];
    const float gamma = -log1pf(expf(g));   // -softplus

    __shared__ float red[8];
    __shared__ float wsum[8];
    __shared__ float shtot;

    const int base = tid * 4;
    const float4 sv = *(const float4*)(row + base);
    float s[4] = {sv.x, sv.y, sv.z, sv.w};
    bool valid[4];
#pragma unroll
    for (int i = 0; i < 4; i++) valid[i] = (base + i) < L;

    // softmax #1
    float m = -3.402823466e+38f;
#pragma unroll
    for (int i = 0; i < 4; i++) if (valid[i]) m = fmaxf(m, s[i]);
    m = u_blkmax(m, red);

    float p[4], c[4];
    float run = 0.f;
#pragma unroll
    for (int i = 0; i < 4; i++) {
        p[i] = valid[i] ? expf(s[i] - m) : 0.f;
        run += p[i];
        c[i] = run;
    }

    // block inclusive scan of per-thread sums
    float x = run;
#pragma unroll
    for (int o = 1; o < 32; o <<= 1) {
        const float y = __shfl_up_sync(~0u, x, o);
        if (lane >= o) x += y;
    }
    const float texcl = x - run;
    if (lane == 31) wsum[wid] = x;
    __syncthreads();
    if (wid == 0 && lane < 8) {
        float w = wsum[lane];
#pragma unroll
        for (int o = 1; o < 8; o <<= 1) {
            const float y = __shfl_up_sync(0xffu, w, o);
            if (lane >= o) w += y;
        }
        wsum[lane] = w;
        if (lane == 7) shtot = w;
    }
    __syncthreads();
    const float off  = texcl + (wid ? wsum[wid - 1] : 0.f);
    const float invT = 1.f / shtot;

    // decay-modified logits
    float l[4];
#pragma unroll
    for (int i = 0; i < 4; i++) {
        const float cum  = (c[i] + off) * invT;       // normalized inclusive cumsum
        const float tail = fmaxf(1.f - cum, 0.f);     // disttot - distcum
        const float pos  = (float)(q - (base + i));   // |q-k| for k<=q
        const float dist = sqrtf(tail * pos);
        float eff = expf(gamma * dist);
        eff = fminf(fmaxf(eff, 1e-5f), 1e5f);
        l[i] = s[i] * eff;
    }

    // softmax #2
    float m2 = -3.402823466e+38f;
#pragma unroll
    for (int i = 0; i < 4; i++) if (valid[i]) m2 = fmaxf(m2, l[i]);
    m2 = u_blkmax(m2, red);

    float e[4];
    float es = 0.f;
#pragma unroll
    for (int i = 0; i < 4; i++) {
        e[i] = valid[i] ? expf(l[i] - m2) : 0.f;
        es += e[i];
    }
    es = u_blksum(es, red);
    const float invE = 1.f / es;

    float4 ov;
    ov.x = (q == 0) ? 0.f : e[0] * invE;
    ov.y = (q == 0) ? 0.f : e[1] * invE;
    ov.z = (q == 0) ? 0.f : e[2] * invE;
    ov.w = (q == 0) ? 0.f : e[3] * invE;
    *(float4*)(row + base) = ov;
}

// ---------------- AV: out_mean = sc @ vm, out_cov = sc^2 @ vc --------------
// One block per (bh, 64-row q-tile). Writes directly into [B,S,D] layout.
__global__ void __launch_bounds__(256) u_av()
{
    const int bh = blockIdx.y;
    const int qb = blockIdx.x * 64;
    __shared__ float Ssm[16][65];   // [k][q]
    __shared__ float Vms[16][68];   // [k][d]
    __shared__ float Vcs[16][68];
    const int tid = threadIdx.x;
    const int tx = tid & 15, ty = tid >> 4;
    const float* att = g_att + (size_t)bh * S * S;
    const size_t vb = (size_t)bh * S * DK;

    float am[4][4], ac[4][4];
#pragma unroll
    for (int i = 0; i < 4; i++)
#pragma unroll
        for (int j = 0; j < 4; j++) { am[i][j] = 0.f; ac[i][j] = 0.f; }

    for (int kb = 0; kb < qb + 64; kb += 16) {
        for (int idx = tid; idx < 1024; idx += 256) {
            const int qq = idx >> 4, kk = idx & 15;
            Ssm[kk][qq] = att[(size_t)(qb + qq) * S + kb + kk];
        }
        for (int idx = tid; idx < 1024; idx += 256) {
            const int kk = idx >> 6, dd = idx & 63;
            Vms[kk][dd] = g_vm[vb + (size_t)(kb + kk) * DK + dd];
            Vcs[kk][dd] = g_vc[vb + (size_t)(kb + kk) * DK + dd];
        }
        __syncthreads();
#pragma unroll
        for (int kk = 0; kk < 16; kk++) {
            float a[4], a2[4], bm[4], bc[4];
#pragma unroll
            for (int i = 0; i < 4; i++) { a[i] = Ssm[kk][ty * 4 + i]; a2[i] = a[i] * a[i]; }
#pragma unroll
            for (int j = 0; j < 4; j++) { bm[j] = Vms[kk][tx * 4 + j]; bc[j] = Vcs[kk][tx * 4 + j]; }
#pragma unroll
            for (int i = 0; i < 4; i++)
#pragma unroll
                for (int j = 0; j < 4; j++) {
                    am[i][j] += a[i] * bm[j];
                    ac[i][j] += a2[i] * bc[j];
                }
        }
        __syncthreads();
    }

    const int b = bh >> 3, h = bh & 7;
#pragma unroll
    for (int i = 0; i < 4; i++) {
        const int s = qb + ty * 4 + i;
#pragma unroll
        for (int j = 0; j < 4; j++) {
            const int col = h * DK + tx * 4 + j;
            g_cm[((size_t)(b * S + s)) * D + col] = am[i][j];
            g_cc[((size_t)(b * S + s)) * D + col] = ac[i][j];
        }
    }
}

// ---------------- host launcher --------------------------------------------
extern "C" void kernel_launch(void* const* d_in, const int* in_sizes, int n_in,
                              void* d_out, int out_size)
{
    const float* q_mean = (const float*)d_in[0];
    const float* q_cov  = (const float*)d_in[1];
    const float* k_mean = (const float*)d_in[2];
    const float* k_cov  = (const float*)d_in[3];
    const float* v_mean = (const float*)d_in[4];
    const float* v_cov  = (const float*)d_in[5];
    const float* Wqm = (const float*)d_in[6];  const float* bqm = (const float*)d_in[7];
    const float* Wqc = (const float*)d_in[8];  const float* bqc = (const float*)d_in[9];
    const float* Wkm = (const float*)d_in[10]; const float* bkm = (const float*)d_in[11];
    const float* Wkc = (const float*)d_in[12]; const float* bkc = (const float*)d_in[13];
    const float* Wvm = (const float*)d_in[14]; const float* bvm = (const float*)d_in[15];
    const float* Wvc = (const float*)d_in[16]; const float* bvc = (const float*)d_in[17];
    const float* Wom = (const float*)d_in[18]; const float* bom = (const float*)d_in[19];
    const float* Woc = (const float*)d_in[20]; const float* boc = (const float*)d_in[21];
    const float* gammas = (const float*)d_in[22];
    // d_in[23] = mask: known causal tril, handled analytically

    float* out = (float*)d_out;

    float *qm, *qc, *km, *kc, *vm, *vc, *q2, *qcs, *k2, *kcs, *cm, *cc;
    cudaGetSymbolAddress((void**)&qm,  g_qm);
    cudaGetSymbolAddress((void**)&qc,  g_qc);
    cudaGetSymbolAddress((void**)&km,  g_km);
    cudaGetSymbolAddress((void**)&kc,  g_kc);
    cudaGetSymbolAddress((void**)&vm,  g_vm);
    cudaGetSymbolAddress((void**)&vc,  g_vc);
    cudaGetSymbolAddress((void**)&q2,  g_q2);
    cudaGetSymbolAddress((void**)&qcs, g_qcs);
    cudaGetSymbolAddress((void**)&k2,  g_k2);
    cudaGetSymbolAddress((void**)&kcs, g_kcs);
    cudaGetSymbolAddress((void**)&cm,  g_cm);
    cudaGetSymbolAddress((void**)&cc,  g_cc);

    const dim3 gP(D / 128, MR / 128);  // (4, 64)

    // 6 input projections into head-major layout
    u_sgemm<<<gP, 256>>>(q_mean, Wqm, bqm, qm, 0);
    u_sgemm<<<gP, 256>>>(q_cov,  Wqc, bqc, qc, 0);
    u_sgemm<<<gP, 256>>>(k_mean, Wkm, bkm, km, 0);
    u_sgemm<<<gP, 256>>>(k_cov,  Wkc, bkc, kc, 0);
    u_sgemm<<<gP, 256>>>(v_mean, Wvm, bvm, vm, 0);
    u_sgemm<<<gP, 256>>>(v_cov,  Wvc, bvc, vc, 0);

    // row statistics (+ in-place sqrt(clip) for covariances)
    u_rowstats<<<BHS / 8, 256>>>(qm, q2, 0);
    u_rowstats<<<BHS / 8, 256>>>(km, k2, 0);
    u_rowstats<<<BHS / 8, 256>>>(qc, qcs, 1);
    u_rowstats<<<BHS / 8, 256>>>(kc, kcs, 1);

    // Wasserstein scores (causal tiles only)
    u_scores<<<dim3(S / 64, S / 64, BH), dim3(16, 16)>>>();

    // fused softmax -> cumsum -> decay -> softmax, in-place
    u_decay<<<dim3(S, BH), 256>>>(gammas);

    // attention-value products (mean + cov fused)
    u_av<<<dim3(S / 64, BH), 256>>>();

    // output projections straight into d_out (mean first, then cov)
    u_sgemm<<<gP, 256>>>(cm, Wom, bom, out, 1);
    u_sgemm<<<gP, 256>>>(cc, Woc, boc, out + (size_t)MR * D, 1);
}

// round 3
// speedup vs baseline: 1.2646x; 1.2646x over previous
#include <cuda_runtime.h>
#include <cuda_bf16.h>
#include <mma.h>
#include <math.h>
#include <stdint.h>

using namespace nvcuda;

// Problem constants
constexpr int B  = 8;
constexpr int S  = 1024;
constexpr int H  = 8;
constexpr int DK = 64;
constexpr int D  = 512;
constexpr int BH  = B * H;     // 64
constexpr int BHS = BH * S;    // 65536
constexpr int MR  = B * S;     // 8192 rows in projection GEMMs

// ---------------- device scratch (static: no allocations allowed) ----------
__device__ float g_qm[BHS * DK];
__device__ float g_qc[BHS * DK];
__device__ float g_km[BHS * DK];
__device__ float g_kc[BHS * DK];
__device__ float g_vm[BHS * DK];
__device__ float g_vc[BHS * DK];
__device__ float g_q2[BHS];
__device__ float g_qcs[BHS];
__device__ float g_k2[BHS];
__device__ float g_kcs[BHS];
__device__ float g_att[(size_t)BH * S * S];
__device__ float g_cm[(size_t)MR * D];
__device__ float g_cc[(size_t)MR * D];
// bf16 split staging (reused across sequential GEMMs)
__device__ __nv_bfloat16 g_ah[(size_t)MR * D];
__device__ __nv_bfloat16 g_al[(size_t)MR * D];
__device__ __nv_bfloat16 g_wth[D * D];   // W^T hi  [N=512][K=512]
__device__ __nv_bfloat16 g_wtl[D * D];   // W^T lo

// ---------------- fp32 -> bf16 hi/lo split (elementwise) -------------------
__global__ void u_split(const float* __restrict__ x,
                        __nv_bfloat16* __restrict__ h,
                        __nv_bfloat16* __restrict__ l)
{
    const int i = (blockIdx.x * 256 + threadIdx.x) * 4;
    const float4 v = *(const float4*)(x + i);
    __nv_bfloat16 h0 = __float2bfloat16(v.x), h1 = __float2bfloat16(v.y);
    __nv_bfloat16 h2 = __float2bfloat16(v.z), h3 = __float2bfloat16(v.w);
    __nv_bfloat162 hh0 = {h0, h1}, hh1 = {h2, h3};
    __nv_bfloat162 ll0 = {__float2bfloat16(v.x - __bfloat162float(h0)),
                          __float2bfloat16(v.y - __bfloat162float(h1))};
    __nv_bfloat162 ll1 = {__float2bfloat16(v.z - __bfloat162float(h2)),
                          __float2bfloat16(v.w - __bfloat162float(h3))};
    *(uint2*)(h + i) = make_uint2(*(uint32_t*)&hh0, *(uint32_t*)&hh1);
    *(uint2*)(l + i) = make_uint2(*(uint32_t*)&ll0, *(uint32_t*)&ll1);
}

// ---------------- W[K,N] -> W^T[N,K] bf16 hi/lo -----------------------------
__global__ void u_splitWt(const float* __restrict__ W,
                          __nv_bfloat16* __restrict__ th,
                          __nv_bfloat16* __restrict__ tl)
{
    __shared__ float tile[32][33];
    const int k0 = blockIdx.y * 32, n0 = blockIdx.x * 32;
    const int tx = threadIdx.x & 31, tw = threadIdx.x >> 5;
    for (int r = tw; r < 32; r += 8)
        tile[r][tx] = W[(size_t)(k0 + r) * D + n0 + tx];
    __syncthreads();
    for (int r = tw; r < 32; r += 8) {
        const float v = tile[tx][r];                 // = W[k0+tx][n0+r]
        const __nv_bfloat16 hv = __float2bfloat16(v);
        const size_t o = (size_t)(n0 + r) * D + k0 + tx;
        th[o] = hv;
        tl[o] = __float2bfloat16(v - __bfloat162float(hv));
    }
}

// ---------------- WMMA GEMM: C[M,N] = A[M,K]*W[K,N] + bias ------------------
// A as bf16 hi/lo [M,K] row-major; W as transposed bf16 hi/lo [N,K]
// (= col-major K x N for wmma matrix_b).
// 128x128 CTA tile, 8 warps (2 m x 4 n), each warp 64x32 (4x2 frags), BK=32.
// 3-term split product: Ah*Bh + Ah*Bl + Al*Bh (f32 accum).
// mode 0: scatter to head-major [B,H,S,DK]; mode 1: row-major [M,D].
constexpr int PITCH = 40;                 // bf16 pitch (80B: 16B-aligned, conflict-free)
constexpr int TILEB = 128 * PITCH * 2;    // 10240 bytes per staged matrix

__global__ void __launch_bounds__(256) u_wmma_gemm(
    const __nv_bfloat16* __restrict__ Ah, const __nv_bfloat16* __restrict__ Al,
    const __nv_bfloat16* __restrict__ Bh, const __nv_bfloat16* __restrict__ Bl,
    const float* __restrict__ bias, float* __restrict__ out, int mode)
{
    __shared__ __align__(16) char smem[4 * TILEB];   // 40 KB; epilogue reuses head
    __nv_bfloat16* sAh = (__nv_bfloat16*)(smem);
    __nv_bfloat16* sAl = (__nv_bfloat16*)(smem + TILEB);
    __nv_bfloat16* sBh = (__nv_bfloat16*)(smem + 2 * TILEB);
    __nv_bfloat16* sBl = (__nv_bfloat16*)(smem + 3 * TILEB);

    const int tid = threadIdx.x, wid = tid >> 5, lane = tid & 31;
    const int m0 = blockIdx.y * 128, n0 = blockIdx.x * 128;
    const int warp_m = wid >> 2, warp_n = wid & 3;   // 2 x 4

    wmma::fragment<wmma::accumulator, 16, 16, 16, float> acc[4][2];
#pragma unroll
    for (int mi = 0; mi < 4; mi++)
#pragma unroll
        for (int nj = 0; nj < 2; nj++) wmma::fill_fragment(acc[mi][nj], 0.f);

    for (int kt = 0; kt < D / 32; kt++) {
        const int k0 = kt * 32;
        // stage A/B hi+lo tiles: 128 rows x 32 bf16 each; 512 16B-chunks per matrix
#pragma unroll
        for (int i = 0; i < 2; i++) {
            const int c = tid + i * 256;
            const int r = c >> 2, cc = (c & 3) * 8;
            const int so = r * PITCH + cc;
            const size_t ao = (size_t)(m0 + r) * D + k0 + cc;
            const size_t bo = (size_t)(n0 + r) * D + k0 + cc;
            *(uint4*)(sAh + so) = *(const uint4*)(Ah + ao);
            *(uint4*)(sAl + so) = *(const uint4*)(Al + ao);
            *(uint4*)(sBh + so) = *(const uint4*)(Bh + bo);
            *(uint4*)(sBl + so) = *(const uint4*)(Bl + bo);
        }
        __syncthreads();

#pragma unroll
        for (int ks = 0; ks < 32; ks += 16) {
            wmma::fragment<wmma::matrix_a, 16, 16, 16, __nv_bfloat16, wmma::row_major> aH[4], aL[4];
#pragma unroll
            for (int mi = 0; mi < 4; mi++) {
                const int row = warp_m * 64 + mi * 16;
                wmma::load_matrix_sync(aH[mi], sAh + row * PITCH + ks, PITCH);
                wmma::load_matrix_sync(aL[mi], sAl + row * PITCH + ks, PITCH);
            }
#pragma unroll
            for (int nj = 0; nj < 2; nj++) {
                const int col = warp_n * 32 + nj * 16;
                wmma::fragment<wmma::matrix_b, 16, 16, 16, __nv_bfloat16, wmma::col_major> bH, bL;
                wmma::load_matrix_sync(bH, sBh + col * PITCH + ks, PITCH);
                wmma::load_matrix_sync(bL, sBl + col * PITCH + ks, PITCH);
#pragma unroll
                for (int mi = 0; mi < 4; mi++) {
                    wmma::mma_sync(acc[mi][nj], aH[mi], bH, acc[mi][nj]);
                    wmma::mma_sync(acc[mi][nj], aH[mi], bL, acc[mi][nj]);
                    wmma::mma_sync(acc[mi][nj], aL[mi], bH, acc[mi][nj]);
                }
            }
        }
        __syncthreads();
    }

    // epilogue: per-warp 16x16 scratch (reuses smem head; all mainloop reads done)
    float* epi = (float*)(smem) + wid * 256;
#pragma unroll
    for (int mi = 0; mi < 4; mi++) {
#pragma unroll
        for (int nj = 0; nj < 2; nj++) {
            wmma::store_matrix_sync(epi, acc[mi][nj], 16, wmma::mem_row_major);
            __syncwarp();
            const int r  = lane >> 1;
            const int c0 = (lane & 1) * 8;
            const int m  = m0 + warp_m * 64 + mi * 16 + r;
            const int n  = n0 + warp_n * 32 + nj * 16 + c0;
            float v[8];
#pragma unroll
            for (int c = 0; c < 8; c++) v[c] = epi[r * 16 + c0 + c] + bias[n + c];
            if (mode == 0) {
                const int b = m >> 10, s = m & (S - 1);
                const int h = n >> 6, d = n & 63;
                float* dst = out + (((size_t)(b * H + h)) * S + s) * DK + d;
                *(float4*)(dst)     = make_float4(v[0], v[1], v[2], v[3]);
                *(float4*)(dst + 4) = make_float4(v[4], v[5], v[6], v[7]);
            } else {
                float* dst = out + (size_t)m * D + n;
                *(float4*)(dst)     = make_float4(v[0], v[1], v[2], v[3]);
                *(float4*)(dst + 4) = make_float4(v[4], v[5], v[6], v[7]);
            }
            __syncwarp();
        }
    }
}

// ---------------- per-row stats over DK=64 --------------------------------
__global__ void u_rowstats(float* __restrict__ data, float* __restrict__ osum, int mode)
{
    const int row  = blockIdx.x * 8 + (threadIdx.x >> 5);
    const int lane = threadIdx.x & 31;
    float* p = data + (size_t)row * DK;
    const float a = p[lane], b = p[lane + 32];
    float v = (mode == 0) ? (a * a + b * b) : (a + b);
#pragma unroll
    for (int o = 16; o; o >>= 1) v += __shfl_xor_sync(~0u, v, o);
    if (lane == 0) osum[row] = v;
    if (mode == 1) {
        p[lane]      = sqrtf(fmaxf(a, 1e-24f));
        p[lane + 32] = sqrtf(fmaxf(b, 1e-24f));
    }
}

// ---------------- scores: -(wdist)/sqrt(DK), 64x64 tiles, causal-skipped ---
__global__ void __launch_bounds__(256) u_scores()
{
    const int bh = blockIdx.z;
    const int qb = blockIdx.y * 64, kb = blockIdx.x * 64;
    if (kb > qb + 63) return;

    __shared__ float Qs[64][65];
    __shared__ float Ks[64][65];
    const int tx = threadIdx.x, ty = threadIdx.y;
    const int tid = ty * 16 + tx;
    const size_t base = (size_t)bh * S * DK;

    float d1[4][4], d2[4][4];
#pragma unroll
    for (int i = 0; i < 4; i++)
#pragma unroll
        for (int j = 0; j < 4; j++) { d1[i][j] = 0.f; d2[i][j] = 0.f; }

    for (int idx = tid; idx < 4096; idx += 256) {
        const int r = idx >> 6, d = idx & 63;
        Qs[d][r] = g_qm[base + (size_t)(qb + r) * DK + d];
        Ks[d][r] = g_km[base + (size_t)(kb + r) * DK + d];
    }
    __syncthreads();
#pragma unroll 4
    for (int d = 0; d < 64; d++) {
        float aq[4], ak[4];
#pragma unroll
        for (int i = 0; i < 4; i++) aq[i] = Qs[d][ty * 4 + i];
#pragma unroll
        for (int j = 0; j < 4; j++) ak[j] = Ks[d][tx * 4 + j];
#pragma unroll
        for (int i = 0; i < 4; i++)
#pragma unroll
            for (int j = 0; j < 4; j++) d1[i][j] += aq[i] * ak[j];
    }
    __syncthreads();

    for (int idx = tid; idx < 4096; idx += 256) {
        const int r = idx >> 6, d = idx & 63;
        Qs[d][r] = g_qc[base + (size_t)(qb + r) * DK + d];
        Ks[d][r] = g_kc[base + (size_t)(kb + r) * DK + d];
    }
    __syncthreads();
#pragma unroll 4
    for (int d = 0; d < 64; d++) {
        float aq[4], ak[4];
#pragma unroll
        for (int i = 0; i < 4; i++) aq[i] = Qs[d][ty * 4 + i];
#pragma unroll
        for (int j = 0; j < 4; j++) ak[j] = Ks[d][tx * 4 + j];
#pragma unroll
        for (int i = 0; i < 4; i++)
#pragma unroll
            for (int j = 0; j < 4; j++) d2[i][j] += aq[i] * ak[j];
    }

    const float* q2  = g_q2  + bh * S;
    const float* qcs = g_qcs + bh * S;
    const float* k2  = g_k2  + bh * S;
    const float* kcs = g_kcs + bh * S;
#pragma unroll
    for (int i = 0; i < 4; i++) {
        const int q = qb + ty * 4 + i;
        const float tq = q2[q] + qcs[q];
#pragma unroll
        for (int j = 0; j < 4; j++) {
            const int k = kb + tx * 4 + j;
            const float tk = k2[k] + kcs[k];
            const float wd = tq + tk - 2.f * (d1[i][j] + d2[i][j]);
            g_att[((size_t)bh * S + q) * S + k] = -wd * 0.125f;
        }
    }
}

// ---------------- block reduction helpers ----------------------------------
__device__ __forceinline__ float u_blkmax(float v, float* red)
{
    const int lane = threadIdx.x & 31, wid = threadIdx.x >> 5;
#pragma unroll
    for (int o = 16; o; o >>= 1) v = fmaxf(v, __shfl_xor_sync(~0u, v, o));
    __syncthreads();
    if (lane == 0) red[wid] = v;
    __syncthreads();
    float r = red[0];
#pragma unroll
    for (int i = 1; i < 8; i++) r = fmaxf(r, red[i]);
    return r;
}
__device__ __forceinline__ float u_blksum(float v, float* red)
{
    const int lane = threadIdx.x & 31, wid = threadIdx.x >> 5;
#pragma unroll
    for (int o = 16; o; o >>= 1) v += __shfl_xor_sync(~0u, v, o);
    __syncthreads();
    if (lane == 0) red[wid] = v;
    __syncthreads();
    float r = red[0];
#pragma unroll
    for (int i = 1; i < 8; i++) r += red[i];
    return r;
}

// ---------------- fused row kernel: softmax -> cumsum -> decay -> softmax --
__global__ void __launch_bounds__(256) u_decay(const float* __restrict__ gammas)
{
    const int q  = blockIdx.x;
    const int bh = blockIdx.y;
    const int L  = q + 1;
    const int tid  = threadIdx.x;
    const int lane = tid & 31, wid = tid >> 5;
    float* row = g_att + ((size_t)bh * S + q) * S;

    const float g = gammas[bh & (H - 1)];
    const float gamma = -log1pf(expf(g));

    __shared__ float red[8];
    __shared__ float wsum[8];
    __shared__ float shtot;

    const int base = tid * 4;
    const float4 sv = *(const float4*)(row + base);
    float s[4] = {sv.x, sv.y, sv.z, sv.w};
    bool valid[4];
#pragma unroll
    for (int i = 0; i < 4; i++) valid[i] = (base + i) < L;

    float m = -3.402823466e+38f;
#pragma unroll
    for (int i = 0; i < 4; i++) if (valid[i]) m = fmaxf(m, s[i]);
    m = u_blkmax(m, red);

    float p[4], c[4];
    float run = 0.f;
#pragma unroll
    for (int i = 0; i < 4; i++) {
        p[i] = valid[i] ? expf(s[i] - m) : 0.f;
        run += p[i];
        c[i] = run;
    }

    float x = run;
#pragma unroll
    for (int o = 1; o < 32; o <<= 1) {
        const float y = __shfl_up_sync(~0u, x, o);
        if (lane >= o) x += y;
    }
    const float texcl = x - run;
    if (lane == 31) wsum[wid] = x;
    __syncthreads();
    if (wid == 0 && lane < 8) {
        float w = wsum[lane];
#pragma unroll
        for (int o = 1; o < 8; o <<= 1) {
            const float y = __shfl_up_sync(0xffu, w, o);
            if (lane >= o) w += y;
        }
        wsum[lane] = w;
        if (lane == 7) shtot = w;
    }
    __syncthreads();
    const float off  = texcl + (wid ? wsum[wid - 1] : 0.f);
    const float invT = 1.f / shtot;

    float l[4];
#pragma unroll
    for (int i = 0; i < 4; i++) {
        const float cum  = (c[i] + off) * invT;
        const float tail = fmaxf(1.f - cum, 0.f);
        const float pos  = (float)(q - (base + i));
        const float dist = sqrtf(tail * pos);
        float eff = expf(gamma * dist);
        eff = fminf(fmaxf(eff, 1e-5f), 1e5f);
        l[i] = s[i] * eff;
    }

    float m2 = -3.402823466e+38f;
#pragma unroll
    for (int i = 0; i < 4; i++) if (valid[i]) m2 = fmaxf(m2, l[i]);
    m2 = u_blkmax(m2, red);

    float e[4];
    float es = 0.f;
#pragma unroll
    for (int i = 0; i < 4; i++) {
        e[i] = valid[i] ? expf(l[i] - m2) : 0.f;
        es += e[i];
    }
    es = u_blksum(es, red);
    const float invE = 1.f / es;

    float4 ov;
    ov.x = (q == 0) ? 0.f : e[0] * invE;
    ov.y = (q == 0) ? 0.f : e[1] * invE;
    ov.z = (q == 0) ? 0.f : e[2] * invE;
    ov.w = (q == 0) ? 0.f : e[3] * invE;
    *(float4*)(row + base) = ov;
}

// ---------------- AV: out_mean = sc @ vm, out_cov = sc^2 @ vc --------------
__global__ void __launch_bounds__(256) u_av()
{
    const int bh = blockIdx.y;
    const int qb = blockIdx.x * 64;
    __shared__ float Ssm[16][65];
    __shared__ float Vms[16][68];
    __shared__ float Vcs[16][68];
    const int tid = threadIdx.x;
    const int tx = tid & 15, ty = tid >> 4;
    const float* att = g_att + (size_t)bh * S * S;
    const size_t vb = (size_t)bh * S * DK;

    float am[4][4], ac[4][4];
#pragma unroll
    for (int i = 0; i < 4; i++)
#pragma unroll
        for (int j = 0; j < 4; j++) { am[i][j] = 0.f; ac[i][j] = 0.f; }

    for (int kb = 0; kb < qb + 64; kb += 16) {
        for (int idx = tid; idx < 1024; idx += 256) {
            const int qq = idx >> 4, kk = idx & 15;
            Ssm[kk][qq] = att[(size_t)(qb + qq) * S + kb + kk];
        }
        for (int idx = tid; idx < 1024; idx += 256) {
            const int kk = idx >> 6, dd = idx & 63;
            Vms[kk][dd] = g_vm[vb + (size_t)(kb + kk) * DK + dd];
            Vcs[kk][dd] = g_vc[vb + (size_t)(kb + kk) * DK + dd];
        }
        __syncthreads();
#pragma unroll
        for (int kk = 0; kk < 16; kk++) {
            float a[4], a2[4], bm[4], bc[4];
#pragma unroll
            for (int i = 0; i < 4; i++) { a[i] = Ssm[kk][ty * 4 + i]; a2[i] = a[i] * a[i]; }
#pragma unroll
            for (int j = 0; j < 4; j++) { bm[j] = Vms[kk][tx * 4 + j]; bc[j] = Vcs[kk][tx * 4 + j]; }
#pragma unroll
            for (int i = 0; i < 4; i++)
#pragma unroll
                for (int j = 0; j < 4; j++) {
                    am[i][j] += a[i] * bm[j];
                    ac[i][j] += a2[i] * bc[j];
                }
        }
        __syncthreads();
    }

    const int b = bh >> 3, h = bh & 7;
#pragma unroll
    for (int i = 0; i < 4; i++) {
        const int s = qb + ty * 4 + i;
#pragma unroll
        for (int j = 0; j < 4; j++) {
            const int col = h * DK + tx * 4 + j;
            g_cm[((size_t)(b * S + s)) * D + col] = am[i][j];
            g_cc[((size_t)(b * S + s)) * D + col] = ac[i][j];
        }
    }
}

// ---------------- host launcher --------------------------------------------
extern "C" void kernel_launch(void* const* d_in, const int* in_sizes, int n_in,
                              void* d_out, int out_size)
{
    const float* q_mean = (const float*)d_in[0];
    const float* q_cov  = (const float*)d_in[1];
    const float* k_mean = (const float*)d_in[2];
    const float* k_cov  = (const float*)d_in[3];
    const float* v_mean = (const float*)d_in[4];
    const float* v_cov  = (const float*)d_in[5];
    const float* Wqm = (const float*)d_in[6];  const float* bqm = (const float*)d_in[7];
    const float* Wqc = (const float*)d_in[8];  const float* bqc = (const float*)d_in[9];
    const float* Wkm = (const float*)d_in[10]; const float* bkm = (const float*)d_in[11];
    const float* Wkc = (const float*)d_in[12]; const float* bkc = (const float*)d_in[13];
    const float* Wvm = (const float*)d_in[14]; const float* bvm = (const float*)d_in[15];
    const float* Wvc = (const float*)d_in[16]; const float* bvc = (const float*)d_in[17];
    const float* Wom = (const float*)d_in[18]; const float* bom = (const float*)d_in[19];
    const float* Woc = (const float*)d_in[20]; const float* boc = (const float*)d_in[21];
    const float* gammas = (const float*)d_in[22];

    float* out = (float*)d_out;

    float *qm, *qc, *km, *kc, *vm, *vc, *q2, *qcs, *k2, *kcs, *cm, *cc;
    __nv_bfloat16 *ah, *al, *wth, *wtl;
    cudaGetSymbolAddress((void**)&qm,  g_qm);
    cudaGetSymbolAddress((void**)&qc,  g_qc);
    cudaGetSymbolAddress((void**)&km,  g_km);
    cudaGetSymbolAddress((void**)&kc,  g_kc);
    cudaGetSymbolAddress((void**)&vm,  g_vm);
    cudaGetSymbolAddress((void**)&vc,  g_vc);
    cudaGetSymbolAddress((void**)&q2,  g_q2);
    cudaGetSymbolAddress((void**)&qcs, g_qcs);
    cudaGetSymbolAddress((void**)&k2,  g_k2);
    cudaGetSymbolAddress((void**)&kcs, g_kcs);
    cudaGetSymbolAddress((void**)&cm,  g_cm);
    cudaGetSymbolAddress((void**)&cc,  g_cc);
    cudaGetSymbolAddress((void**)&ah,  g_ah);
    cudaGetSymbolAddress((void**)&al,  g_al);
    cudaGetSymbolAddress((void**)&wth, g_wth);
    cudaGetSymbolAddress((void**)&wtl, g_wtl);

    const dim3 gG(D / 128, MR / 128);      // (4, 64)
    const dim3 gS(MR * D / 1024);          // split grid: 4096
    const dim3 gW(D / 32, D / 32);         // (16, 16)

    struct { const float *X, *W, *bias; float* dst; } proj[6] = {
        {q_mean, Wqm, bqm, qm}, {q_cov, Wqc, bqc, qc},
        {k_mean, Wkm, bkm, km}, {k_cov, Wkc, bkc, kc},
        {v_mean, Wvm, bvm, vm}, {v_cov, Wvc, bvc, vc},
    };
    for (int i = 0; i < 6; i++) {
        u_split<<<gS, 256>>>(proj[i].X, ah, al);
        u_splitWt<<<gW, 256>>>(proj[i].W, wth, wtl);
        u_wmma_gemm<<<gG, 256>>>(ah, al, wth, wtl, proj[i].bias, proj[i].dst, 0);
    }

    u_rowstats<<<BHS / 8, 256>>>(qm, q2, 0);
    u_rowstats<<<BHS / 8, 256>>>(km, k2, 0);
    u_rowstats<<<BHS / 8, 256>>>(qc, qcs, 1);
    u_rowstats<<<BHS / 8, 256>>>(kc, kcs, 1);

    u_scores<<<dim3(S / 64, S / 64, BH), dim3(16, 16)>>>();
    u_decay<<<dim3(S, BH), 256>>>(gammas);
    u_av<<<dim3(S / 64, BH), 256>>>();

    // output projections
    u_split<<<gS, 256>>>(cm, ah, al);
    u_splitWt<<<gW, 256>>>(Wom, wth, wtl);
    u_wmma_gemm<<<gG, 256>>>(ah, al, wth, wtl, bom, out, 1);
    u_split<<<gS, 256>>>(cc, ah, al);
    u_splitWt<<<gW, 256>>>(Woc, wth, wtl);
    u_wmma_gemm<<<gG, 256>>>(ah, al, wth, wtl, boc, out + (size_t)MR * D, 1);
}

// round 4
// speedup vs baseline: 1.7377x; 1.3741x over previous
#include <cuda_runtime.h>
#include <cuda_bf16.h>
#include <mma.h>
#include <math.h>
#include <stdint.h>

using namespace nvcuda;

// Problem constants
constexpr int B  = 8;
constexpr int S  = 1024;
constexpr int H  = 8;
constexpr int DK = 64;
constexpr int D  = 512;
constexpr int BH  = B * H;     // 64
constexpr int BHS = BH * S;    // 65536
constexpr int MR  = B * S;     // 8192 rows in projection GEMMs

// ---------------- device scratch (static: no allocations allowed) ----------
__device__ float g_qm[BHS * DK];
__device__ float g_qc[BHS * DK];   // -> sqrt(clip) in place after rowstats
__device__ float g_km[BHS * DK];
__device__ float g_kc[BHS * DK];
__device__ float g_vm[BHS * DK];
__device__ float g_vc[BHS * DK];
__device__ float g_q2[BHS];
__device__ float g_qcs[BHS];
__device__ float g_k2[BHS];
__device__ float g_kcs[BHS];
__device__ float g_att[(size_t)BH * S * S];
__device__ float g_cm[(size_t)MR * D];
__device__ float g_cc[(size_t)MR * D];
// bf16 split staging
__device__ __nv_bfloat16 g_ah[(size_t)MR * D];
__device__ __nv_bfloat16 g_al[(size_t)MR * D];
__device__ __nv_bfloat16 g_wth[D * D];
__device__ __nv_bfloat16 g_wtl[D * D];
// concat [qm | sqrt(qc)] and [km | sqrt(kc)]: [BH, S, 128] bf16 hi/lo
__device__ __nv_bfloat16 g_Qh[(size_t)BHS * 128];
__device__ __nv_bfloat16 g_Ql[(size_t)BHS * 128];
__device__ __nv_bfloat16 g_Kh[(size_t)BHS * 128];
__device__ __nv_bfloat16 g_Kl[(size_t)BHS * 128];
// vm/vc bf16 hi/lo, head-major [BH,S,64]
__device__ __nv_bfloat16 g_Vmh[(size_t)BHS * DK];
__device__ __nv_bfloat16 g_Vml[(size_t)BHS * DK];
__device__ __nv_bfloat16 g_Vch[(size_t)BHS * DK];
__device__ __nv_bfloat16 g_Vcl[(size_t)BHS * DK];

// ---------------- fp32 -> bf16 hi/lo split (flat) ---------------------------
__global__ void u_split(const float* __restrict__ x,
                        __nv_bfloat16* __restrict__ h,
                        __nv_bfloat16* __restrict__ l)
{
    const int i = (blockIdx.x * 256 + threadIdx.x) * 4;
    const float4 v = *(const float4*)(x + i);
    __nv_bfloat16 h0 = __float2bfloat16(v.x), h1 = __float2bfloat16(v.y);
    __nv_bfloat16 h2 = __float2bfloat16(v.z), h3 = __float2bfloat16(v.w);
    __nv_bfloat162 hh0 = {h0, h1}, hh1 = {h2, h3};
    __nv_bfloat162 ll0 = {__float2bfloat16(v.x - __bfloat162float(h0)),
                          __float2bfloat16(v.y - __bfloat162float(h1))};
    __nv_bfloat162 ll1 = {__float2bfloat16(v.z - __bfloat162float(h2)),
                          __float2bfloat16(v.w - __bfloat162float(h3))};
    *(uint2*)(h + i) = make_uint2(*(uint32_t*)&hh0, *(uint32_t*)&hh1);
    *(uint2*)(l + i) = make_uint2(*(uint32_t*)&ll0, *(uint32_t*)&ll1);
}

// ---------------- split [BHS,64] fp32 into cols of [BHS,128] bf16 -----------
__global__ void u_split2(const float* __restrict__ src,
                         __nv_bfloat16* __restrict__ h,
                         __nv_bfloat16* __restrict__ l, int colOff)
{
    const int t = blockIdx.x * 256 + threadIdx.x;
    const int i = t * 4;
    const int row = i >> 6, col = i & 63;
    const float4 v = *(const float4*)(src + i);
    __nv_bfloat16 h0 = __float2bfloat16(v.x), h1 = __float2bfloat16(v.y);
    __nv_bfloat16 h2 = __float2bfloat16(v.z), h3 = __float2bfloat16(v.w);
    __nv_bfloat162 hh0 = {h0, h1}, hh1 = {h2, h3};
    __nv_bfloat162 ll0 = {__float2bfloat16(v.x - __bfloat162float(h0)),
                          __float2bfloat16(v.y - __bfloat162float(h1))};
    __nv_bfloat162 ll1 = {__float2bfloat16(v.z - __bfloat162float(h2)),
                          __float2bfloat16(v.w - __bfloat162float(h3))};
    const size_t o = (size_t)row * 128 + colOff + col;
    *(uint2*)(h + o) = make_uint2(*(uint32_t*)&hh0, *(uint32_t*)&hh1);
    *(uint2*)(l + o) = make_uint2(*(uint32_t*)&ll0, *(uint32_t*)&ll1);
}

// ---------------- W[K,N] -> W^T[N,K] bf16 hi/lo -----------------------------
__global__ void u_splitWt(const float* __restrict__ W,
                          __nv_bfloat16* __restrict__ th,
                          __nv_bfloat16* __restrict__ tl)
{
    __shared__ float tile[32][33];
    const int k0 = blockIdx.y * 32, n0 = blockIdx.x * 32;
    const int tx = threadIdx.x & 31, tw = threadIdx.x >> 5;
    for (int r = tw; r < 32; r += 8)
        tile[r][tx] = W[(size_t)(k0 + r) * D + n0 + tx];
    __syncthreads();
    for (int r = tw; r < 32; r += 8) {
        const float v = tile[tx][r];
        const __nv_bfloat16 hv = __float2bfloat16(v);
        const size_t o = (size_t)(n0 + r) * D + k0 + tx;
        th[o] = hv;
        tl[o] = __float2bfloat16(v - __bfloat162float(hv));
    }
}

// ---------------- WMMA GEMM (projections): C = A*W + bias ------------------
constexpr int PITCH = 40;
constexpr int TILEB = 128 * PITCH * 2;

__global__ void __launch_bounds__(256) u_wmma_gemm(
    const __nv_bfloat16* __restrict__ Ah, const __nv_bfloat16* __restrict__ Al,
    const __nv_bfloat16* __restrict__ Bh, const __nv_bfloat16* __restrict__ Bl,
    const float* __restrict__ bias, float* __restrict__ out, int mode)
{
    __shared__ __align__(16) char smem[4 * TILEB];
    __nv_bfloat16* sAh = (__nv_bfloat16*)(smem);
    __nv_bfloat16* sAl = (__nv_bfloat16*)(smem + TILEB);
    __nv_bfloat16* sBh = (__nv_bfloat16*)(smem + 2 * TILEB);
    __nv_bfloat16* sBl = (__nv_bfloat16*)(smem + 3 * TILEB);

    const int tid = threadIdx.x, wid = tid >> 5, lane = tid & 31;
    const int m0 = blockIdx.y * 128, n0 = blockIdx.x * 128;
    const int warp_m = wid >> 2, warp_n = wid & 3;

    wmma::fragment<wmma::accumulator, 16, 16, 16, float> acc[4][2];
#pragma unroll
    for (int mi = 0; mi < 4; mi++)
#pragma unroll
        for (int nj = 0; nj < 2; nj++) wmma::fill_fragment(acc[mi][nj], 0.f);

    for (int kt = 0; kt < D / 32; kt++) {
        const int k0 = kt * 32;
#pragma unroll
        for (int i = 0; i < 2; i++) {
            const int c = tid + i * 256;
            const int r = c >> 2, cc = (c & 3) * 8;
            const int so = r * PITCH + cc;
            const size_t ao = (size_t)(m0 + r) * D + k0 + cc;
            const size_t bo = (size_t)(n0 + r) * D + k0 + cc;
            *(uint4*)(sAh + so) = *(const uint4*)(Ah + ao);
            *(uint4*)(sAl + so) = *(const uint4*)(Al + ao);
            *(uint4*)(sBh + so) = *(const uint4*)(Bh + bo);
            *(uint4*)(sBl + so) = *(const uint4*)(Bl + bo);
        }
        __syncthreads();

#pragma unroll
        for (int ks = 0; ks < 32; ks += 16) {
            wmma::fragment<wmma::matrix_a, 16, 16, 16, __nv_bfloat16, wmma::row_major> aH[4], aL[4];
#pragma unroll
            for (int mi = 0; mi < 4; mi++) {
                const int row = warp_m * 64 + mi * 16;
                wmma::load_matrix_sync(aH[mi], sAh + row * PITCH + ks, PITCH);
                wmma::load_matrix_sync(aL[mi], sAl + row * PITCH + ks, PITCH);
            }
#pragma unroll
            for (int nj = 0; nj < 2; nj++) {
                const int col = warp_n * 32 + nj * 16;
                wmma::fragment<wmma::matrix_b, 16, 16, 16, __nv_bfloat16, wmma::col_major> bH, bL;
                wmma::load_matrix_sync(bH, sBh + col * PITCH + ks, PITCH);
                wmma::load_matrix_sync(bL, sBl + col * PITCH + ks, PITCH);
#pragma unroll
                for (int mi = 0; mi < 4; mi++) {
                    wmma::mma_sync(acc[mi][nj], aH[mi], bH, acc[mi][nj]);
                    wmma::mma_sync(acc[mi][nj], aH[mi], bL, acc[mi][nj]);
                    wmma::mma_sync(acc[mi][nj], aL[mi], bH, acc[mi][nj]);
                }
            }
        }
        __syncthreads();
    }

    float* epi = (float*)(smem) + wid * 256;
#pragma unroll
    for (int mi = 0; mi < 4; mi++) {
#pragma unroll
        for (int nj = 0; nj < 2; nj++) {
            wmma::store_matrix_sync(epi, acc[mi][nj], 16, wmma::mem_row_major);
            __syncwarp();
            const int r  = lane >> 1;
            const int c0 = (lane & 1) * 8;
            const int m  = m0 + warp_m * 64 + mi * 16 + r;
            const int n  = n0 + warp_n * 32 + nj * 16 + c0;
            float v[8];
#pragma unroll
            for (int c = 0; c < 8; c++) v[c] = epi[r * 16 + c0 + c] + bias[n + c];
            if (mode == 0) {
                const int b = m >> 10, s = m & (S - 1);
                const int h = n >> 6, d = n & 63;
                float* dst = out + (((size_t)(b * H + h)) * S + s) * DK + d;
                *(float4*)(dst)     = make_float4(v[0], v[1], v[2], v[3]);
                *(float4*)(dst + 4) = make_float4(v[4], v[5], v[6], v[7]);
            } else {
                float* dst = out + (size_t)m * D + n;
                *(float4*)(dst)     = make_float4(v[0], v[1], v[2], v[3]);
                *(float4*)(dst + 4) = make_float4(v[4], v[5], v[6], v[7]);
            }
            __syncwarp();
        }
    }
}

// ---------------- WMMA scores: 128x128 causal tiles ------------------------
// scores[q,k] = 0.25*gram - 0.125*(tq[q]+tk[k]),  gram over 128-concat dim.
__global__ void __launch_bounds__(256) u_scores_wmma()
{
    __shared__ __align__(16) char smem[4 * TILEB];
    __nv_bfloat16* sQh = (__nv_bfloat16*)(smem);
    __nv_bfloat16* sQl = (__nv_bfloat16*)(smem + TILEB);
    __nv_bfloat16* sKh = (__nv_bfloat16*)(smem + 2 * TILEB);
    __nv_bfloat16* sKl = (__nv_bfloat16*)(smem + 3 * TILEB);

    const int bh = blockIdx.y;
    // triangular decode of blockIdx.x in [0,36): tq >= tk
    int tq = (int)((sqrtf(8.f * blockIdx.x + 1.f) - 1.f) * 0.5f);
    while ((tq + 1) * (tq + 2) / 2 <= (int)blockIdx.x) tq++;
    while (tq * (tq + 1) / 2 > (int)blockIdx.x) tq--;
    const int tk = blockIdx.x - tq * (tq + 1) / 2;
    const int qb = tq * 128, kb = tk * 128;

    const int tid = threadIdx.x, wid = tid >> 5, lane = tid & 31;
    const int warp_m = wid >> 2, warp_n = wid & 3;
    const __nv_bfloat16* Qh = g_Qh + ((size_t)bh * S + qb) * 128;
    const __nv_bfloat16* Ql = g_Ql + ((size_t)bh * S + qb) * 128;
    const __nv_bfloat16* Kh = g_Kh + ((size_t)bh * S + kb) * 128;
    const __nv_bfloat16* Kl = g_Kl + ((size_t)bh * S + kb) * 128;

    wmma::fragment<wmma::accumulator, 16, 16, 16, float> acc[4][2];
#pragma unroll
    for (int mi = 0; mi < 4; mi++)
#pragma unroll
        for (int nj = 0; nj < 2; nj++) wmma::fill_fragment(acc[mi][nj], 0.f);

#pragma unroll
    for (int kt = 0; kt < 4; kt++) {
        const int k0 = kt * 32;
#pragma unroll
        for (int i = 0; i < 2; i++) {
            const int c = tid + i * 256;
            const int r = c >> 2, cc = (c & 3) * 8;
            const int so = r * PITCH + cc;
            const size_t o = (size_t)r * 128 + k0 + cc;
            *(uint4*)(sQh + so) = *(const uint4*)(Qh + o);
            *(uint4*)(sQl + so) = *(const uint4*)(Ql + o);
            *(uint4*)(sKh + so) = *(const uint4*)(Kh + o);
            *(uint4*)(sKl + so) = *(const uint4*)(Kl + o);
        }
        __syncthreads();

#pragma unroll
        for (int ks = 0; ks < 32; ks += 16) {
            wmma::fragment<wmma::matrix_a, 16, 16, 16, __nv_bfloat16, wmma::row_major> aH[4], aL[4];
#pragma unroll
            for (int mi = 0; mi < 4; mi++) {
                const int row = warp_m * 64 + mi * 16;
                wmma::load_matrix_sync(aH[mi], sQh + row * PITCH + ks, PITCH);
                wmma::load_matrix_sync(aL[mi], sQl + row * PITCH + ks, PITCH);
            }
#pragma unroll
            for (int nj = 0; nj < 2; nj++) {
                const int col = warp_n * 32 + nj * 16;
                wmma::fragment<wmma::matrix_b, 16, 16, 16, __nv_bfloat16, wmma::col_major> bH, bL;
                wmma::load_matrix_sync(bH, sKh + col * PITCH + ks, PITCH);
                wmma::load_matrix_sync(bL, sKl + col * PITCH + ks, PITCH);
#pragma unroll
                for (int mi = 0; mi < 4; mi++) {
                    wmma::mma_sync(acc[mi][nj], aH[mi], bH, acc[mi][nj]);
                    wmma::mma_sync(acc[mi][nj], aH[mi], bL, acc[mi][nj]);
                    wmma::mma_sync(acc[mi][nj], aL[mi], bH, acc[mi][nj]);
                }
            }
        }
        __syncthreads();
    }

    const float* tqv = g_q2  + bh * S;
    const float* tqc = g_qcs + bh * S;
    const float* tkv = g_k2  + bh * S;
    const float* tkc = g_kcs + bh * S;
    float* att = g_att + (size_t)bh * S * S;

    float* epi = (float*)(smem) + wid * 256;
#pragma unroll
    for (int mi = 0; mi < 4; mi++) {
#pragma unroll
        for (int nj = 0; nj < 2; nj++) {
            wmma::store_matrix_sync(epi, acc[mi][nj], 16, wmma::mem_row_major);
            __syncwarp();
            const int r  = lane >> 1;
            const int c0 = (lane & 1) * 8;
            const int q  = qb + warp_m * 64 + mi * 16 + r;
            const int k  = kb + warp_n * 32 + nj * 16 + c0;
            const float tq2 = tqv[q] + tqc[q];
            float v[8];
#pragma unroll
            for (int c = 0; c < 8; c++)
                v[c] = 0.25f * epi[r * 16 + c0 + c] - 0.125f * (tq2 + tkv[k + c] + tkc[k + c]);
            float* dst = att + (size_t)q * S + k;
            *(float4*)(dst)     = make_float4(v[0], v[1], v[2], v[3]);
            *(float4*)(dst + 4) = make_float4(v[4], v[5], v[6], v[7]);
            __syncwarp();
        }
    }
}

// ---------------- per-row stats over DK=64 --------------------------------
__global__ void u_rowstats(float* __restrict__ data, float* __restrict__ osum, int mode)
{
    const int row  = blockIdx.x * 8 + (threadIdx.x >> 5);
    const int lane = threadIdx.x & 31;
    float* p = data + (size_t)row * DK;
    const float a = p[lane], b = p[lane + 32];
    float v = (mode == 0) ? (a * a + b * b) : (a + b);
#pragma unroll
    for (int o = 16; o; o >>= 1) v += __shfl_xor_sync(~0u, v, o);
    if (lane == 0) osum[row] = v;
    if (mode == 1) {
        p[lane]      = sqrtf(fmaxf(a, 1e-24f));
        p[lane + 32] = sqrtf(fmaxf(b, 1e-24f));
    }
}

// ---------------- block reduction helpers ----------------------------------
__device__ __forceinline__ float u_blkmax(float v, float* red)
{
    const int lane = threadIdx.x & 31, wid = threadIdx.x >> 5;
#pragma unroll
    for (int o = 16; o; o >>= 1) v = fmaxf(v, __shfl_xor_sync(~0u, v, o));
    __syncthreads();
    if (lane == 0) red[wid] = v;
    __syncthreads();
    float r = red[0];
#pragma unroll
    for (int i = 1; i < 8; i++) r = fmaxf(r, red[i]);
    return r;
}
__device__ __forceinline__ float u_blksum(float v, float* red)
{
    const int lane = threadIdx.x & 31, wid = threadIdx.x >> 5;
#pragma unroll
    for (int o = 16; o; o >>= 1) v += __shfl_xor_sync(~0u, v, o);
    __syncthreads();
    if (lane == 0) red[wid] = v;
    __syncthreads();
    float r = red[0];
#pragma unroll
    for (int i = 1; i < 8; i++) r += red[i];
    return r;
}

// ---------------- fused row kernel: softmax -> cumsum -> decay -> softmax --
__global__ void __launch_bounds__(256) u_decay(const float* __restrict__ gammas)
{
    const int q  = blockIdx.x;
    const int bh = blockIdx.y;
    const int L  = q + 1;
    const int Lr = (L + 127) & ~127;       // region AV consumes (zero-filled)
    const int tid  = threadIdx.x;
    const int lane = tid & 31, wid = tid >> 5;
    float* row = g_att + ((size_t)bh * S + q) * S;

    const float g = gammas[bh & (H - 1)];
    const float gamma = -log1pf(expf(g));

    __shared__ float red[8];
    __shared__ float wsum[8];
    __shared__ float shtot;

    const int base = tid * 4;
    float s[4] = {0.f, 0.f, 0.f, 0.f};
    if (base < L) {
        const float4 sv = *(const float4*)(row + base);
        s[0] = sv.x; s[1] = sv.y; s[2] = sv.z; s[3] = sv.w;
    }
    bool valid[4];
#pragma unroll
    for (int i = 0; i < 4; i++) valid[i] = (base + i) < L;

    float m = -3.402823466e+38f;
#pragma unroll
    for (int i = 0; i < 4; i++) if (valid[i]) m = fmaxf(m, s[i]);
    m = u_blkmax(m, red);

    float p[4], c[4];
    float run = 0.f;
#pragma unroll
    for (int i = 0; i < 4; i++) {
        p[i] = valid[i] ? expf(s[i] - m) : 0.f;
        run += p[i];
        c[i] = run;
    }

    float x = run;
#pragma unroll
    for (int o = 1; o < 32; o <<= 1) {
        const float y = __shfl_up_sync(~0u, x, o);
        if (lane >= o) x += y;
    }
    const float texcl = x - run;
    if (lane == 31) wsum[wid] = x;
    __syncthreads();
    if (wid == 0 && lane < 8) {
        float w = wsum[lane];
#pragma unroll
        for (int o = 1; o < 8; o <<= 1) {
            const float y = __shfl_up_sync(0xffu, w, o);
            if (lane >= o) w += y;
        }
        wsum[lane] = w;
        if (lane == 7) shtot = w;
    }
    __syncthreads();
    const float off  = texcl + (wid ? wsum[wid - 1] : 0.f);
    const float invT = 1.f / shtot;

    float l[4];
#pragma unroll
    for (int i = 0; i < 4; i++) {
        const float cum  = (c[i] + off) * invT;
        const float tail = fmaxf(1.f - cum, 0.f);
        const float pos  = (float)(q - (base + i));
        const float dist = sqrtf(tail * pos);
        float eff = expf(gamma * dist);
        eff = fminf(fmaxf(eff, 1e-5f), 1e5f);
        l[i] = s[i] * eff;
    }

    float m2 = -3.402823466e+38f;
#pragma unroll
    for (int i = 0; i < 4; i++) if (valid[i]) m2 = fmaxf(m2, l[i]);
    m2 = u_blkmax(m2, red);

    float e[4];
    float es = 0.f;
#pragma unroll
    for (int i = 0; i < 4; i++) {
        e[i] = valid[i] ? expf(l[i] - m2) : 0.f;
        es += e[i];
    }
    es = u_blksum(es, red);
    const float invE = 1.f / es;

    if (base < Lr) {
        float4 ov;
        ov.x = (q == 0) ? 0.f : e[0] * invE;
        ov.y = (q == 0) ? 0.f : e[1] * invE;
        ov.z = (q == 0) ? 0.f : e[2] * invE;
        ov.w = (q == 0) ? 0.f : e[3] * invE;
        *(float4*)(row + base) = ov;
    }
}

// ---------------- WMMA AV: mean = sc@vm (warps 0-3), cov = sc^2@vc (4-7) ----
constexpr int APITCH = 24;                 // [128][24] bf16 per matrix
constexpr int BPITCH = 72;                 // [16][72] bf16 per matrix
constexpr int ATB = 128 * APITCH * 2;      // 6144
constexpr int BTB = 16 * BPITCH * 2;       // 2304

__global__ void __launch_bounds__(256) u_av_wmma()
{
    __shared__ __align__(16) char smem[4 * ATB + 4 * BTB];  // 33792
    __nv_bfloat16* sSh = (__nv_bfloat16*)(smem);
    __nv_bfloat16* sSl = (__nv_bfloat16*)(smem + ATB);
    __nv_bfloat16* s2h = (__nv_bfloat16*)(smem + 2 * ATB);
    __nv_bfloat16* s2l = (__nv_bfloat16*)(smem + 3 * ATB);
    __nv_bfloat16* sBp[4] = {
        (__nv_bfloat16*)(smem + 4 * ATB),
        (__nv_bfloat16*)(smem + 4 * ATB + BTB),
        (__nv_bfloat16*)(smem + 4 * ATB + 2 * BTB),
        (__nv_bfloat16*)(smem + 4 * ATB + 3 * BTB)};

    const int bh = blockIdx.y;
    const int qb = (7 - blockIdx.x) * 128;      // heavy tiles first
    const int tid = threadIdx.x, wid = tid >> 5, lane = tid & 31;
    const int wg = wid >> 2;                    // 0 = mean, 1 = cov
    const int w4 = wid & 3;                     // row group (32 rows each)

    const float* att = g_att + ((size_t)bh * S + qb) * S;
    const __nv_bfloat16* Vsrc[4] = {
        g_Vmh + (size_t)bh * S * DK, g_Vml + (size_t)bh * S * DK,
        g_Vch + (size_t)bh * S * DK, g_Vcl + (size_t)bh * S * DK};

    wmma::fragment<wmma::accumulator, 16, 16, 16, float> acc[2][4];
#pragma unroll
    for (int mi = 0; mi < 2; mi++)
#pragma unroll
        for (int nj = 0; nj < 4; nj++) wmma::fill_fragment(acc[mi][nj], 0.f);

    const int kend = qb + 128;
    for (int kb = 0; kb < kend; kb += 16) {
        // stage A: att [128 x 16] fp32 -> sc hi/lo + sc^2 hi/lo bf16
#pragma unroll
        for (int i = 0; i < 2; i++) {
            const int c = (tid + i * 256) * 4;      // 0..2047 step 4
            const int r = c >> 4, cc = c & 15;
            const float4 v = *(const float4*)(att + (size_t)r * S + kb + cc);
            const int so = r * APITCH + cc;
            float vv[4] = {v.x, v.y, v.z, v.w};
            uint32_t ph[2], pl[2], qh[2], ql[2];
#pragma unroll
            for (int u = 0; u < 2; u++) {
                const float a0 = vv[u * 2], a1 = vv[u * 2 + 1];
                __nv_bfloat16 h0 = __float2bfloat16(a0), h1 = __float2bfloat16(a1);
                __nv_bfloat162 hp = {h0, h1};
                __nv_bfloat162 lp = {__float2bfloat16(a0 - __bfloat162float(h0)),
                                     __float2bfloat16(a1 - __bfloat162float(h1))};
                const float b0 = a0 * a0, b1 = a1 * a1;
                __nv_bfloat16 g0 = __float2bfloat16(b0), g1 = __float2bfloat16(b1);
                __nv_bfloat162 gp = {g0, g1};
                __nv_bfloat162 mp = {__float2bfloat16(b0 - __bfloat162float(g0)),
                                     __float2bfloat16(b1 - __bfloat162float(g1))};
                ph[u] = *(uint32_t*)&hp; pl[u] = *(uint32_t*)&lp;
                qh[u] = *(uint32_t*)&gp; ql[u] = *(uint32_t*)&mp;
            }
            *(uint32_t*)(sSh + so)     = ph[0]; *(uint32_t*)(sSh + so + 2) = ph[1];
            *(uint32_t*)(sSl + so)     = pl[0]; *(uint32_t*)(sSl + so + 2) = pl[1];
            *(uint32_t*)(s2h + so)     = qh[0]; *(uint32_t*)(s2h + so + 2) = qh[1];
            *(uint32_t*)(s2l + so)     = ql[0]; *(uint32_t*)(s2l + so + 2) = ql[1];
        }
        // stage B: vm/vc hi/lo [16 x 64] bf16 (16B chunks)
#pragma unroll
        for (int i = 0; i < 2; i++) {
            const int c = tid + i * 256;            // 0..511
            const int mtx = c >> 7, cc = c & 127;
            const int r = cc >> 3, col = (cc & 7) * 8;
            *(uint4*)(sBp[mtx] + r * BPITCH + col) =
                *(const uint4*)(Vsrc[mtx] + (size_t)(kb + r) * DK + col);
        }
        __syncthreads();

        const __nv_bfloat16* aHp = wg ? s2h : sSh;
        const __nv_bfloat16* aLp = wg ? s2l : sSl;
        const __nv_bfloat16* bHp = wg ? sBp[2] : sBp[0];
        const __nv_bfloat16* bLp = wg ? sBp[3] : sBp[1];

        wmma::fragment<wmma::matrix_a, 16, 16, 16, __nv_bfloat16, wmma::row_major> aH[2], aL[2];
#pragma unroll
        for (int mi = 0; mi < 2; mi++) {
            const int row = w4 * 32 + mi * 16;
            wmma::load_matrix_sync(aH[mi], aHp + row * APITCH, APITCH);
            wmma::load_matrix_sync(aL[mi], aLp + row * APITCH, APITCH);
        }
#pragma unroll
        for (int nj = 0; nj < 4; nj++) {
            wmma::fragment<wmma::matrix_b, 16, 16, 16, __nv_bfloat16, wmma::row_major> bH, bL;
            wmma::load_matrix_sync(bH, bHp + nj * 16, BPITCH);
            wmma::load_matrix_sync(bL, bLp + nj * 16, BPITCH);
#pragma unroll
            for (int mi = 0; mi < 2; mi++) {
                wmma::mma_sync(acc[mi][nj], aH[mi], bH, acc[mi][nj]);
                wmma::mma_sync(acc[mi][nj], aH[mi], bL, acc[mi][nj]);
                wmma::mma_sync(acc[mi][nj], aL[mi], bH, acc[mi][nj]);
            }
        }
        __syncthreads();
    }

    // epilogue -> g_cm / g_cc in [B,S,D] layout
    const int b = bh >> 3, h = bh & 7;
    float* dstbase = (wg ? g_cc : g_cm);
    float* epi = (float*)(smem) + wid * 256;
#pragma unroll
    for (int mi = 0; mi < 2; mi++) {
#pragma unroll
        for (int nj = 0; nj < 4; nj++) {
            wmma::store_matrix_sync(epi, acc[mi][nj], 16, wmma::mem_row_major);
            __syncwarp();
            const int r  = lane >> 1;
            const int c0 = (lane & 1) * 8;
            const int s  = qb + w4 * 32 + mi * 16 + r;
            const int d  = nj * 16 + c0;
            float* dst = dstbase + ((size_t)(b * S + s)) * D + h * DK + d;
            *(float4*)(dst)     = make_float4(epi[r * 16 + c0],     epi[r * 16 + c0 + 1],
                                              epi[r * 16 + c0 + 2], epi[r * 16 + c0 + 3]);
            *(float4*)(dst + 4) = make_float4(epi[r * 16 + c0 + 4], epi[r * 16 + c0 + 5],
                                              epi[r * 16 + c0 + 6], epi[r * 16 + c0 + 7]);
            __syncwarp();
        }
    }
}

// ---------------- host launcher --------------------------------------------
extern "C" void kernel_launch(void* const* d_in, const int* in_sizes, int n_in,
                              void* d_out, int out_size)
{
    const float* q_mean = (const float*)d_in[0];
    const float* q_cov  = (const float*)d_in[1];
    const float* k_mean = (const float*)d_in[2];
    const float* k_cov  = (const float*)d_in[3];
    const float* v_mean = (const float*)d_in[4];
    const float* v_cov  = (const float*)d_in[5];
    const float* Wqm = (const float*)d_in[6];  const float* bqm = (const float*)d_in[7];
    const float* Wqc = (const float*)d_in[8];  const float* bqc = (const float*)d_in[9];
    const float* Wkm = (const float*)d_in[10]; const float* bkm = (const float*)d_in[11];
    const float* Wkc = (const float*)d_in[12]; const float* bkc = (const float*)d_in[13];
    const float* Wvm = (const float*)d_in[14]; const float* bvm = (const float*)d_in[15];
    const float* Wvc = (const float*)d_in[16]; const float* bvc = (const float*)d_in[17];
    const float* Wom = (const float*)d_in[18]; const float* bom = (const float*)d_in[19];
    const float* Woc = (const float*)d_in[20]; const float* boc = (const float*)d_in[21];
    const float* gammas = (const float*)d_in[22];

    float* out = (float*)d_out;

    float *qm, *qc, *km, *kc, *vm, *vc, *q2, *qcs, *k2, *kcs, *cm, *cc;
    __nv_bfloat16 *ah, *al, *wth, *wtl, *Qh, *Ql, *Kh, *Kl, *Vmh, *Vml, *Vch, *Vcl;
    cudaGetSymbolAddress((void**)&qm,  g_qm);
    cudaGetSymbolAddress((void**)&qc,  g_qc);
    cudaGetSymbolAddress((void**)&km,  g_km);
    cudaGetSymbolAddress((void**)&kc,  g_kc);
    cudaGetSymbolAddress((void**)&vm,  g_vm);
    cudaGetSymbolAddress((void**)&vc,  g_vc);
    cudaGetSymbolAddress((void**)&q2,  g_q2);
    cudaGetSymbolAddress((void**)&qcs, g_qcs);
    cudaGetSymbolAddress((void**)&k2,  g_k2);
    cudaGetSymbolAddress((void**)&kcs, g_kcs);
    cudaGetSymbolAddress((void**)&cm,  g_cm);
    cudaGetSymbolAddress((void**)&cc,  g_cc);
    cudaGetSymbolAddress((void**)&ah,  g_ah);
    cudaGetSymbolAddress((void**)&al,  g_al);
    cudaGetSymbolAddress((void**)&wth, g_wth);
    cudaGetSymbolAddress((void**)&wtl, g_wtl);
    cudaGetSymbolAddress((void**)&Qh,  g_Qh);
    cudaGetSymbolAddress((void**)&Ql,  g_Ql);
    cudaGetSymbolAddress((void**)&Kh,  g_Kh);
    cudaGetSymbolAddress((void**)&Kl,  g_Kl);
    cudaGetSymbolAddress((void**)&Vmh, g_Vmh);
    cudaGetSymbolAddress((void**)&Vml, g_Vml);
    cudaGetSymbolAddress((void**)&Vch, g_Vch);
    cudaGetSymbolAddress((void**)&Vcl, g_Vcl);

    const dim3 gG(D / 128, MR / 128);      // (4, 64)
    const dim3 gS(MR * D / 1024);          // 4096
    const dim3 gW(D / 32, D / 32);         // (16, 16)

    struct { const float *X, *W, *bias; float* dst; } proj[6] = {
        {q_mean, Wqm, bqm, qm}, {q_cov, Wqc, bqc, qc},
        {k_mean, Wkm, bkm, km}, {k_cov, Wkc, bkc, kc},
        {v_mean, Wvm, bvm, vm}, {v_cov, Wvc, bvc, vc},
    };
    for (int i = 0; i < 6; i++) {
        u_split<<<gS, 256>>>(proj[i].X, ah, al);
        u_splitWt<<<gW, 256>>>(proj[i].W, wth, wtl);
        u_wmma_gemm<<<gG, 256>>>(ah, al, wth, wtl, proj[i].bias, proj[i].dst, 0);
    }

    u_rowstats<<<BHS / 8, 256>>>(qm, q2, 0);
    u_rowstats<<<BHS / 8, 256>>>(km, k2, 0);
    u_rowstats<<<BHS / 8, 256>>>(qc, qcs, 1);   // also sqrt in place
    u_rowstats<<<BHS / 8, 256>>>(kc, kcs, 1);

    // build concat Q/K bf16 hi/lo and V hi/lo
    u_split2<<<gS, 256>>>(qm, Qh, Ql, 0);
    u_split2<<<gS, 256>>>(qc, Qh, Ql, 64);
    u_split2<<<gS, 256>>>(km, Kh, Kl, 0);
    u_split2<<<gS, 256>>>(kc, Kh, Kl, 64);
    u_split<<<gS, 256>>>(vm, Vmh, Vml);
    u_split<<<gS, 256>>>(vc, Vch, Vcl);

    u_scores_wmma<<<dim3(36, BH), 256>>>();
    u_decay<<<dim3(S, BH), 256>>>(gammas);
    u_av_wmma<<<dim3(S / 128, BH), 256>>>();

    // output projections
    u_split<<<gS, 256>>>(cm, ah, al);
    u_splitWt<<<gW, 256>>>(Wom, wth, wtl);
    u_wmma_gemm<<<gG, 256>>>(ah, al, wth, wtl, bom, out, 1);
    u_split<<<gS, 256>>>(cc, ah, al);
    u_splitWt<<<gW, 256>>>(Woc, wth, wtl);
    u_wmma_gemm<<<gG, 256>>>(ah, al, wth, wtl, boc, out + (size_t)MR * D, 1);
}

// round 6
// speedup vs baseline: 2.0001x; 1.1510x over previous
#include <cuda_runtime.h>
#include <cuda_bf16.h>
#include <mma.h>
#include <math.h>
#include <stdint.h>

using namespace nvcuda;

constexpr int B  = 8;
constexpr int S  = 1024;
constexpr int H  = 8;
constexpr int DK = 64;
constexpr int D  = 512;
constexpr int BH  = B * H;     // 64
constexpr int BHS = BH * S;    // 65536
constexpr int MR  = B * S;     // 8192

// ---------------- device scratch ----------------
__device__ float g_att[(size_t)BH * S * S];                 // raw scores
__device__ __nv_bfloat16 g_sch[(size_t)BH * S * S];         // prob hi
__device__ __nv_bfloat16 g_scl[(size_t)BH * S * S];         // prob lo
__device__ __nv_bfloat16 g_s2h[(size_t)BH * S * S];         // prob^2 hi
__device__ __nv_bfloat16 g_s2l[(size_t)BH * S * S];         // prob^2 lo
__device__ __nv_bfloat16 g_Qh[(size_t)BHS * 128];
__device__ __nv_bfloat16 g_Ql[(size_t)BHS * 128];
__device__ __nv_bfloat16 g_Kh[(size_t)BHS * 128];
__device__ __nv_bfloat16 g_Kl[(size_t)BHS * 128];
__device__ __nv_bfloat16 g_Vmh[(size_t)BHS * DK];
__device__ __nv_bfloat16 g_Vml[(size_t)BHS * DK];
__device__ __nv_bfloat16 g_Vch[(size_t)BHS * DK];
__device__ __nv_bfloat16 g_Vcl[(size_t)BHS * DK];
__device__ __nv_bfloat16 g_A6h[(size_t)6 * MR * D];
__device__ __nv_bfloat16 g_A6l[(size_t)6 * MR * D];
__device__ __nv_bfloat16 g_W8h[8 * D * D];
__device__ __nv_bfloat16 g_W8l[8 * D * D];
__device__ __nv_bfloat16 g_cmh[(size_t)MR * D];
__device__ __nv_bfloat16 g_cml[(size_t)MR * D];
__device__ __nv_bfloat16 g_cch[(size_t)MR * D];
__device__ __nv_bfloat16 g_ccl[(size_t)MR * D];
// raw fp32 head-major projections (for exact tq/tk row stats)
__device__ float g_rawQm[(size_t)BHS * DK];
__device__ float g_rawQc[(size_t)BHS * DK];
__device__ float g_rawKm[(size_t)BHS * DK];
__device__ float g_rawKc[(size_t)BHS * DK];
__device__ float g_tq[BHS];
__device__ float g_tk[BHS];

// ---------------- cp.async helpers ----------------
#define CP16(dst, src) asm volatile( \
    "cp.async.cg.shared.global [%0], [%1], 16;" \
    :: "r"((uint32_t)__cvta_generic_to_shared(dst)), "l"(src))
#define CP_COMMIT() asm volatile("cp.async.commit_group;")
#define CP_WAIT(n)  asm volatile("cp.async.wait_group %0;" :: "n"(n))

struct Ptr6f { const float* p[6]; };
struct Ptr8f { const float* p[8]; };

// ---------------- pack 8 fp32 -> bf16 hi/lo uint4 pair --------------------
__device__ __forceinline__ void pack8(const float* v, uint4& uh, uint4& ul)
{
    __align__(16) unsigned short hh[8];
    __align__(16) unsigned short ll[8];
#pragma unroll
    for (int c = 0; c < 8; c++) {
        const __nv_bfloat16 x = __float2bfloat16(v[c]);
        hh[c] = __bfloat16_as_ushort(x);
        ll[c] = __bfloat16_as_ushort(__float2bfloat16(v[c] - __bfloat162float(x)));
    }
    uh = *(uint4*)hh;
    ul = *(uint4*)ll;
}

// ---------------- batched fp32 -> bf16 hi/lo split (inputs) ----------------
__global__ void u_split6(Ptr6f xs)
{
    const size_t zo = (size_t)blockIdx.z * MR * D;
    const int i = (blockIdx.x * 256 + threadIdx.x) * 4;
    const float4 v = *(const float4*)(xs.p[blockIdx.z] + i);
    __nv_bfloat16 h0 = __float2bfloat16(v.x), h1 = __float2bfloat16(v.y);
    __nv_bfloat16 h2 = __float2bfloat16(v.z), h3 = __float2bfloat16(v.w);
    __nv_bfloat162 hh0 = {h0, h1}, hh1 = {h2, h3};
    __nv_bfloat162 ll0 = {__float2bfloat16(v.x - __bfloat162float(h0)),
                          __float2bfloat16(v.y - __bfloat162float(h1))};
    __nv_bfloat162 ll1 = {__float2bfloat16(v.z - __bfloat162float(h2)),
                          __float2bfloat16(v.w - __bfloat162float(h3))};
    *(uint2*)(g_A6h + zo + i) = make_uint2(*(uint32_t*)&hh0, *(uint32_t*)&hh1);
    *(uint2*)(g_A6l + zo + i) = make_uint2(*(uint32_t*)&ll0, *(uint32_t*)&ll1);
}

// ---------------- batched W[K,N] -> W^T[N,K] bf16 hi/lo --------------------
__global__ void u_splitWt8(Ptr8f ws)
{
    __shared__ float tile[32][33];
    const size_t zo = (size_t)blockIdx.z * D * D;
    const float* W = ws.p[blockIdx.z];
    const int k0 = blockIdx.y * 32, n0 = blockIdx.x * 32;
    const int tx = threadIdx.x & 31, tw = threadIdx.x >> 5;
    for (int r = tw; r < 32; r += 8)
        tile[r][tx] = W[(size_t)(k0 + r) * D + n0 + tx];
    __syncthreads();
    for (int r = tw; r < 32; r += 8) {
        const float v = tile[tx][r];
        const __nv_bfloat16 hv = __float2bfloat16(v);
        const size_t o = zo + (size_t)(n0 + r) * D + k0 + tx;
        g_W8h[o] = hv;
        g_W8l[o] = __float2bfloat16(v - __bfloat162float(hv));
    }
}

// ===================  double-buffered WMMA GEMM core  ======================
constexpr int GP = 24;   // smem pitch (16 + 8 pad)

#define GEMM_MAINLOOP(Ah, Al, Bh, Bl)                                          \
    const __nv_bfloat16* srcs[4] = {Ah, Al, Bh, Bl};                           \
    const int baserow[4] = {m0, m0, n0, n0};                                   \
    wmma::fragment<wmma::accumulator, 16, 16, 16, float> acc[4][2];            \
    _Pragma("unroll")                                                          \
    for (int mi = 0; mi < 4; mi++)                                             \
        _Pragma("unroll")                                                      \
        for (int nj = 0; nj < 2; nj++) wmma::fill_fragment(acc[mi][nj], 0.f);  \
    {                                                                          \
        _Pragma("unroll")                                                      \
        for (int i = 0; i < 4; i++) {                                          \
            const int c = tid + i * 256;                                       \
            const int mtx = c >> 8, rr = (c & 255) >> 1, col8 = (c & 1) * 8;   \
            CP16(&buf[0][mtx][rr * GP + col8],                                 \
                 srcs[mtx] + (size_t)(baserow[mtx] + rr) * D + col8);          \
        }                                                                      \
        CP_COMMIT();                                                           \
    }                                                                          \
    for (int kt = 0; kt < 32; kt++) {                                          \
        if (kt < 31) {                                                         \
            const int k0n = (kt + 1) * 16;                                     \
            const int bn = (kt + 1) & 1;                                       \
            _Pragma("unroll")                                                  \
            for (int i = 0; i < 4; i++) {                                      \
                const int c = tid + i * 256;                                   \
                const int mtx = c >> 8, rr = (c & 255) >> 1, col8 = (c & 1) * 8;\
                CP16(&buf[bn][mtx][rr * GP + col8],                            \
                     srcs[mtx] + (size_t)(baserow[mtx] + rr) * D + k0n + col8);\
            }                                                                  \
            CP_COMMIT();                                                       \
            CP_WAIT(1);                                                        \
        } else {                                                               \
            CP_WAIT(0);                                                       \
        }                                                                      \
        __syncthreads();                                                       \
        const __nv_bfloat16* sAh = buf[kt & 1][0];                             \
        const __nv_bfloat16* sAl = buf[kt & 1][1];                             \
        const __nv_bfloat16* sBh = buf[kt & 1][2];                             \
        const __nv_bfloat16* sBl = buf[kt & 1][3];                             \
        wmma::fragment<wmma::matrix_a, 16, 16, 16, __nv_bfloat16, wmma::row_major> aH[4], aL[4]; \
        _Pragma("unroll")                                                      \
        for (int mi = 0; mi < 4; mi++) {                                       \
            const int row = warp_m * 64 + mi * 16;                             \
            wmma::load_matrix_sync(aH[mi], sAh + row * GP, GP);                \
            wmma::load_matrix_sync(aL[mi], sAl + row * GP, GP);                \
        }                                                                      \
        _Pragma("unroll")                                                      \
        for (int nj = 0; nj < 2; nj++) {                                       \
            const int col = warp_n * 32 + nj * 16;                             \
            wmma::fragment<wmma::matrix_b, 16, 16, 16, __nv_bfloat16, wmma::col_major> bH, bL; \
            wmma::load_matrix_sync(bH, sBh + col * GP, GP);                    \
            wmma::load_matrix_sync(bL, sBl + col * GP, GP);                    \
            _Pragma("unroll")                                                  \
            for (int mi = 0; mi < 4; mi++) {                                   \
                wmma::mma_sync(acc[mi][nj], aH[mi], bH, acc[mi][nj]);          \
                wmma::mma_sync(acc[mi][nj], aH[mi], bL, acc[mi][nj]);          \
                wmma::mma_sync(acc[mi][nj], aL[mi], bH, acc[mi][nj]);          \
            }                                                                  \
        }                                                                      \
        __syncthreads();                                                       \
    }

// ---------------- projection GEMM (z = 0..5), fused epilogue ---------------
// z: 0 qm, 1 qc(sqrt), 2 km, 3 kc(sqrt), 4 vm, 5 vc
__global__ void __launch_bounds__(256) u_gemm_proj(Ptr6f biases)
{
    __shared__ __align__(16) __nv_bfloat16 buf[2][4][128 * GP];  // 48 KB
    const int z = blockIdx.z;
    const __nv_bfloat16* Ah = g_A6h + (size_t)z * MR * D;
    const __nv_bfloat16* Al = g_A6l + (size_t)z * MR * D;
    const __nv_bfloat16* Bh = g_W8h + (size_t)z * D * D;
    const __nv_bfloat16* Bl = g_W8l + (size_t)z * D * D;
    const float* bias = biases.p[z];
    const int tid = threadIdx.x, wid = tid >> 5, lane = tid & 31;
    const int m0 = blockIdx.y * 128, n0 = blockIdx.x * 128;
    const int warp_m = wid >> 2, warp_n = wid & 3;

    GEMM_MAINLOOP(Ah, Al, Bh, Bl)

    float* epi = (float*)buf + wid * 256;
#pragma unroll
    for (int mi = 0; mi < 4; mi++) {
#pragma unroll
        for (int nj = 0; nj < 2; nj++) {
            wmma::store_matrix_sync(epi, acc[mi][nj], 16, wmma::mem_row_major);
            __syncwarp();
            const int r  = lane >> 1;
            const int c0 = (lane & 1) * 8;
            const int m  = m0 + warp_m * 64 + mi * 16 + r;
            const int n  = n0 + warp_n * 32 + nj * 16 + c0;
            float v[8];
#pragma unroll
            for (int c = 0; c < 8; c++) v[c] = epi[r * 16 + c0 + c] + bias[n + c];
            const int b = m >> 10, s = m & (S - 1);
            const int h = n >> 6, d = n & 63;
            if (z < 4) {
                // dump raw fp32 (pre-sqrt) for exact tq/tk row statistics
                float* raw = (z == 0) ? g_rawQm : (z == 1) ? g_rawQc
                           : (z == 2) ? g_rawKm : g_rawKc;
                const size_t ro = (((size_t)(b * H + h)) * S + s) * 64 + d;
                *(float4*)(raw + ro)     = make_float4(v[0], v[1], v[2], v[3]);
                *(float4*)(raw + ro + 4) = make_float4(v[4], v[5], v[6], v[7]);
                if (z & 1) {
#pragma unroll
                    for (int c = 0; c < 8; c++) v[c] = sqrtf(fmaxf(v[c], 1e-24f));
                }
                __nv_bfloat16* dh = (z < 2) ? g_Qh : g_Kh;
                __nv_bfloat16* dl = (z < 2) ? g_Ql : g_Kl;
                const size_t o = (((size_t)(b * H + h)) * S + s) * 128 + (z & 1) * 64 + d;
                uint4 uh, ul;
                pack8(v, uh, ul);
                *(uint4*)(dh + o) = uh;
                *(uint4*)(dl + o) = ul;
            } else {
                __nv_bfloat16* dh = (z == 4) ? g_Vmh : g_Vch;
                __nv_bfloat16* dl = (z == 4) ? g_Vml : g_Vcl;
                const size_t o = (((size_t)(b * H + h)) * S + s) * 64 + d;
                uint4 uh, ul;
                pack8(v, uh, ul);
                *(uint4*)(dh + o) = uh;
                *(uint4*)(dl + o) = ul;
            }
            __syncwarp();
        }
    }
}

// ---------------- output GEMM (z = 0 mean, 1 cov) --------------------------
__global__ void __launch_bounds__(256) u_gemm_out(const float* bias0, const float* bias1,
                                                  float* out)
{
    __shared__ __align__(16) __nv_bfloat16 buf[2][4][128 * GP];
    const int z = blockIdx.z;
    const __nv_bfloat16* Ah = z ? g_cch : g_cmh;
    const __nv_bfloat16* Al = z ? g_ccl : g_cml;
    const __nv_bfloat16* Bh = g_W8h + (size_t)(6 + z) * D * D;
    const __nv_bfloat16* Bl = g_W8l + (size_t)(6 + z) * D * D;
    const float* bias = z ? bias1 : bias0;
    const int tid = threadIdx.x, wid = tid >> 5, lane = tid & 31;
    const int m0 = blockIdx.y * 128, n0 = blockIdx.x * 128;
    const int warp_m = wid >> 2, warp_n = wid & 3;

    GEMM_MAINLOOP(Ah, Al, Bh, Bl)

    float* epi = (float*)buf + wid * 256;
    float* dstm = out + (size_t)z * MR * D;
#pragma unroll
    for (int mi = 0; mi < 4; mi++) {
#pragma unroll
        for (int nj = 0; nj < 2; nj++) {
            wmma::store_matrix_sync(epi, acc[mi][nj], 16, wmma::mem_row_major);
            __syncwarp();
            const int r  = lane >> 1;
            const int c0 = (lane & 1) * 8;
            const int m  = m0 + warp_m * 64 + mi * 16 + r;
            const int n  = n0 + warp_n * 32 + nj * 16 + c0;
            float v[8];
#pragma unroll
            for (int c = 0; c < 8; c++) v[c] = epi[r * 16 + c0 + c] + bias[n + c];
            float* dst = dstm + (size_t)m * D + n;
            *(float4*)(dst)     = make_float4(v[0], v[1], v[2], v[3]);
            *(float4*)(dst + 4) = make_float4(v[4], v[5], v[6], v[7]);
            __syncwarp();
        }
    }
}

// ---------------- exact row stats: tq = sum(qm^2) + sum(raw qc) ------------
__global__ void u_rownorm()
{
    const int row  = blockIdx.x * 8 + (threadIdx.x >> 5);
    const int lane = threadIdx.x & 31;
    const float* pm = (blockIdx.y ? g_rawKm : g_rawQm) + (size_t)row * DK;
    const float* pc = (blockIdx.y ? g_rawKc : g_rawQc) + (size_t)row * DK;
    const float a0 = pm[lane], a1 = pm[lane + 32];
    const float c0 = pc[lane], c1 = pc[lane + 32];
    float v = a0 * a0 + a1 * a1 + c0 + c1;
#pragma unroll
    for (int o = 16; o; o >>= 1) v += __shfl_xor_sync(~0u, v, o);
    if (lane == 0) (blockIdx.y ? g_tk : g_tq)[row] = v;
}

// ---------------- WMMA scores: 128x128 causal tiles ------------------------
constexpr int SP = 40;
constexpr int STB = 128 * SP * 2;

__global__ void __launch_bounds__(256) u_scores_wmma()
{
    __shared__ __align__(16) char smem[4 * STB];
    __nv_bfloat16* sQh = (__nv_bfloat16*)(smem);
    __nv_bfloat16* sQl = (__nv_bfloat16*)(smem + STB);
    __nv_bfloat16* sKh = (__nv_bfloat16*)(smem + 2 * STB);
    __nv_bfloat16* sKl = (__nv_bfloat16*)(smem + 3 * STB);

    const int bh = blockIdx.y;
    int tq = (int)((sqrtf(8.f * blockIdx.x + 1.f) - 1.f) * 0.5f);
    while ((tq + 1) * (tq + 2) / 2 <= (int)blockIdx.x) tq++;
    while (tq * (tq + 1) / 2 > (int)blockIdx.x) tq--;
    const int tk = blockIdx.x - tq * (tq + 1) / 2;
    const int qb = tq * 128, kb = tk * 128;

    const int tid = threadIdx.x, wid = tid >> 5, lane = tid & 31;
    const int warp_m = wid >> 2, warp_n = wid & 3;
    const __nv_bfloat16* Qh = g_Qh + ((size_t)bh * S + qb) * 128;
    const __nv_bfloat16* Ql = g_Ql + ((size_t)bh * S + qb) * 128;
    const __nv_bfloat16* Kh = g_Kh + ((size_t)bh * S + kb) * 128;
    const __nv_bfloat16* Kl = g_Kl + ((size_t)bh * S + kb) * 128;

    wmma::fragment<wmma::accumulator, 16, 16, 16, float> acc[4][2];
#pragma unroll
    for (int mi = 0; mi < 4; mi++)
#pragma unroll
        for (int nj = 0; nj < 2; nj++) wmma::fill_fragment(acc[mi][nj], 0.f);

#pragma unroll
    for (int kt = 0; kt < 4; kt++) {
        const int k0 = kt * 32;
#pragma unroll
        for (int i = 0; i < 2; i++) {
            const int c = tid + i * 256;
            const int r = c >> 2, cc = (c & 3) * 8;
            const int so = r * SP + cc;
            const size_t o = (size_t)r * 128 + k0 + cc;
            *(uint4*)(sQh + so) = *(const uint4*)(Qh + o);
            *(uint4*)(sQl + so) = *(const uint4*)(Ql + o);
            *(uint4*)(sKh + so) = *(const uint4*)(Kh + o);
            *(uint4*)(sKl + so) = *(const uint4*)(Kl + o);
        }
        __syncthreads();

#pragma unroll
        for (int ks = 0; ks < 32; ks += 16) {
            wmma::fragment<wmma::matrix_a, 16, 16, 16, __nv_bfloat16, wmma::row_major> aH[4], aL[4];
#pragma unroll
            for (int mi = 0; mi < 4; mi++) {
                const int row = warp_m * 64 + mi * 16;
                wmma::load_matrix_sync(aH[mi], sQh + row * SP + ks, SP);
                wmma::load_matrix_sync(aL[mi], sQl + row * SP + ks, SP);
            }
#pragma unroll
            for (int nj = 0; nj < 2; nj++) {
                const int col = warp_n * 32 + nj * 16;
                wmma::fragment<wmma::matrix_b, 16, 16, 16, __nv_bfloat16, wmma::col_major> bH, bL;
                wmma::load_matrix_sync(bH, sKh + col * SP + ks, SP);
                wmma::load_matrix_sync(bL, sKl + col * SP + ks, SP);
#pragma unroll
                for (int mi = 0; mi < 4; mi++) {
                    wmma::mma_sync(acc[mi][nj], aH[mi], bH, acc[mi][nj]);
                    wmma::mma_sync(acc[mi][nj], aH[mi], bL, acc[mi][nj]);
                    wmma::mma_sync(acc[mi][nj], aL[mi], bH, acc[mi][nj]);
                }
            }
        }
        __syncthreads();
    }

    float* att = g_att + (size_t)bh * S * S;
    const float* tqv = g_tq + bh * S;
    const float* tkv = g_tk + bh * S;

    float* epi = (float*)(smem) + wid * 256;
#pragma unroll
    for (int mi = 0; mi < 4; mi++) {
#pragma unroll
        for (int nj = 0; nj < 2; nj++) {
            wmma::store_matrix_sync(epi, acc[mi][nj], 16, wmma::mem_row_major);
            __syncwarp();
            const int r  = lane >> 1;
            const int c0 = (lane & 1) * 8;
            const int q  = qb + warp_m * 64 + mi * 16 + r;
            const int k  = kb + warp_n * 32 + nj * 16 + c0;
            const float tq2 = tqv[q];
            float v[8];
#pragma unroll
            for (int c = 0; c < 8; c++)
                v[c] = 0.25f * epi[r * 16 + c0 + c] - 0.125f * (tq2 + tkv[k + c]);
            float* dst = att + (size_t)q * S + k;
            *(float4*)(dst)     = make_float4(v[0], v[1], v[2], v[3]);
            *(float4*)(dst + 4) = make_float4(v[4], v[5], v[6], v[7]);
            __syncwarp();
        }
    }
}

// ---------------- block reduction helpers ----------------------------------
__device__ __forceinline__ float u_blkmax(float v, float* red)
{
    const int lane = threadIdx.x & 31, wid = threadIdx.x >> 5;
#pragma unroll
    for (int o = 16; o; o >>= 1) v = fmaxf(v, __shfl_xor_sync(~0u, v, o));
    __syncthreads();
    if (lane == 0) red[wid] = v;
    __syncthreads();
    float r = red[0];
#pragma unroll
    for (int i = 1; i < 8; i++) r = fmaxf(r, red[i]);
    return r;
}
__device__ __forceinline__ float u_blksum(float v, float* red)
{
    const int lane = threadIdx.x & 31, wid = threadIdx.x >> 5;
#pragma unroll
    for (int o = 16; o; o >>= 1) v += __shfl_xor_sync(~0u, v, o);
    __syncthreads();
    if (lane == 0) red[wid] = v;
    __syncthreads();
    float r = red[0];
#pragma unroll
    for (int i = 1; i < 8; i++) r += red[i];
    return r;
}

// ---------------- fused softmax -> cumsum -> decay -> softmax --------------
__global__ void __launch_bounds__(256) u_decay(const float* __restrict__ gammas)
{
    const int q  = blockIdx.x;
    const int bh = blockIdx.y;
    const int L  = q + 1;
    const int Lr = (L + 127) & ~127;
    const int tid  = threadIdx.x;
    const int lane = tid & 31, wid = tid >> 5;
    const float* row = g_att + ((size_t)bh * S + q) * S;

    const float g = gammas[bh & (H - 1)];
    const float gamma = -log1pf(expf(g));

    __shared__ float red[8];
    __shared__ float wsum[8];
    __shared__ float shtot;

    const int base = tid * 4;
    float s[4] = {0.f, 0.f, 0.f, 0.f};
    if (base < L) {
        const float4 sv = *(const float4*)(row + base);
        s[0] = sv.x; s[1] = sv.y; s[2] = sv.z; s[3] = sv.w;
    }
    bool valid[4];
#pragma unroll
    for (int i = 0; i < 4; i++) valid[i] = (base + i) < L;

    float m = -3.402823466e+38f;
#pragma unroll
    for (int i = 0; i < 4; i++) if (valid[i]) m = fmaxf(m, s[i]);
    m = u_blkmax(m, red);

    float p[4], c[4];
    float run = 0.f;
#pragma unroll
    for (int i = 0; i < 4; i++) {
        p[i] = valid[i] ? expf(s[i] - m) : 0.f;
        run += p[i];
        c[i] = run;
    }

    float x = run;
#pragma unroll
    for (int o = 1; o < 32; o <<= 1) {
        const float y = __shfl_up_sync(~0u, x, o);
        if (lane >= o) x += y;
    }
    const float texcl = x - run;
    if (lane == 31) wsum[wid] = x;
    __syncthreads();
    if (wid == 0 && lane < 8) {
        float w = wsum[lane];
#pragma unroll
        for (int o = 1; o < 8; o <<= 1) {
            const float y = __shfl_up_sync(0xffu, w, o);
            if (lane >= o) w += y;
        }
        wsum[lane] = w;
        if (lane == 7) shtot = w;
    }
    __syncthreads();
    const float off  = texcl + (wid ? wsum[wid - 1] : 0.f);
    const float invT = 1.f / shtot;

    float l[4];
#pragma unroll
    for (int i = 0; i < 4; i++) {
        const float cum  = (c[i] + off) * invT;
        const float tail = fmaxf(1.f - cum, 0.f);
        const float pos  = (float)(q - (base + i));
        const float dist = sqrtf(tail * pos);
        float eff = expf(gamma * dist);
        eff = fminf(fmaxf(eff, 1e-5f), 1e5f);
        l[i] = s[i] * eff;
    }

    float m2 = -3.402823466e+38f;
#pragma unroll
    for (int i = 0; i < 4; i++) if (valid[i]) m2 = fmaxf(m2, l[i]);
    m2 = u_blkmax(m2, red);

    float e[4];
    float es = 0.f;
#pragma unroll
    for (int i = 0; i < 4; i++) {
        e[i] = valid[i] ? expf(l[i] - m2) : 0.f;
        es += e[i];
    }
    es = u_blksum(es, red);
    const float invE = 1.f / es;

    if (base < Lr) {
        __align__(8) unsigned short hh[4], ll[4], h2[4], l2[4];
#pragma unroll
        for (int i = 0; i < 4; i++) {
            const float pv = (q == 0) ? 0.f : e[i] * invE;
            const __nv_bfloat16 ph = __float2bfloat16(pv);
            hh[i] = __bfloat16_as_ushort(ph);
            ll[i] = __bfloat16_as_ushort(__float2bfloat16(pv - __bfloat162float(ph)));
            const float p2 = pv * pv;
            const __nv_bfloat16 qh2 = __float2bfloat16(p2);
            h2[i] = __bfloat16_as_ushort(qh2);
            l2[i] = __bfloat16_as_ushort(__float2bfloat16(p2 - __bfloat162float(qh2)));
        }
        const size_t pidx = ((size_t)bh * S + q) * S + base;
        *(uint2*)(g_sch + pidx) = *(uint2*)hh;
        *(uint2*)(g_scl + pidx) = *(uint2*)ll;
        *(uint2*)(g_s2h + pidx) = *(uint2*)h2;
        *(uint2*)(g_s2l + pidx) = *(uint2*)l2;
    }
}

// ---------------- WMMA AV: mean = sc@vm (warps 0-3), cov = sc^2@vc (4-7) ---
constexpr int AP  = 24;
constexpr int BPp = 72;

__global__ void __launch_bounds__(256) u_av_wmma()
{
    __shared__ __align__(16) __nv_bfloat16 sA[4][128 * AP];
    __shared__ __align__(16) __nv_bfloat16 sB[4][16 * BPp];

    const int bh = blockIdx.y;
    const int qb = (7 - blockIdx.x) * 128;
    const int tid = threadIdx.x, wid = tid >> 5, lane = tid & 31;
    const int wg = wid >> 2, w4 = wid & 3;

    const size_t aoff = ((size_t)bh * S + qb) * S;
    const size_t vb   = (size_t)bh * S * DK;
    const __nv_bfloat16* Ap[4] = {g_sch + aoff, g_scl + aoff, g_s2h + aoff, g_s2l + aoff};
    const __nv_bfloat16* Vp[4] = {g_Vmh + vb, g_Vml + vb, g_Vch + vb, g_Vcl + vb};

    wmma::fragment<wmma::accumulator, 16, 16, 16, float> acc[2][4];
#pragma unroll
    for (int mi = 0; mi < 2; mi++)
#pragma unroll
        for (int nj = 0; nj < 4; nj++) wmma::fill_fragment(acc[mi][nj], 0.f);

    const int kend = qb + 128;
    for (int kb = 0; kb < kend; kb += 16) {
#pragma unroll
        for (int i = 0; i < 4; i++) {
            const int c = tid + i * 256;
            const int pl = c >> 8, rr = (c & 255) >> 1, col8 = (c & 1) * 8;
            CP16(&sA[pl][rr * AP + col8], Ap[pl] + (size_t)rr * S + kb + col8);
        }
#pragma unroll
        for (int i = 0; i < 2; i++) {
            const int c = tid + i * 256;
            const int mtx = c >> 7, idx = c & 127;
            const int rr = idx >> 3, col8 = (idx & 7) * 8;
            CP16(&sB[mtx][rr * BPp + col8], Vp[mtx] + (size_t)(kb + rr) * DK + col8);
        }
        CP_COMMIT();
        CP_WAIT(0);
        __syncthreads();

        const __nv_bfloat16* aHp = wg ? sA[2] : sA[0];
        const __nv_bfloat16* aLp = wg ? sA[3] : sA[1];
        const __nv_bfloat16* bHp = wg ? sB[2] : sB[0];
        const __nv_bfloat16* bLp = wg ? sB[3] : sB[1];

        wmma::fragment<wmma::matrix_a, 16, 16, 16, __nv_bfloat16, wmma::row_major> aH[2], aL[2];
#pragma unroll
        for (int mi = 0; mi < 2; mi++) {
            const int row = w4 * 32 + mi * 16;
            wmma::load_matrix_sync(aH[mi], aHp + row * AP, AP);
            wmma::load_matrix_sync(aL[mi], aLp + row * AP, AP);
        }
#pragma unroll
        for (int nj = 0; nj < 4; nj++) {
            wmma::fragment<wmma::matrix_b, 16, 16, 16, __nv_bfloat16, wmma::row_major> bH, bL;
            wmma::load_matrix_sync(bH, bHp + nj * 16, BPp);
            wmma::load_matrix_sync(bL, bLp + nj * 16, BPp);
#pragma unroll
            for (int mi = 0; mi < 2; mi++) {
                wmma::mma_sync(acc[mi][nj], aH[mi], bH, acc[mi][nj]);
                wmma::mma_sync(acc[mi][nj], aH[mi], bL, acc[mi][nj]);
                wmma::mma_sync(acc[mi][nj], aL[mi], bH, acc[mi][nj]);
            }
        }
        __syncthreads();
    }

    const int b = bh >> 3, h = bh & 7;
    __nv_bfloat16* dh = wg ? g_cch : g_cmh;
    __nv_bfloat16* dl = wg ? g_ccl : g_cml;
    float* epi = (float*)sA + wid * 256;
#pragma unroll
    for (int mi = 0; mi < 2; mi++) {
#pragma unroll
        for (int nj = 0; nj < 4; nj++) {
            wmma::store_matrix_sync(epi, acc[mi][nj], 16, wmma::mem_row_major);
            __syncwarp();
            const int r  = lane >> 1;
            const int c0 = (lane & 1) * 8;
            const int s  = qb + w4 * 32 + mi * 16 + r;
            const int d  = nj * 16 + c0;
            float v[8];
#pragma unroll
            for (int c = 0; c < 8; c++) v[c] = epi[r * 16 + c0 + c];
            uint4 uh, ul;
            pack8(v, uh, ul);
            const size_t o = ((size_t)(b * S + s)) * D + h * DK + d;
            *(uint4*)(dh + o) = uh;
            *(uint4*)(dl + o) = ul;
            __syncwarp();
        }
    }
}

// ---------------- host launcher --------------------------------------------
extern "C" void kernel_launch(void* const* d_in, const int* in_sizes, int n_in,
                              void* d_out, int out_size)
{
    const float* q_mean = (const float*)d_in[0];
    const float* q_cov  = (const float*)d_in[1];
    const float* k_mean = (const float*)d_in[2];
    const float* k_cov  = (const float*)d_in[3];
    const float* v_mean = (const float*)d_in[4];
    const float* v_cov  = (const float*)d_in[5];
    const float* Wqm = (const float*)d_in[6];  const float* bqm = (const float*)d_in[7];
    const float* Wqc = (const float*)d_in[8];  const float* bqc = (const float*)d_in[9];
    const float* Wkm = (const float*)d_in[10]; const float* bkm = (const float*)d_in[11];
    const float* Wkc = (const float*)d_in[12]; const float* bkc = (const float*)d_in[13];
    const float* Wvm = (const float*)d_in[14]; const float* bvm = (const float*)d_in[15];
    const float* Wvc = (const float*)d_in[16]; const float* bvc = (const float*)d_in[17];
    const float* Wom = (const float*)d_in[18]; const float* bom = (const float*)d_in[19];
    const float* Woc = (const float*)d_in[20]; const float* boc = (const float*)d_in[21];
    const float* gammas = (const float*)d_in[22];

    float* out = (float*)d_out;

    Ptr6f xs;   xs.p[0] = q_mean; xs.p[1] = q_cov; xs.p[2] = k_mean;
                xs.p[3] = k_cov;  xs.p[4] = v_mean; xs.p[5] = v_cov;
    Ptr8f ws;   ws.p[0] = Wqm; ws.p[1] = Wqc; ws.p[2] = Wkm; ws.p[3] = Wkc;
                ws.p[4] = Wvm; ws.p[5] = Wvc; ws.p[6] = Wom; ws.p[7] = Woc;
    Ptr6f bs;   bs.p[0] = bqm; bs.p[1] = bqc; bs.p[2] = bkm;
                bs.p[3] = bkc; bs.p[4] = bvm; bs.p[5] = bvc;

    u_split6  <<<dim3(MR * D / 1024, 1, 6), 256>>>(xs);
    u_splitWt8<<<dim3(D / 32, D / 32, 8), 256>>>(ws);
    u_gemm_proj<<<dim3(D / 128, MR / 128, 6), 256>>>(bs);
    u_rownorm <<<dim3(BHS / 8, 2), 256>>>();
    u_scores_wmma<<<dim3(36, BH), 256>>>();
    u_decay   <<<dim3(S, BH), 256>>>(gammas);
    u_av_wmma <<<dim3(S / 128, BH), 256>>>();
    u_gemm_out<<<dim3(D / 128, MR / 128, 2), 256>>>(bom, boc, out);
}

// round 8
// speedup vs baseline: 2.0326x; 1.0163x over previous
#include <cuda_runtime.h>
#include <cuda_bf16.h>
#include <mma.h>
#include <math.h>
#include <stdint.h>

using namespace nvcuda;

constexpr int B  = 8;
constexpr int S  = 1024;
constexpr int H  = 8;
constexpr int DK = 64;
constexpr int D  = 512;
constexpr int BH  = B * H;     // 64
constexpr int BHS = BH * S;    // 65536
constexpr int MR  = B * S;     // 8192

// ---------------- device scratch ----------------
__device__ float g_att[(size_t)BH * S * S];                 // raw scores
__device__ __nv_bfloat16 g_sch[(size_t)BH * S * S];         // prob hi
__device__ __nv_bfloat16 g_scl[(size_t)BH * S * S];         // prob lo
__device__ __nv_bfloat16 g_s2h[(size_t)BH * S * S];         // prob^2 hi
__device__ __nv_bfloat16 g_s2l[(size_t)BH * S * S];         // prob^2 lo
__device__ __nv_bfloat16 g_Qh[(size_t)BHS * 128];
__device__ __nv_bfloat16 g_Ql[(size_t)BHS * 128];
__device__ __nv_bfloat16 g_Kh[(size_t)BHS * 128];
__device__ __nv_bfloat16 g_Kl[(size_t)BHS * 128];
__device__ __nv_bfloat16 g_Vmh[(size_t)BHS * DK];
__device__ __nv_bfloat16 g_Vml[(size_t)BHS * DK];
__device__ __nv_bfloat16 g_Vch[(size_t)BHS * DK];
__device__ __nv_bfloat16 g_Vcl[(size_t)BHS * DK];
__device__ __nv_bfloat16 g_A6h[(size_t)6 * MR * D];
__device__ __nv_bfloat16 g_A6l[(size_t)6 * MR * D];
__device__ __nv_bfloat16 g_W8h[8 * D * D];
__device__ __nv_bfloat16 g_W8l[8 * D * D];
__device__ __nv_bfloat16 g_cmh[(size_t)MR * D];
__device__ __nv_bfloat16 g_cml[(size_t)MR * D];
__device__ __nv_bfloat16 g_cch[(size_t)MR * D];
__device__ __nv_bfloat16 g_ccl[(size_t)MR * D];
// raw fp32 head-major projections (for exact tq/tk row stats)
__device__ float g_rawQm[(size_t)BHS * DK];
__device__ float g_rawQc[(size_t)BHS * DK];
__device__ float g_rawKm[(size_t)BHS * DK];
__device__ float g_rawKc[(size_t)BHS * DK];
__device__ float g_tq[BHS];
__device__ float g_tk[BHS];

// ---------------- cp.async helpers ----------------
#define CP16(dst, src) asm volatile( \
    "cp.async.cg.shared.global [%0], [%1], 16;" \
    :: "r"((uint32_t)__cvta_generic_to_shared(dst)), "l"(src))
#define CP_COMMIT() asm volatile("cp.async.commit_group;")
#define CP_WAIT(n)  asm volatile("cp.async.wait_group %0;" :: "n"(n))

struct Ptr6f { const float* p[6]; };
struct Ptr8f { const float* p[8]; };

// ---------------- pack 8 fp32 -> bf16 hi/lo uint4 pair --------------------
__device__ __forceinline__ void pack8(const float* v, uint4& uh, uint4& ul)
{
    __align__(16) unsigned short hh[8];
    __align__(16) unsigned short ll[8];
#pragma unroll
    for (int c = 0; c < 8; c++) {
        const __nv_bfloat16 x = __float2bfloat16(v[c]);
        hh[c] = __bfloat16_as_ushort(x);
        ll[c] = __bfloat16_as_ushort(__float2bfloat16(v[c] - __bfloat162float(x)));
    }
    uh = *(uint4*)hh;
    ul = *(uint4*)ll;
}

// ---------------- batched fp32 -> bf16 hi/lo split (inputs) ----------------
__global__ void u_split6(Ptr6f xs)
{
    const size_t zo = (size_t)blockIdx.z * MR * D;
    const int i = (blockIdx.x * 256 + threadIdx.x) * 4;
    const float4 v = *(const float4*)(xs.p[blockIdx.z] + i);
    __nv_bfloat16 h0 = __float2bfloat16(v.x), h1 = __float2bfloat16(v.y);
    __nv_bfloat16 h2 = __float2bfloat16(v.z), h3 = __float2bfloat16(v.w);
    __nv_bfloat162 hh0 = {h0, h1}, hh1 = {h2, h3};
    __nv_bfloat162 ll0 = {__float2bfloat16(v.x - __bfloat162float(h0)),
                          __float2bfloat16(v.y - __bfloat162float(h1))};
    __nv_bfloat162 ll1 = {__float2bfloat16(v.z - __bfloat162float(h2)),
                          __float2bfloat16(v.w - __bfloat162float(h3))};
    *(uint2*)(g_A6h + zo + i) = make_uint2(*(uint32_t*)&hh0, *(uint32_t*)&hh1);
    *(uint2*)(g_A6l + zo + i) = make_uint2(*(uint32_t*)&ll0, *(uint32_t*)&ll1);
}

// ---------------- batched W[K,N] -> W^T[N,K] bf16 hi/lo --------------------
__global__ void u_splitWt8(Ptr8f ws)
{
    __shared__ float tile[32][33];
    const size_t zo = (size_t)blockIdx.z * D * D;
    const float* W = ws.p[blockIdx.z];
    const int k0 = blockIdx.y * 32, n0 = blockIdx.x * 32;
    const int tx = threadIdx.x & 31, tw = threadIdx.x >> 5;
    for (int r = tw; r < 32; r += 8)
        tile[r][tx] = W[(size_t)(k0 + r) * D + n0 + tx];
    __syncthreads();
    for (int r = tw; r < 32; r += 8) {
        const float v = tile[tx][r];
        const __nv_bfloat16 hv = __float2bfloat16(v);
        const size_t o = zo + (size_t)(n0 + r) * D + k0 + tx;
        g_W8h[o] = hv;
        g_W8l[o] = __float2bfloat16(v - __bfloat162float(hv));
    }
}

// ===================  double-buffered WMMA GEMM core  ======================
// A bf16 hi/lo row-major stride ldv; B = transposed bf16 hi/lo stride ldv.
// 128x128 CTA tile, BK=16, 2-stage cp.async pipeline, ONE sync per K-step.
constexpr int GP = 24;   // smem pitch (16 + 8 pad)

#define GEMM_PREFETCH(dstbuf, koff)                                            \
    _Pragma("unroll")                                                          \
    for (int i = 0; i < 4; i++) {                                              \
        const int c = tid + i * 256;                                           \
        const int mtx = c >> 8, rr = (c & 255) >> 1, col8 = (c & 1) * 8;       \
        CP16(&buf[dstbuf][mtx][rr * GP + col8],                                \
             srcs[mtx] + (size_t)(baserow[mtx] + rr) * ldv + (koff) + col8);   \
    }

#define GEMM_MAINLOOP(Ah, Al, Bh, Bl, LD, NITER)                               \
    const __nv_bfloat16* srcs[4] = {Ah, Al, Bh, Bl};                           \
    const int baserow[4] = {m0, m0, n0, n0};                                   \
    const int ldv = (LD);                                                      \
    wmma::fragment<wmma::accumulator, 16, 16, 16, float> acc[4][2];            \
    _Pragma("unroll")                                                          \
    for (int mi = 0; mi < 4; mi++)                                             \
        _Pragma("unroll")                                                      \
        for (int nj = 0; nj < 2; nj++) wmma::fill_fragment(acc[mi][nj], 0.f);  \
    GEMM_PREFETCH(0, 0)                                                        \
    CP_COMMIT();                                                               \
    for (int kt = 0; kt < (NITER); kt++) {                                     \
        CP_WAIT(0);                                                            \
        __syncthreads();                                                       \
        if (kt + 1 < (NITER)) {                                                \
            const int bn = (kt + 1) & 1;                                       \
            GEMM_PREFETCH(bn, (kt + 1) * 16)                                   \
            CP_COMMIT();                                                       \
        }                                                                      \
        const __nv_bfloat16* sAh = buf[kt & 1][0];                             \
        const __nv_bfloat16* sAl = buf[kt & 1][1];                             \
        const __nv_bfloat16* sBh = buf[kt & 1][2];                             \
        const __nv_bfloat16* sBl = buf[kt & 1][3];                             \
        wmma::fragment<wmma::matrix_a, 16, 16, 16, __nv_bfloat16, wmma::row_major> aH[4], aL[4]; \
        _Pragma("unroll")                                                      \
        for (int mi = 0; mi < 4; mi++) {                                       \
            const int row = warp_m * 64 + mi * 16;                             \
            wmma::load_matrix_sync(aH[mi], sAh + row * GP, GP);                \
            wmma::load_matrix_sync(aL[mi], sAl + row * GP, GP);                \
        }                                                                      \
        _Pragma("unroll")                                                      \
        for (int nj = 0; nj < 2; nj++) {                                       \
            const int col = warp_n * 32 + nj * 16;                             \
            wmma::fragment<wmma::matrix_b, 16, 16, 16, __nv_bfloat16, wmma::col_major> bH, bL; \
            wmma::load_matrix_sync(bH, sBh + col * GP, GP);                    \
            wmma::load_matrix_sync(bL, sBl + col * GP, GP);                    \
            _Pragma("unroll")                                                  \
            for (int mi = 0; mi < 4; mi++) {                                   \
                wmma::mma_sync(acc[mi][nj], aH[mi], bH, acc[mi][nj]);          \
                wmma::mma_sync(acc[mi][nj], aH[mi], bL, acc[mi][nj]);          \
                wmma::mma_sync(acc[mi][nj], aL[mi], bH, acc[mi][nj]);          \
            }                                                                  \
        }                                                                      \
    }                                                                          \
    __syncthreads();

// ---------------- projection GEMM (z = 0..5), fused epilogue ---------------
__global__ void __launch_bounds__(256, 2) u_gemm_proj(Ptr6f biases)
{
    __shared__ __align__(16) __nv_bfloat16 buf[2][4][128 * GP];  // 48 KB
    const int z = blockIdx.z;
    const __nv_bfloat16* Ah = g_A6h + (size_t)z * MR * D;
    const __nv_bfloat16* Al = g_A6l + (size_t)z * MR * D;
    const __nv_bfloat16* Bh = g_W8h + (size_t)z * D * D;
    const __nv_bfloat16* Bl = g_W8l + (size_t)z * D * D;
    const float* bias = biases.p[z];
    const int tid = threadIdx.x, wid = tid >> 5, lane = tid & 31;
    const int m0 = blockIdx.y * 128, n0 = blockIdx.x * 128;
    const int warp_m = wid >> 2, warp_n = wid & 3;

    GEMM_MAINLOOP(Ah, Al, Bh, Bl, D, 32)

    float* epi = (float*)buf + wid * 256;
#pragma unroll
    for (int mi = 0; mi < 4; mi++) {
#pragma unroll
        for (int nj = 0; nj < 2; nj++) {
            wmma::store_matrix_sync(epi, acc[mi][nj], 16, wmma::mem_row_major);
            __syncwarp();
            const int r  = lane >> 1;
            const int c0 = (lane & 1) * 8;
            const int m  = m0 + warp_m * 64 + mi * 16 + r;
            const int n  = n0 + warp_n * 32 + nj * 16 + c0;
            float v[8];
#pragma unroll
            for (int c = 0; c < 8; c++) v[c] = epi[r * 16 + c0 + c] + bias[n + c];
            const int b = m >> 10, s = m & (S - 1);
            const int h = n >> 6, d = n & 63;
            if (z < 4) {
                float* raw = (z == 0) ? g_rawQm : (z == 1) ? g_rawQc
                           : (z == 2) ? g_rawKm : g_rawKc;
                const size_t ro = (((size_t)(b * H + h)) * S + s) * 64 + d;
                *(float4*)(raw + ro)     = make_float4(v[0], v[1], v[2], v[3]);
                *(float4*)(raw + ro + 4) = make_float4(v[4], v[5], v[6], v[7]);
                if (z & 1) {
#pragma unroll
                    for (int c = 0; c < 8; c++) v[c] = sqrtf(fmaxf(v[c], 1e-24f));
                }
                __nv_bfloat16* dh = (z < 2) ? g_Qh : g_Kh;
                __nv_bfloat16* dl = (z < 2) ? g_Ql : g_Kl;
                const size_t o = (((size_t)(b * H + h)) * S + s) * 128 + (z & 1) * 64 + d;
                uint4 uh, ul;
                pack8(v, uh, ul);
                *(uint4*)(dh + o) = uh;
                *(uint4*)(dl + o) = ul;
            } else {
                __nv_bfloat16* dh = (z == 4) ? g_Vmh : g_Vch;
                __nv_bfloat16* dl = (z == 4) ? g_Vml : g_Vcl;
                const size_t o = (((size_t)(b * H + h)) * S + s) * 64 + d;
                uint4 uh, ul;
                pack8(v, uh, ul);
                *(uint4*)(dh + o) = uh;
                *(uint4*)(dl + o) = ul;
            }
            __syncwarp();
        }
    }
}

// ---------------- output GEMM (z = 0 mean, 1 cov) --------------------------
__global__ void __launch_bounds__(256, 2) u_gemm_out(const float* bias0, const float* bias1,
                                                     float* out)
{
    __shared__ __align__(16) __nv_bfloat16 buf[2][4][128 * GP];
    const int z = blockIdx.z;
    const __nv_bfloat16* Ah = z ? g_cch : g_cmh;
    const __nv_bfloat16* Al = z ? g_ccl : g_cml;
    const __nv_bfloat16* Bh = g_W8h + (size_t)(6 + z) * D * D;
    const __nv_bfloat16* Bl = g_W8l + (size_t)(6 + z) * D * D;
    const float* bias = z ? bias1 : bias0;
    const int tid = threadIdx.x, wid = tid >> 5, lane = tid & 31;
    const int m0 = blockIdx.y * 128, n0 = blockIdx.x * 128;
    const int warp_m = wid >> 2, warp_n = wid & 3;

    GEMM_MAINLOOP(Ah, Al, Bh, Bl, D, 32)

    float* epi = (float*)buf + wid * 256;
    float* dstm = out + (size_t)z * MR * D;
#pragma unroll
    for (int mi = 0; mi < 4; mi++) {
#pragma unroll
        for (int nj = 0; nj < 2; nj++) {
            wmma::store_matrix_sync(epi, acc[mi][nj], 16, wmma::mem_row_major);
            __syncwarp();
            const int r  = lane >> 1;
            const int c0 = (lane & 1) * 8;
            const int m  = m0 + warp_m * 64 + mi * 16 + r;
            const int n  = n0 + warp_n * 32 + nj * 16 + c0;
            float v[8];
#pragma unroll
            for (int c = 0; c < 8; c++) v[c] = epi[r * 16 + c0 + c] + bias[n + c];
            float* dst = dstm + (size_t)m * D + n;
            *(float4*)(dst)     = make_float4(v[0], v[1], v[2], v[3]);
            *(float4*)(dst + 4) = make_float4(v[4], v[5], v[6], v[7]);
            __syncwarp();
        }
    }
}

// ---------------- exact row stats: tq = sum(qm^2) + sum(raw qc) ------------
__global__ void u_rownorm()
{
    const int row  = blockIdx.x * 8 + (threadIdx.x >> 5);
    const int lane = threadIdx.x & 31;
    const float* pm = (blockIdx.y ? g_rawKm : g_rawQm) + (size_t)row * DK;
    const float* pc = (blockIdx.y ? g_rawKc : g_rawQc) + (size_t)row * DK;
    const float a0 = pm[lane], a1 = pm[lane + 32];
    const float c0 = pc[lane], c1 = pc[lane + 32];
    float v = a0 * a0 + a1 * a1 + c0 + c1;
#pragma unroll
    for (int o = 16; o; o >>= 1) v += __shfl_xor_sync(~0u, v, o);
    if (lane == 0) (blockIdx.y ? g_tk : g_tq)[row] = v;
}

// ---------------- WMMA scores: 128x128 causal tiles ------------------------
__global__ void __launch_bounds__(256, 2) u_scores_wmma()
{
    __shared__ __align__(16) __nv_bfloat16 buf[2][4][128 * GP];  // 48 KB
    const int bh = blockIdx.y;
    int tq = (int)((sqrtf(8.f * blockIdx.x + 1.f) - 1.f) * 0.5f);
    while ((tq + 1) * (tq + 2) / 2 <= (int)blockIdx.x) tq++;
    while (tq * (tq + 1) / 2 > (int)blockIdx.x) tq--;
    const int tk = blockIdx.x - tq * (tq + 1) / 2;
    const int qb = tq * 128, kb = tk * 128;

    const int tid = threadIdx.x, wid = tid >> 5, lane = tid & 31;
    const int warp_m = wid >> 2, warp_n = wid & 3;
    const int m0 = 0, n0 = 0;
    const __nv_bfloat16* Qh = g_Qh + ((size_t)bh * S + qb) * 128;
    const __nv_bfloat16* Ql = g_Ql + ((size_t)bh * S + qb) * 128;
    const __nv_bfloat16* Kh = g_Kh + ((size_t)bh * S + kb) * 128;
    const __nv_bfloat16* Kl = g_Kl + ((size_t)bh * S + kb) * 128;

    GEMM_MAINLOOP(Qh, Ql, Kh, Kl, 128, 8)

    float* att = g_att + (size_t)bh * S * S;
    const float* tqv = g_tq + bh * S;
    const float* tkv = g_tk + bh * S;

    float* epi = (float*)buf + wid * 256;
#pragma unroll
    for (int mi = 0; mi < 4; mi++) {
#pragma unroll
        for (int nj = 0; nj < 2; nj++) {
            wmma::store_matrix_sync(epi, acc[mi][nj], 16, wmma::mem_row_major);
            __syncwarp();
            const int r  = lane >> 1;
            const int c0 = (lane & 1) * 8;
            const int q  = qb + warp_m * 64 + mi * 16 + r;
            const int k  = kb + warp_n * 32 + nj * 16 + c0;
            const float tq2 = tqv[q];
            float v[8];
#pragma unroll
            for (int c = 0; c < 8; c++)
                v[c] = 0.25f * epi[r * 16 + c0 + c] - 0.125f * (tq2 + tkv[k + c]);
            float* dst = att + (size_t)q * S + k;
            *(float4*)(dst)     = make_float4(v[0], v[1], v[2], v[3]);
            *(float4*)(dst + 4) = make_float4(v[4], v[5], v[6], v[7]);
            __syncwarp();
        }
    }
}

// ---------------- block reduction helpers ----------------------------------
__device__ __forceinline__ float u_blkmax(float v, float* red)
{
    const int lane = threadIdx.x & 31, wid = threadIdx.x >> 5;
#pragma unroll
    for (int o = 16; o; o >>= 1) v = fmaxf(v, __shfl_xor_sync(~0u, v, o));
    __syncthreads();
    if (lane == 0) red[wid] = v;
    __syncthreads();
    float r = red[0];
#pragma unroll
    for (int i = 1; i < 8; i++) r = fmaxf(r, red[i]);
    return r;
}
__device__ __forceinline__ float u_blksum(float v, float* red)
{
    const int lane = threadIdx.x & 31, wid = threadIdx.x >> 5;
#pragma unroll
    for (int o = 16; o; o >>= 1) v += __shfl_xor_sync(~0u, v, o);
    __syncthreads();
    if (lane == 0) red[wid] = v;
    __syncthreads();
    float r = red[0];
#pragma unroll
    for (int i = 1; i < 8; i++) r += red[i];
    return r;
}

// ---------------- fused softmax -> cumsum -> decay -> softmax --------------
__global__ void __launch_bounds__(256) u_decay(const float* __restrict__ gammas)
{
    const int q  = blockIdx.x;
    const int bh = blockIdx.y;
    const int L  = q + 1;
    const int Lr = (L + 127) & ~127;
    const int tid  = threadIdx.x;
    const int lane = tid & 31, wid = tid >> 5;
    const float* row = g_att + ((size_t)bh * S + q) * S;

    const float g = gammas[bh & (H - 1)];
    const float gamma = -log1pf(expf(g));

    __shared__ float red[8];
    __shared__ float wsum[8];
    __shared__ float shtot;

    const int base = tid * 4;
    float s[4] = {0.f, 0.f, 0.f, 0.f};
    if (base < L) {
        const float4 sv = *(const float4*)(row + base);
        s[0] = sv.x; s[1] = sv.y; s[2] = sv.z; s[3] = sv.w;
    }
    bool valid[4];
#pragma unroll
    for (int i = 0; i < 4; i++) valid[i] = (base + i) < L;

    float m = -3.402823466e+38f;
#pragma unroll
    for (int i = 0; i < 4; i++) if (valid[i]) m = fmaxf(m, s[i]);
    m = u_blkmax(m, red);

    float p[4], c[4];
    float run = 0.f;
#pragma unroll
    for (int i = 0; i < 4; i++) {
        p[i] = valid[i] ? expf(s[i] - m) : 0.f;
        run += p[i];
        c[i] = run;
    }

    float x = run;
#pragma unroll
    for (int o = 1; o < 32; o <<= 1) {
        const float y = __shfl_up_sync(~0u, x, o);
        if (lane >= o) x += y;
    }
    const float texcl = x - run;
    if (lane == 31) wsum[wid] = x;
    __syncthreads();
    if (wid == 0 && lane < 8) {
        float w = wsum[lane];
#pragma unroll
        for (int o = 1; o < 8; o <<= 1) {
            const float y = __shfl_up_sync(0xffu, w, o);
            if (lane >= o) w += y;
        }
        wsum[lane] = w;
        if (lane == 7) shtot = w;
    }
    __syncthreads();
    const float off  = texcl + (wid ? wsum[wid - 1] : 0.f);
    const float invT = 1.f / shtot;

    float l[4];
#pragma unroll
    for (int i = 0; i < 4; i++) {
        const float cum  = (c[i] + off) * invT;
        const float tail = fmaxf(1.f - cum, 0.f);
        const float pos  = (float)(q - (base + i));
        const float dist = sqrtf(tail * pos);
        float eff = expf(gamma * dist);
        eff = fminf(fmaxf(eff, 1e-5f), 1e5f);
        l[i] = s[i] * eff;
    }

    float m2 = -3.402823466e+38f;
#pragma unroll
    for (int i = 0; i < 4; i++) if (valid[i]) m2 = fmaxf(m2, l[i]);
    m2 = u_blkmax(m2, red);

    float e[4];
    float es = 0.f;
#pragma unroll
    for (int i = 0; i < 4; i++) {
        e[i] = valid[i] ? expf(l[i] - m2) : 0.f;
        es += e[i];
    }
    es = u_blksum(es, red);
    const float invE = 1.f / es;

    if (base < Lr) {
        __align__(8) unsigned short hh[4], ll[4], h2[4], l2[4];
#pragma unroll
        for (int i = 0; i < 4; i++) {
            const float pv = (q == 0) ? 0.f : e[i] * invE;
            const __nv_bfloat16 ph = __float2bfloat16(pv);
            hh[i] = __bfloat16_as_ushort(ph);
            ll[i] = __bfloat16_as_ushort(__float2bfloat16(pv - __bfloat162float(ph)));
            const float p2 = pv * pv;
            const __nv_bfloat16 qh2 = __float2bfloat16(p2);
            h2[i] = __bfloat16_as_ushort(qh2);
            l2[i] = __bfloat16_as_ushort(__float2bfloat16(p2 - __bfloat162float(qh2)));
        }
        const size_t pidx = ((size_t)bh * S + q) * S + base;
        *(uint2*)(g_sch + pidx) = *(uint2*)hh;
        *(uint2*)(g_scl + pidx) = *(uint2*)ll;
        *(uint2*)(g_s2h + pidx) = *(uint2*)h2;
        *(uint2*)(g_s2l + pidx) = *(uint2*)l2;
    }
}

// ---------------- WMMA AV: mean = sc@vm (warps 0-3), cov = sc^2@vc (4-7) ---
constexpr int AP  = 24;
constexpr int BPp = 72;

__global__ void __launch_bounds__(256, 2) u_av_wmma()
{
    __shared__ __align__(16) __nv_bfloat16 sA[4][128 * AP];
    __shared__ __align__(16) __nv_bfloat16 sB[4][16 * BPp];

    const int bh = blockIdx.y;
    const int qb = (7 - blockIdx.x) * 128;
    const int tid = threadIdx.x, wid = tid >> 5, lane = tid & 31;
    const int wg = wid >> 2, w4 = wid & 3;

    const size_t aoff = ((size_t)bh * S + qb) * S;
    const size_t vb   = (size_t)bh * S * DK;
    const __nv_bfloat16* Ap[4] = {g_sch + aoff, g_scl + aoff, g_s2h + aoff, g_s2l + aoff};
    const __nv_bfloat16* Vp[4] = {g_Vmh + vb, g_Vml + vb, g_Vch + vb, g_Vcl + vb};

    wmma::fragment<wmma::accumulator, 16, 16, 16, float> acc[2][4];
#pragma unroll
    for (int mi = 0; mi < 2; mi++)
#pragma unroll
        for (int nj = 0; nj < 4; nj++) wmma::fill_fragment(acc[mi][nj], 0.f);

    const int kend = qb + 128;
    for (int kb = 0; kb < kend; kb += 16) {
#pragma unroll
        for (int i = 0; i < 4; i++) {
            const int c = tid + i * 256;
            const int pl = c >> 8, rr = (c & 255) >> 1, col8 = (c & 1) * 8;
            CP16(&sA[pl][rr * AP + col8], Ap[pl] + (size_t)rr * S + kb + col8);
        }
#pragma unroll
        for (int i = 0; i < 2; i++) {
            const int c = tid + i * 256;
            const int mtx = c >> 7, idx = c & 127;
            const int rr = idx >> 3, col8 = (idx & 7) * 8;
            CP16(&sB[mtx][rr * BPp + col8], Vp[mtx] + (size_t)(kb + rr) * DK + col8);
        }
        CP_COMMIT();
        CP_WAIT(0);
        __syncthreads();

        const __nv_bfloat16* aHp = wg ? sA[2] : sA[0];
        const __nv_bfloat16* aLp = wg ? sA[3] : sA[1];
        const __nv_bfloat16* bHp = wg ? sB[2] : sB[0];
        const __nv_bfloat16* bLp = wg ? sB[3] : sB[1];

        wmma::fragment<wmma::matrix_a, 16, 16, 16, __nv_bfloat16, wmma::row_major> aH[2], aL[2];
#pragma unroll
        for (int mi = 0; mi < 2; mi++) {
            const int row = w4 * 32 + mi * 16;
            wmma::load_matrix_sync(aH[mi], aHp + row * AP, AP);
            wmma::load_matrix_sync(aL[mi], aLp + row * AP, AP);
        }
#pragma unroll
        for (int nj = 0; nj < 4; nj++) {
            wmma::fragment<wmma::matrix_b, 16, 16, 16, __nv_bfloat16, wmma::row_major> bH, bL;
            wmma::load_matrix_sync(bH, bHp + nj * 16, BPp);
            wmma::load_matrix_sync(bL, bLp + nj * 16, BPp);
#pragma unroll
            for (int mi = 0; mi < 2; mi++) {
                wmma::mma_sync(acc[mi][nj], aH[mi], bH, acc[mi][nj]);
                wmma::mma_sync(acc[mi][nj], aH[mi], bL, acc[mi][nj]);
                wmma::mma_sync(acc[mi][nj], aL[mi], bH, acc[mi][nj]);
            }
        }
        __syncthreads();
    }

    const int b = bh >> 3, h = bh & 7;
    __nv_bfloat16* dh = wg ? g_cch : g_cmh;
    __nv_bfloat16* dl = wg ? g_ccl : g_cml;
    float* epi = (float*)sA + wid * 256;
#pragma unroll
    for (int mi = 0; mi < 2; mi++) {
#pragma unroll
        for (int nj = 0; nj < 4; nj++) {
            wmma::store_matrix_sync(epi, acc[mi][nj], 16, wmma::mem_row_major);
            __syncwarp();
            const int r  = lane >> 1;
            const int c0 = (lane & 1) * 8;
            const int s  = qb + w4 * 32 + mi * 16 + r;
            const int d  = nj * 16 + c0;
            float v[8];
#pragma unroll
            for (int c = 0; c < 8; c++) v[c] = epi[r * 16 + c0 + c];
            uint4 uh, ul;
            pack8(v, uh, ul);
            const size_t o = ((size_t)(b * S + s)) * D + h * DK + d;
            *(uint4*)(dh + o) = uh;
            *(uint4*)(dl + o) = ul;
            __syncwarp();
        }
    }
}

// ---------------- host launcher --------------------------------------------
extern "C" void kernel_launch(void* const* d_in, const int* in_sizes, int n_in,
                              void* d_out, int out_size)
{
    const float* q_mean = (const float*)d_in[0];
    const float* q_cov  = (const float*)d_in[1];
    const float* k_mean = (const float*)d_in[2];
    const float* k_cov  = (const float*)d_in[3];
    const float* v_mean = (const float*)d_in[4];
    const float* v_cov  = (const float*)d_in[5];
    const float* Wqm = (const float*)d_in[6];  const float* bqm = (const float*)d_in[7];
    const float* Wqc = (const float*)d_in[8];  const float* bqc = (const float*)d_in[9];
    const float* Wkm = (const float*)d_in[10]; const float* bkm = (const float*)d_in[11];
    const float* Wkc = (const float*)d_in[12]; const float* bkc = (const float*)d_in[13];
    const float* Wvm = (const float*)d_in[14]; const float* bvm = (const float*)d_in[15];
    const float* Wvc = (const float*)d_in[16]; const float* bvc = (const float*)d_in[17];
    const float* Wom = (const float*)d_in[18]; const float* bom = (const float*)d_in[19];
    const float* Woc = (const float*)d_in[20]; const float* boc = (const float*)d_in[21];
    const float* gammas = (const float*)d_in[22];

    float* out = (float*)d_out;

    Ptr6f xs;   xs.p[0] = q_mean; xs.p[1] = q_cov; xs.p[2] = k_mean;
                xs.p[3] = k_cov;  xs.p[4] = v_mean; xs.p[5] = v_cov;
    Ptr8f ws;   ws.p[0] = Wqm; ws.p[1] = Wqc; ws.p[2] = Wkm; ws.p[3] = Wkc;
                ws.p[4] = Wvm; ws.p[5] = Wvc; ws.p[6] = Wom; ws.p[7] = Woc;
    Ptr6f bs;   bs.p[0] = bqm; bs.p[1] = bqc; bs.p[2] = bkm;
                bs.p[3] = bkc; bs.p[4] = bvm; bs.p[5] = bvc;

    u_split6  <<<dim3(MR * D / 1024, 1, 6), 256>>>(xs);
    u_splitWt8<<<dim3(D / 32, D / 32, 8), 256>>>(ws);
    u_gemm_proj<<<dim3(D / 128, MR / 128, 6), 256>>>(bs);
    u_rownorm <<<dim3(BHS / 8, 2), 256>>>();
    u_scores_wmma<<<dim3(36, BH), 256>>>();
    u_decay   <<<dim3(S, BH), 256>>>(gammas);
    u_av_wmma <<<dim3(S / 128, BH), 256>>>();
    u_gemm_out<<<dim3(D / 128, MR / 128, 2), 256>>>(bom, boc, out);
}

// round 11
// speedup vs baseline: 2.2185x; 1.0915x over previous
#include <cuda_runtime.h>
#include <cuda_fp16.h>
#include <mma.h>
#include <math.h>
#include <stdint.h>

using namespace nvcuda;

constexpr int B  = 8;
constexpr int S  = 1024;
constexpr int H  = 8;
constexpr int DK = 64;
constexpr int D  = 512;
constexpr int BH  = B * H;     // 64
constexpr int BHS = BH * S;    // 65536
constexpr int MR  = B * S;     // 8192

// ---------------- device scratch ----------------
__device__ float g_att[(size_t)BH * S * S];                 // raw scores
__device__ __half g_sch[(size_t)BH * S * S];                // prob hi
__device__ __half g_scl[(size_t)BH * S * S];                // prob lo
__device__ __half g_s2h[(size_t)BH * S * S];                // prob^2 hi
__device__ __half g_s2l[(size_t)BH * S * S];                // prob^2 lo
__device__ __half g_Qh[(size_t)BHS * 128];
__device__ __half g_Ql[(size_t)BHS * 128];
__device__ __half g_Kh[(size_t)BHS * 128];
__device__ __half g_Kl[(size_t)BHS * 128];
__device__ __half g_Vm[(size_t)BHS * DK];                   // single-plane V
__device__ __half g_Vc[(size_t)BHS * DK];
__device__ __half g_A6h[(size_t)6 * MR * D];
__device__ __half g_A6l[(size_t)6 * MR * D];
__device__ __half g_W8h[8 * D * D];
__device__ __half g_W8l[8 * D * D];
__device__ __half g_cmh[(size_t)MR * D];
__device__ __half g_cml[(size_t)MR * D];
__device__ __half g_cch[(size_t)MR * D];
__device__ __half g_ccl[(size_t)MR * D];
// raw fp32 covariance projections (pre-sqrt) for exact tq/tk
__device__ float g_rawQc[(size_t)BHS * DK];
__device__ float g_rawKc[(size_t)BHS * DK];
__device__ float g_tq[BHS];
__device__ float g_tk[BHS];

// ---------------- cp.async helpers ----------------
#define CP16(dst, src) asm volatile( \
    "cp.async.cg.shared.global [%0], [%1], 16;" \
    :: "r"((uint32_t)__cvta_generic_to_shared(dst)), "l"(src))
#define CP_COMMIT() asm volatile("cp.async.commit_group;")
#define CP_WAIT(n)  asm volatile("cp.async.wait_group %0;" :: "n"(n))

struct Ptr6f { const float* p[6]; };
struct Ptr8f { const float* p[8]; };

// ---------------- pack 8 fp32 -> fp16 hi/lo uint4 pair --------------------
__device__ __forceinline__ void pack8h(const float* v, uint4& uh, uint4& ul)
{
    __align__(16) unsigned short hh[8];
    __align__(16) unsigned short ll[8];
#pragma unroll
    for (int c = 0; c < 8; c++) {
        const __half x = __float2half_rn(v[c]);
        hh[c] = __half_as_ushort(x);
        ll[c] = __half_as_ushort(__float2half_rn(v[c] - __half2float(x)));
    }
    uh = *(uint4*)hh;
    ul = *(uint4*)ll;
}

// ---------------- batched fp32 -> fp16 hi/lo split (inputs) ----------------
__global__ void u_split6(Ptr6f xs)
{
    const size_t zo = (size_t)blockIdx.z * MR * D;
    const int i = (blockIdx.x * 256 + threadIdx.x) * 4;
    const float4 fv = *(const float4*)(xs.p[blockIdx.z] + i);
    const float v[4] = {fv.x, fv.y, fv.z, fv.w};
    __align__(8) unsigned short hh[4], ll[4];
#pragma unroll
    for (int c = 0; c < 4; c++) {
        const __half x = __float2half_rn(v[c]);
        hh[c] = __half_as_ushort(x);
        ll[c] = __half_as_ushort(__float2half_rn(v[c] - __half2float(x)));
    }
    *(uint2*)(g_A6h + zo + i) = *(uint2*)hh;
    *(uint2*)(g_A6l + zo + i) = *(uint2*)ll;
}

// ---------------- batched W[K,N] -> W^T[N,K] fp16 hi/lo --------------------
__global__ void u_splitWt8(Ptr8f ws)
{
    __shared__ float tile[32][33];
    const size_t zo = (size_t)blockIdx.z * D * D;
    const float* W = ws.p[blockIdx.z];
    const int k0 = blockIdx.y * 32, n0 = blockIdx.x * 32;
    const int tx = threadIdx.x & 31, tw = threadIdx.x >> 5;
    for (int r = tw; r < 32; r += 8)
        tile[r][tx] = W[(size_t)(k0 + r) * D + n0 + tx];
    __syncthreads();
    for (int r = tw; r < 32; r += 8) {
        const float v = tile[tx][r];
        const __half hv = __float2half_rn(v);
        const size_t o = zo + (size_t)(n0 + r) * D + k0 + tx;
        g_W8h[o] = hv;
        g_W8l[o] = __float2half_rn(v - __half2float(hv));
    }
}

// ===================  double-buffered WMMA GEMM core (fp16 3-term) ========
constexpr int GP = 24;   // smem pitch (16 + 8 pad)

#define GEMM_PREFETCH(dstbuf, koff)                                            \
    _Pragma("unroll")                                                          \
    for (int i = 0; i < 4; i++) {                                              \
        const int c = tid + i * 256;                                           \
        const int mtx = c >> 8, rr = (c & 255) >> 1, col8 = (c & 1) * 8;       \
        CP16(&buf[dstbuf][mtx][rr * GP + col8],                                \
             srcs[mtx] + (size_t)(baserow[mtx] + rr) * ldv + (koff) + col8);   \
    }

#define GEMM_MAINLOOP(Ah, Al, Bh, Bl, LD, NITER)                               \
    const __half* srcs[4] = {Ah, Al, Bh, Bl};                                  \
    const int baserow[4] = {m0, m0, n0, n0};                                   \
    const int ldv = (LD);                                                      \
    wmma::fragment<wmma::accumulator, 16, 16, 16, float> acc[4][2];            \
    _Pragma("unroll")                                                          \
    for (int mi = 0; mi < 4; mi++)                                             \
        _Pragma("unroll")                                                      \
        for (int nj = 0; nj < 2; nj++) wmma::fill_fragment(acc[mi][nj], 0.f);  \
    GEMM_PREFETCH(0, 0)                                                        \
    CP_COMMIT();                                                               \
    for (int kt = 0; kt < (NITER); kt++) {                                     \
        CP_WAIT(0);                                                            \
        __syncthreads();                                                       \
        if (kt + 1 < (NITER)) {                                                \
            const int bn = (kt + 1) & 1;                                       \
            GEMM_PREFETCH(bn, (kt + 1) * 16)                                   \
            CP_COMMIT();                                                       \
        }                                                                      \
        const __half* sAh = buf[kt & 1][0];                                    \
        const __half* sAl = buf[kt & 1][1];                                    \
        const __half* sBh = buf[kt & 1][2];                                    \
        const __half* sBl = buf[kt & 1][3];                                    \
        wmma::fragment<wmma::matrix_a, 16, 16, 16, __half, wmma::row_major> aH[4], aL[4]; \
        _Pragma("unroll")                                                      \
        for (int mi = 0; mi < 4; mi++) {                                       \
            const int row = warp_m * 64 + mi * 16;                             \
            wmma::load_matrix_sync(aH[mi], sAh + row * GP, GP);                \
            wmma::load_matrix_sync(aL[mi], sAl + row * GP, GP);                \
        }                                                                      \
        _Pragma("unroll")                                                      \
        for (int nj = 0; nj < 2; nj++) {                                       \
            const int col = warp_n * 32 + nj * 16;                             \
            wmma::fragment<wmma::matrix_b, 16, 16, 16, __half, wmma::col_major> bH, bL; \
            wmma::load_matrix_sync(bH, sBh + col * GP, GP);                    \
            wmma::load_matrix_sync(bL, sBl + col * GP, GP);                    \
            _Pragma("unroll")                                                  \
            for (int mi = 0; mi < 4; mi++) {                                   \
                wmma::mma_sync(acc[mi][nj], aH[mi], bH, acc[mi][nj]);          \
                wmma::mma_sync(acc[mi][nj], aH[mi], bL, acc[mi][nj]);          \
                wmma::mma_sync(acc[mi][nj], aL[mi], bH, acc[mi][nj]);          \
            }                                                                  \
        }                                                                      \
    }                                                                          \
    __syncthreads();

// ---------------- projection GEMM (z = 0..5), fused epilogue ---------------
// z: 0 qm, 1 qc(sqrt), 2 km, 3 kc(sqrt), 4 vm, 5 vc
__global__ void __launch_bounds__(256, 2) u_gemm_proj(Ptr6f biases)
{
    __shared__ __align__(16) __half buf[2][4][128 * GP];  // 48 KB
    const int z = blockIdx.z;
    const __half* Ah = g_A6h + (size_t)z * MR * D;
    const __half* Al = g_A6l + (size_t)z * MR * D;
    const __half* Bh = g_W8h + (size_t)z * D * D;
    const __half* Bl = g_W8l + (size_t)z * D * D;
    const float* bias = biases.p[z];
    const int tid = threadIdx.x, wid = tid >> 5, lane = tid & 31;
    const int m0 = blockIdx.y * 128, n0 = blockIdx.x * 128;
    const int warp_m = wid >> 2, warp_n = wid & 3;

    GEMM_MAINLOOP(Ah, Al, Bh, Bl, D, 32)

    float* epi = (float*)buf + wid * 256;
#pragma unroll
    for (int mi = 0; mi < 4; mi++) {
#pragma unroll
        for (int nj = 0; nj < 2; nj++) {
            wmma::store_matrix_sync(epi, acc[mi][nj], 16, wmma::mem_row_major);
            __syncwarp();
            const int r  = lane >> 1;
            const int c0 = (lane & 1) * 8;
            const int m  = m0 + warp_m * 64 + mi * 16 + r;
            const int n  = n0 + warp_n * 32 + nj * 16 + c0;
            float v[8];
#pragma unroll
            for (int c = 0; c < 8; c++) v[c] = epi[r * 16 + c0 + c] + bias[n + c];
            const int b = m >> 10, s = m & (S - 1);
            const int h = n >> 6, d = n & 63;
            if (z < 4) {
                if (z & 1) {
                    // dump raw fp32 (pre-sqrt) for exact tq/tk cov sums
                    float* raw = (z == 1) ? g_rawQc : g_rawKc;
                    const size_t ro = (((size_t)(b * H + h)) * S + s) * 64 + d;
                    *(float4*)(raw + ro)     = make_float4(v[0], v[1], v[2], v[3]);
                    *(float4*)(raw + ro + 4) = make_float4(v[4], v[5], v[6], v[7]);
#pragma unroll
                    for (int c = 0; c < 8; c++) v[c] = sqrtf(fmaxf(v[c], 1e-24f));
                }
                __half* dh = (z < 2) ? g_Qh : g_Kh;
                __half* dl = (z < 2) ? g_Ql : g_Kl;
                const size_t o = (((size_t)(b * H + h)) * S + s) * 128 + (z & 1) * 64 + d;
                uint4 uh, ul;
                pack8h(v, uh, ul);
                *(uint4*)(dh + o) = uh;
                *(uint4*)(dl + o) = ul;
            } else {
                // single fp16 plane for V
                __half* dv = (z == 4) ? g_Vm : g_Vc;
                __align__(16) unsigned short t[8];
#pragma unroll
                for (int c = 0; c < 8; c++) t[c] = __half_as_ushort(__float2half_rn(v[c]));
                const size_t o = (((size_t)(b * H + h)) * S + s) * 64 + d;
                *(uint4*)(dv + o) = *(uint4*)t;
            }
            __syncwarp();
        }
    }
}

// ---------------- output GEMM (z = 0 mean, 1 cov) --------------------------
__global__ void __launch_bounds__(256, 2) u_gemm_out(const float* bias0, const float* bias1,
                                                     float* out)
{
    __shared__ __align__(16) __half buf[2][4][128 * GP];
    const int z = blockIdx.z;
    const __half* Ah = z ? g_cch : g_cmh;
    const __half* Al = z ? g_ccl : g_cml;
    const __half* Bh = g_W8h + (size_t)(6 + z) * D * D;
    const __half* Bl = g_W8l + (size_t)(6 + z) * D * D;
    const float* bias = z ? bias1 : bias0;
    const int tid = threadIdx.x, wid = tid >> 5, lane = tid & 31;
    const int m0 = blockIdx.y * 128, n0 = blockIdx.x * 128;
    const int warp_m = wid >> 2, warp_n = wid & 3;

    GEMM_MAINLOOP(Ah, Al, Bh, Bl, D, 32)

    float* epi = (float*)buf + wid * 256;
    float* dstm = out + (size_t)z * MR * D;
#pragma unroll
    for (int mi = 0; mi < 4; mi++) {
#pragma unroll
        for (int nj = 0; nj < 2; nj++) {
            wmma::store_matrix_sync(epi, acc[mi][nj], 16, wmma::mem_row_major);
            __syncwarp();
            const int r  = lane >> 1;
            const int c0 = (lane & 1) * 8;
            const int m  = m0 + warp_m * 64 + mi * 16 + r;
            const int n  = n0 + warp_n * 32 + nj * 16 + c0;
            float v[8];
#pragma unroll
            for (int c = 0; c < 8; c++) v[c] = epi[r * 16 + c0 + c] + bias[n + c];
            float* dst = dstm + (size_t)m * D + n;
            *(float4*)(dst)     = make_float4(v[0], v[1], v[2], v[3]);
            *(float4*)(dst + 4) = make_float4(v[4], v[5], v[6], v[7]);
            __syncwarp();
        }
    }
}

// ---------------- exact row stats: tq = sum(qm^2) + sum(raw qc) ------------
__global__ void u_rownorm()
{
    const int row  = blockIdx.x * 8 + (threadIdx.x >> 5);
    const int lane = threadIdx.x & 31;
    const __half* ph = (blockIdx.y ? g_Kh : g_Qh) + (size_t)row * 128;
    const __half* pl = (blockIdx.y ? g_Kl : g_Ql) + (size_t)row * 128;
    const float* pc = (blockIdx.y ? g_rawKc : g_rawQc) + (size_t)row * DK;
    const float a0 = __half2float(ph[lane])      + __half2float(pl[lane]);
    const float a1 = __half2float(ph[lane + 32]) + __half2float(pl[lane + 32]);
    const float c0 = pc[lane], c1 = pc[lane + 32];
    float v = a0 * a0 + a1 * a1 + c0 + c1;
#pragma unroll
    for (int o = 16; o; o >>= 1) v += __shfl_xor_sync(~0u, v, o);
    if (lane == 0) (blockIdx.y ? g_tk : g_tq)[row] = v;
}

// ---------------- WMMA scores: 128x128 causal tiles ------------------------
__global__ void __launch_bounds__(256, 2) u_scores_wmma()
{
    __shared__ __align__(16) __half buf[2][4][128 * GP];  // 48 KB
    const int bh = blockIdx.y;
    int tq = (int)((sqrtf(8.f * blockIdx.x + 1.f) - 1.f) * 0.5f);
    while ((tq + 1) * (tq + 2) / 2 <= (int)blockIdx.x) tq++;
    while (tq * (tq + 1) / 2 > (int)blockIdx.x) tq--;
    const int tk = blockIdx.x - tq * (tq + 1) / 2;
    const int qb = tq * 128, kb = tk * 128;

    const int tid = threadIdx.x, wid = tid >> 5, lane = tid & 31;
    const int warp_m = wid >> 2, warp_n = wid & 3;
    const int m0 = 0, n0 = 0;
    const __half* Qh = g_Qh + ((size_t)bh * S + qb) * 128;
    const __half* Ql = g_Ql + ((size_t)bh * S + qb) * 128;
    const __half* Kh = g_Kh + ((size_t)bh * S + kb) * 128;
    const __half* Kl = g_Kl + ((size_t)bh * S + kb) * 128;

    GEMM_MAINLOOP(Qh, Ql, Kh, Kl, 128, 8)

    float* att = g_att + (size_t)bh * S * S;
    const float* tqv = g_tq + bh * S;
    const float* tkv = g_tk + bh * S;

    float* epi = (float*)buf + wid * 256;
#pragma unroll
    for (int mi = 0; mi < 4; mi++) {
#pragma unroll
        for (int nj = 0; nj < 2; nj++) {
            wmma::store_matrix_sync(epi, acc[mi][nj], 16, wmma::mem_row_major);
            __syncwarp();
            const int r  = lane >> 1;
            const int c0 = (lane & 1) * 8;
            const int q  = qb + warp_m * 64 + mi * 16 + r;
            const int k  = kb + warp_n * 32 + nj * 16 + c0;
            const float tq2 = tqv[q];
            float v[8];
#pragma unroll
            for (int c = 0; c < 8; c++)
                v[c] = 0.25f * epi[r * 16 + c0 + c] - 0.125f * (tq2 + tkv[k + c]);
            float* dst = att + (size_t)q * S + k;
            *(float4*)(dst)     = make_float4(v[0], v[1], v[2], v[3]);
            *(float4*)(dst + 4) = make_float4(v[4], v[5], v[6], v[7]);
            __syncwarp();
        }
    }
}

// ---------------- block reduction helpers ----------------------------------
__device__ __forceinline__ float u_blkmax(float v, float* red)
{
    const int lane = threadIdx.x & 31, wid = threadIdx.x >> 5;
#pragma unroll
    for (int o = 16; o; o >>= 1) v = fmaxf(v, __shfl_xor_sync(~0u, v, o));
    __syncthreads();
    if (lane == 0) red[wid] = v;
    __syncthreads();
    float r = red[0];
#pragma unroll
    for (int i = 1; i < 8; i++) r = fmaxf(r, red[i]);
    return r;
}
__device__ __forceinline__ float u_blksum(float v, float* red)
{
    const int lane = threadIdx.x & 31, wid = threadIdx.x >> 5;
#pragma unroll
    for (int o = 16; o; o >>= 1) v += __shfl_xor_sync(~0u, v, o);
    __syncthreads();
    if (lane == 0) red[wid] = v;
    __syncthreads();
    float r = red[0];
#pragma unroll
    for (int i = 1; i < 8; i++) r += red[i];
    return r;
}

// ---------------- fused softmax -> cumsum -> decay -> softmax --------------
__global__ void __launch_bounds__(256) u_decay(const float* __restrict__ gammas)
{
    const int q  = blockIdx.x;
    const int bh = blockIdx.y;
    const int L  = q + 1;
    const int Lr = (L + 127) & ~127;
    const int tid  = threadIdx.x;
    const int lane = tid & 31, wid = tid >> 5;
    const float* row = g_att + ((size_t)bh * S + q) * S;

    const float g = gammas[bh & (H - 1)];
    const float gamma = -log1pf(expf(g));

    __shared__ float red[8];
    __shared__ float wsum[8];
    __shared__ float shtot;

    const int base = tid * 4;
    float s[4] = {0.f, 0.f, 0.f, 0.f};
    if (base < L) {
        const float4 sv = *(const float4*)(row + base);
        s[0] = sv.x; s[1] = sv.y; s[2] = sv.z; s[3] = sv.w;
    }
    bool valid[4];
#pragma unroll
    for (int i = 0; i < 4; i++) valid[i] = (base + i) < L;

    float m = -3.402823466e+38f;
#pragma unroll
    for (int i = 0; i < 4; i++) if (valid[i]) m = fmaxf(m, s[i]);
    m = u_blkmax(m, red);

    float p[4], c[4];
    float run = 0.f;
#pragma unroll
    for (int i = 0; i < 4; i++) {
        p[i] = valid[i] ? expf(s[i] - m) : 0.f;
        run += p[i];
        c[i] = run;
    }

    float x = run;
#pragma unroll
    for (int o = 1; o < 32; o <<= 1) {
        const float y = __shfl_up_sync(~0u, x, o);
        if (lane >= o) x += y;
    }
    const float texcl = x - run;
    if (lane == 31) wsum[wid] = x;
    __syncthreads();
    if (wid == 0 && lane < 8) {
        float w = wsum[lane];
#pragma unroll
        for (int o = 1; o < 8; o <<= 1) {
            const float y = __shfl_up_sync(0xffu, w, o);
            if (lane >= o) w += y;
        }
        wsum[lane] = w;
        if (lane == 7) shtot = w;
    }
    __syncthreads();
    const float off  = texcl + (wid ? wsum[wid - 1] : 0.f);
    const float invT = 1.f / shtot;

    float l[4];
#pragma unroll
    for (int i = 0; i < 4; i++) {
        const float cum  = (c[i] + off) * invT;
        const float tail = fmaxf(1.f - cum, 0.f);
        const float pos  = (float)(q - (base + i));
        const float dist = sqrtf(tail * pos);
        float eff = expf(gamma * dist);
        eff = fminf(fmaxf(eff, 1e-5f), 1e5f);
        l[i] = s[i] * eff;
    }

    float m2 = -3.402823466e+38f;
#pragma unroll
    for (int i = 0; i < 4; i++) if (valid[i]) m2 = fmaxf(m2, l[i]);
    m2 = u_blkmax(m2, red);

    float e[4];
    float es = 0.f;
#pragma unroll
    for (int i = 0; i < 4; i++) {
        e[i] = valid[i] ? expf(l[i] - m2) : 0.f;
        es += e[i];
    }
    es = u_blksum(es, red);
    const float invE = 1.f / es;

    if (base < Lr) {
        __align__(8) unsigned short hh[4], ll[4], h2[4], l2[4];
#pragma unroll
        for (int i = 0; i < 4; i++) {
            const float pv = (q == 0) ? 0.f : e[i] * invE;
            const __half ph = __float2half_rn(pv);
            hh[i] = __half_as_ushort(ph);
            ll[i] = __half_as_ushort(__float2half_rn(pv - __half2float(ph)));
            const float p2 = pv * pv;
            const __half qh2 = __float2half_rn(p2);
            h2[i] = __half_as_ushort(qh2);
            l2[i] = __half_as_ushort(__float2half_rn(p2 - __half2float(qh2)));
        }
        const size_t pidx = ((size_t)bh * S + q) * S + base;
        *(uint2*)(g_sch + pidx) = *(uint2*)hh;
        *(uint2*)(g_scl + pidx) = *(uint2*)ll;
        *(uint2*)(g_s2h + pidx) = *(uint2*)h2;
        *(uint2*)(g_s2l + pidx) = *(uint2*)l2;
    }
}

// ---------------- WMMA AV (2-term): mean = (ph+pl)@Vm, cov = (p2h+p2l)@Vc --
// warps 0-3 mean, warps 4-7 cov. Double-buffered cp.async, one sync per step.
// Uses DYNAMIC shared memory (58368 B > 48 KB static cap).
constexpr int AP  = 24;
constexpr int BPp = 72;
constexpr int AV_SA_ELEMS = 128 * AP;          // per plane per stage
constexpr int AV_SB_ELEMS = 16 * BPp;          // per matrix per stage
constexpr int AV_SMEM = (2 * 4 * AV_SA_ELEMS + 2 * 2 * AV_SB_ELEMS) * 2;  // 58368 B

__global__ void __launch_bounds__(256, 2) u_av_wmma()
{
    extern __shared__ __align__(16) __half dynsm[];
    // layout: sA[stage][plane] then sB[stage][mtx]
    __half* sA[2][4];
    __half* sB[2][2];
#pragma unroll
    for (int st = 0; st < 2; st++)
#pragma unroll
        for (int pl = 0; pl < 4; pl++)
            sA[st][pl] = dynsm + (st * 4 + pl) * AV_SA_ELEMS;
    __half* sbbase = dynsm + 8 * AV_SA_ELEMS;
#pragma unroll
    for (int st = 0; st < 2; st++)
#pragma unroll
        for (int mt = 0; mt < 2; mt++)
            sB[st][mt] = sbbase + (st * 2 + mt) * AV_SB_ELEMS;

    const int bh = blockIdx.y;
    const int qb = (7 - blockIdx.x) * 128;
    const int tid = threadIdx.x, wid = tid >> 5, lane = tid & 31;
    const int wg = wid >> 2, w4 = wid & 3;

    const size_t aoff = ((size_t)bh * S + qb) * S;
    const size_t vb   = (size_t)bh * S * DK;
    const __half* Ap[4] = {g_sch + aoff, g_scl + aoff, g_s2h + aoff, g_s2l + aoff};
    const __half* Vp[2] = {g_Vm + vb, g_Vc + vb};

    wmma::fragment<wmma::accumulator, 16, 16, 16, float> acc[2][4];
#pragma unroll
    for (int mi = 0; mi < 2; mi++)
#pragma unroll
        for (int nj = 0; nj < 4; nj++) wmma::fill_fragment(acc[mi][nj], 0.f);

    const int NITER = (qb + 128) / 16;

#define AV_PREFETCH(bufi, kb)                                                  \
    _Pragma("unroll")                                                          \
    for (int i = 0; i < 4; i++) {                                              \
        const int c = tid + i * 256;                                           \
        const int pl = c >> 8, idx = c & 255;                                  \
        const int rr = idx >> 1, col8 = (idx & 1) * 8;                         \
        CP16(sA[bufi][pl] + rr * AP + col8, Ap[pl] + (size_t)rr * S + (kb) + col8); \
    }                                                                          \
    {                                                                          \
        const int mtx = tid >> 7, idx = tid & 127;                             \
        const int rr = idx >> 3, col8 = (idx & 7) * 8;                         \
        CP16(sB[bufi][mtx] + rr * BPp + col8, Vp[mtx] + (size_t)((kb) + rr) * DK + col8); \
    }

    AV_PREFETCH(0, 0)
    CP_COMMIT();

    for (int kt = 0; kt < NITER; kt++) {
        CP_WAIT(0);
        __syncthreads();
        if (kt + 1 < NITER) {
            const int bn = (kt + 1) & 1;
            AV_PREFETCH(bn, (kt + 1) * 16)
            CP_COMMIT();
        }
        const int cur = kt & 1;
        const __half* aHp = sA[cur][wg * 2];
        const __half* aLp = sA[cur][wg * 2 + 1];
        const __half* bVp = sB[cur][wg];

        wmma::fragment<wmma::matrix_a, 16, 16, 16, __half, wmma::row_major> aH[2], aL[2];
#pragma unroll
        for (int mi = 0; mi < 2; mi++) {
            const int row = w4 * 32 + mi * 16;
            wmma::load_matrix_sync(aH[mi], aHp + row * AP, AP);
            wmma::load_matrix_sync(aL[mi], aLp + row * AP, AP);
        }
#pragma unroll
        for (int nj = 0; nj < 4; nj++) {
            wmma::fragment<wmma::matrix_b, 16, 16, 16, __half, wmma::row_major> bV;
            wmma::load_matrix_sync(bV, bVp + nj * 16, BPp);
#pragma unroll
            for (int mi = 0; mi < 2; mi++) {
                wmma::mma_sync(acc[mi][nj], aH[mi], bV, acc[mi][nj]);
                wmma::mma_sync(acc[mi][nj], aL[mi], bV, acc[mi][nj]);
            }
        }
    }
    __syncthreads();

    const int b = bh >> 3, h = bh & 7;
    __half* dh = wg ? g_cch : g_cmh;
    __half* dl = wg ? g_ccl : g_cml;
    float* epi = (float*)dynsm + wid * 256;
#pragma unroll
    for (int mi = 0; mi < 2; mi++) {
#pragma unroll
        for (int nj = 0; nj < 4; nj++) {
            wmma::store_matrix_sync(epi, acc[mi][nj], 16, wmma::mem_row_major);
            __syncwarp();
            const int r  = lane >> 1;
            const int c0 = (lane & 1) * 8;
            const int s  = qb + w4 * 32 + mi * 16 + r;
            const int d  = nj * 16 + c0;
            float v[8];
#pragma unroll
            for (int c = 0; c < 8; c++) v[c] = epi[r * 16 + c0 + c];
            uint4 uh, ul;
            pack8h(v, uh, ul);
            const size_t o = ((size_t)(b * S + s)) * D + h * DK + d;
            *(uint4*)(dh + o) = uh;
            *(uint4*)(dl + o) = ul;
            __syncwarp();
        }
    }
#undef AV_PREFETCH
}

// ---------------- host launcher --------------------------------------------
extern "C" void kernel_launch(void* const* d_in, const int* in_sizes, int n_in,
                              void* d_out, int out_size)
{
    const float* q_mean = (const float*)d_in[0];
    const float* q_cov  = (const float*)d_in[1];
    const float* k_mean = (const float*)d_in[2];
    const float* k_cov  = (const float*)d_in[3];
    const float* v_mean = (const float*)d_in[4];
    const float* v_cov  = (const float*)d_in[5];
    const float* Wqm = (const float*)d_in[6];  const float* bqm = (const float*)d_in[7];
    const float* Wqc = (const float*)d_in[8];  const float* bqc = (const float*)d_in[9];
    const float* Wkm = (const float*)d_in[10]; const float* bkm = (const float*)d_in[11];
    const float* Wkc = (const float*)d_in[12]; const float* bkc = (const float*)d_in[13];
    const float* Wvm = (const float*)d_in[14]; const float* bvm = (const float*)d_in[15];
    const float* Wvc = (const float*)d_in[16]; const float* bvc = (const float*)d_in[17];
    const float* Wom = (const float*)d_in[18]; const float* bom = (const float*)d_in[19];
    const float* Woc = (const float*)d_in[20]; const float* boc = (const float*)d_in[21];
    const float* gammas = (const float*)d_in[22];

    float* out = (float*)d_out;

    static bool attr_set = false;
    if (!attr_set) {
        cudaFuncSetAttribute(u_av_wmma, cudaFuncAttributeMaxDynamicSharedMemorySize, AV_SMEM);
        attr_set = true;
    }

    Ptr6f xs;   xs.p[0] = q_mean; xs.p[1] = q_cov; xs.p[2] = k_mean;
                xs.p[3] = k_cov;  xs.p[4] = v_mean; xs.p[5] = v_cov;
    Ptr8f ws;   ws.p[0] = Wqm; ws.p[1] = Wqc; ws.p[2] = Wkm; ws.p[3] = Wkc;
                ws.p[4] = Wvm; ws.p[5] = Wvc; ws.p[6] = Wom; ws.p[7] = Woc;
    Ptr6f bs;   bs.p[0] = bqm; bs.p[1] = bqc; bs.p[2] = bkm;
                bs.p[3] = bkc; bs.p[4] = bvm; bs.p[5] = bvc;

    u_split6  <<<dim3(MR * D / 1024, 1, 6), 256>>>(xs);
    u_splitWt8<<<dim3(D / 32, D / 32, 8), 256>>>(ws);
    u_gemm_proj<<<dim3(D / 128, MR / 128, 6), 256>>>(bs);
    u_rownorm <<<dim3(BHS / 8, 2), 256>>>();
    u_scores_wmma<<<dim3(36, BH), 256>>>();
    u_decay   <<<dim3(S, BH), 256>>>(gammas);
    u_av_wmma <<<dim3(S / 128, BH), 256, AV_SMEM>>>();
    u_gemm_out<<<dim3(D / 128, MR / 128, 2), 256>>>(bom, boc, out);
}

// round 12
// speedup vs baseline: 2.3918x; 1.0781x over previous
#include <cuda_runtime.h>
#include <cuda_fp16.h>
#include <mma.h>
#include <math.h>
#include <stdint.h>

using namespace nvcuda;

constexpr int B  = 8;
constexpr int S  = 1024;
constexpr int H  = 8;
constexpr int DK = 64;
constexpr int D  = 512;
constexpr int BH  = B * H;     // 64
constexpr int BHS = BH * S;    // 65536
constexpr int MR  = B * S;     // 8192

// ---------------- device scratch ----------------
__device__ float g_att[(size_t)BH * S * S];                 // raw scores
__device__ __half g_sch[(size_t)BH * S * S];                // prob hi
__device__ __half g_scl[(size_t)BH * S * S];                // prob lo
__device__ __half g_s2h[(size_t)BH * S * S];                // prob^2 hi
__device__ __half g_s2l[(size_t)BH * S * S];                // prob^2 lo
__device__ __half g_Qh[(size_t)BHS * 128];
__device__ __half g_Ql[(size_t)BHS * 128];
__device__ __half g_Kh[(size_t)BHS * 128];
__device__ __half g_Kl[(size_t)BHS * 128];
__device__ __half g_Vm[(size_t)BHS * DK];                   // single-plane V
__device__ __half g_Vc[(size_t)BHS * DK];
__device__ __half g_A6h[(size_t)6 * MR * D];
__device__ __half g_A6l[(size_t)6 * MR * D];
__device__ __half g_W8h[8 * D * D];
__device__ __half g_W8l[8 * D * D];
__device__ __half g_cmh[(size_t)MR * D];
__device__ __half g_cml[(size_t)MR * D];
__device__ __half g_cch[(size_t)MR * D];
__device__ __half g_ccl[(size_t)MR * D];
// raw fp32 covariance projections (pre-sqrt) for exact tq/tk
__device__ float g_rawQc[(size_t)BHS * DK];
__device__ float g_rawKc[(size_t)BHS * DK];
__device__ float g_tq[BHS];
__device__ float g_tk[BHS];

// ---------------- cp.async helpers ----------------
#define CP16(dst, src) asm volatile( \
    "cp.async.cg.shared.global [%0], [%1], 16;" \
    :: "r"((uint32_t)__cvta_generic_to_shared(dst)), "l"(src))
#define CP_COMMIT() asm volatile("cp.async.commit_group;")
#define CP_WAIT(n)  asm volatile("cp.async.wait_group %0;" :: "n"(n))

struct Ptr6f { const float* p[6]; };
struct Ptr8f { const float* p[8]; };

// ---------------- pack 8 fp32 -> fp16 hi/lo uint4 pair --------------------
__device__ __forceinline__ void pack8h(const float* v, uint4& uh, uint4& ul)
{
    __align__(16) unsigned short hh[8];
    __align__(16) unsigned short ll[8];
#pragma unroll
    for (int c = 0; c < 8; c++) {
        const __half x = __float2half_rn(v[c]);
        hh[c] = __half_as_ushort(x);
        ll[c] = __half_as_ushort(__float2half_rn(v[c] - __half2float(x)));
    }
    uh = *(uint4*)hh;
    ul = *(uint4*)ll;
}

// ---------------- batched fp32 -> fp16 hi/lo split (inputs) ----------------
__global__ void u_split6(Ptr6f xs)
{
    const size_t zo = (size_t)blockIdx.z * MR * D;
    const int i = (blockIdx.x * 256 + threadIdx.x) * 4;
    const float4 fv = *(const float4*)(xs.p[blockIdx.z] + i);
    const float v[4] = {fv.x, fv.y, fv.z, fv.w};
    __align__(8) unsigned short hh[4], ll[4];
#pragma unroll
    for (int c = 0; c < 4; c++) {
        const __half x = __float2half_rn(v[c]);
        hh[c] = __half_as_ushort(x);
        ll[c] = __half_as_ushort(__float2half_rn(v[c] - __half2float(x)));
    }
    *(uint2*)(g_A6h + zo + i) = *(uint2*)hh;
    *(uint2*)(g_A6l + zo + i) = *(uint2*)ll;
}

// ---------------- batched W[K,N] -> W^T[N,K] fp16 hi/lo --------------------
__global__ void u_splitWt8(Ptr8f ws)
{
    __shared__ float tile[32][33];
    const size_t zo = (size_t)blockIdx.z * D * D;
    const float* W = ws.p[blockIdx.z];
    const int k0 = blockIdx.y * 32, n0 = blockIdx.x * 32;
    const int tx = threadIdx.x & 31, tw = threadIdx.x >> 5;
    for (int r = tw; r < 32; r += 8)
        tile[r][tx] = W[(size_t)(k0 + r) * D + n0 + tx];
    __syncthreads();
    for (int r = tw; r < 32; r += 8) {
        const float v = tile[tx][r];
        const __half hv = __float2half_rn(v);
        const size_t o = zo + (size_t)(n0 + r) * D + k0 + tx;
        g_W8h[o] = hv;
        g_W8l[o] = __float2half_rn(v - __half2float(hv));
    }
}

// ===================  double-buffered WMMA GEMM core  ======================
// MODE 0: aH*bH + aH*bL + aL*bH (3-term)
// MODE 1: aH*bH + aL*bH        (2-term, drop B-lo)
// MODE 2: aH*bH + aH*bL        (2-term, drop A-lo)
constexpr int GP = 24;   // smem pitch (16 + 8 pad)

#define GEMM_PREFETCH(dstbuf, koff)                                            \
    _Pragma("unroll")                                                          \
    for (int i = 0; i < 4; i++) {                                              \
        const int c = tid + i * 256;                                           \
        const int mtx = c >> 8, rr = (c & 255) >> 1, col8 = (c & 1) * 8;       \
        CP16(&buf[dstbuf][mtx][rr * GP + col8],                                \
             srcs[mtx] + (size_t)(baserow[mtx] + rr) * ldv + (koff) + col8);   \
    }

#define GEMM_MAINLOOP(Ah, Al, Bh, Bl, LD, NITER, MODE)                         \
    const __half* srcs[4] = {Ah, Al, Bh, Bl};                                  \
    const int baserow[4] = {m0, m0, n0, n0};                                   \
    const int ldv = (LD);                                                      \
    const int mode = (MODE);                                                   \
    wmma::fragment<wmma::accumulator, 16, 16, 16, float> acc[4][2];            \
    _Pragma("unroll")                                                          \
    for (int mi = 0; mi < 4; mi++)                                             \
        _Pragma("unroll")                                                      \
        for (int nj = 0; nj < 2; nj++) wmma::fill_fragment(acc[mi][nj], 0.f);  \
    GEMM_PREFETCH(0, 0)                                                        \
    CP_COMMIT();                                                               \
    for (int kt = 0; kt < (NITER); kt++) {                                     \
        CP_WAIT(0);                                                            \
        __syncthreads();                                                       \
        if (kt + 1 < (NITER)) {                                                \
            const int bn = (kt + 1) & 1;                                       \
            GEMM_PREFETCH(bn, (kt + 1) * 16)                                   \
            CP_COMMIT();                                                       \
        }                                                                      \
        const __half* sAh = buf[kt & 1][0];                                    \
        const __half* sAl = buf[kt & 1][1];                                    \
        const __half* sBh = buf[kt & 1][2];                                    \
        const __half* sBl = buf[kt & 1][3];                                    \
        wmma::fragment<wmma::matrix_a, 16, 16, 16, __half, wmma::row_major> aH[4], aL[4]; \
        _Pragma("unroll")                                                      \
        for (int mi = 0; mi < 4; mi++) {                                       \
            const int row = warp_m * 64 + mi * 16;                             \
            wmma::load_matrix_sync(aH[mi], sAh + row * GP, GP);                \
            if (mode != 2) wmma::load_matrix_sync(aL[mi], sAl + row * GP, GP); \
        }                                                                      \
        _Pragma("unroll")                                                      \
        for (int nj = 0; nj < 2; nj++) {                                       \
            const int col = warp_n * 32 + nj * 16;                             \
            wmma::fragment<wmma::matrix_b, 16, 16, 16, __half, wmma::col_major> bH, bL; \
            wmma::load_matrix_sync(bH, sBh + col * GP, GP);                    \
            if (mode != 1) wmma::load_matrix_sync(bL, sBl + col * GP, GP);     \
            _Pragma("unroll")                                                  \
            for (int mi = 0; mi < 4; mi++) {                                   \
                wmma::mma_sync(acc[mi][nj], aH[mi], bH, acc[mi][nj]);          \
                if (mode != 1) wmma::mma_sync(acc[mi][nj], aH[mi], bL, acc[mi][nj]); \
                if (mode != 2) wmma::mma_sync(acc[mi][nj], aL[mi], bH, acc[mi][nj]); \
            }                                                                  \
        }                                                                      \
    }                                                                          \
    __syncthreads();

// ---------------- projection GEMM (z = 0..5), fused epilogue ---------------
// z: 0 qm, 1 qc(sqrt), 2 km, 3 kc(sqrt) (3-term); 4 vm, 5 vc (2-term)
__global__ void __launch_bounds__(256, 2) u_gemm_proj(Ptr6f biases)
{
    __shared__ __align__(16) __half buf[2][4][128 * GP];  // 48 KB
    const int z = blockIdx.z;
    const __half* Ah = g_A6h + (size_t)z * MR * D;
    const __half* Al = g_A6l + (size_t)z * MR * D;
    const __half* Bh = g_W8h + (size_t)z * D * D;
    const __half* Bl = g_W8l + (size_t)z * D * D;
    const float* bias = biases.p[z];
    const int tid = threadIdx.x, wid = tid >> 5, lane = tid & 31;
    const int m0 = blockIdx.y * 128, n0 = blockIdx.x * 128;
    const int warp_m = wid >> 2, warp_n = wid & 3;

    GEMM_MAINLOOP(Ah, Al, Bh, Bl, D, 32, (z < 4) ? 0 : 1)

    float* epi = (float*)buf + wid * 256;
#pragma unroll
    for (int mi = 0; mi < 4; mi++) {
#pragma unroll
        for (int nj = 0; nj < 2; nj++) {
            wmma::store_matrix_sync(epi, acc[mi][nj], 16, wmma::mem_row_major);
            __syncwarp();
            const int r  = lane >> 1;
            const int c0 = (lane & 1) * 8;
            const int m  = m0 + warp_m * 64 + mi * 16 + r;
            const int n  = n0 + warp_n * 32 + nj * 16 + c0;
            float v[8];
#pragma unroll
            for (int c = 0; c < 8; c++) v[c] = epi[r * 16 + c0 + c] + bias[n + c];
            const int b = m >> 10, s = m & (S - 1);
            const int h = n >> 6, d = n & 63;
            if (z < 4) {
                if (z & 1) {
                    float* raw = (z == 1) ? g_rawQc : g_rawKc;
                    const size_t ro = (((size_t)(b * H + h)) * S + s) * 64 + d;
                    *(float4*)(raw + ro)     = make_float4(v[0], v[1], v[2], v[3]);
                    *(float4*)(raw + ro + 4) = make_float4(v[4], v[5], v[6], v[7]);
#pragma unroll
                    for (int c = 0; c < 8; c++) v[c] = sqrtf(fmaxf(v[c], 1e-24f));
                }
                __half* dh = (z < 2) ? g_Qh : g_Kh;
                __half* dl = (z < 2) ? g_Ql : g_Kl;
                const size_t o = (((size_t)(b * H + h)) * S + s) * 128 + (z & 1) * 64 + d;
                uint4 uh, ul;
                pack8h(v, uh, ul);
                *(uint4*)(dh + o) = uh;
                *(uint4*)(dl + o) = ul;
            } else {
                __half* dv = (z == 4) ? g_Vm : g_Vc;
                __align__(16) unsigned short t[8];
#pragma unroll
                for (int c = 0; c < 8; c++) t[c] = __half_as_ushort(__float2half_rn(v[c]));
                const size_t o = (((size_t)(b * H + h)) * S + s) * 64 + d;
                *(uint4*)(dv + o) = *(uint4*)t;
            }
            __syncwarp();
        }
    }
}

// ---------------- output GEMM (z = 0 mean, 1 cov), 2-term ------------------
__global__ void __launch_bounds__(256, 2) u_gemm_out(const float* bias0, const float* bias1,
                                                     float* out)
{
    __shared__ __align__(16) __half buf[2][4][128 * GP];
    const int z = blockIdx.z;
    const __half* Ah = z ? g_cch : g_cmh;
    const __half* Al = z ? g_ccl : g_cml;
    const __half* Bh = g_W8h + (size_t)(6 + z) * D * D;
    const __half* Bl = g_W8l + (size_t)(6 + z) * D * D;
    const float* bias = z ? bias1 : bias0;
    const int tid = threadIdx.x, wid = tid >> 5, lane = tid & 31;
    const int m0 = blockIdx.y * 128, n0 = blockIdx.x * 128;
    const int warp_m = wid >> 2, warp_n = wid & 3;

    GEMM_MAINLOOP(Ah, Al, Bh, Bl, D, 32, 1)

    float* epi = (float*)buf + wid * 256;
    float* dstm = out + (size_t)z * MR * D;
#pragma unroll
    for (int mi = 0; mi < 4; mi++) {
#pragma unroll
        for (int nj = 0; nj < 2; nj++) {
            wmma::store_matrix_sync(epi, acc[mi][nj], 16, wmma::mem_row_major);
            __syncwarp();
            const int r  = lane >> 1;
            const int c0 = (lane & 1) * 8;
            const int m  = m0 + warp_m * 64 + mi * 16 + r;
            const int n  = n0 + warp_n * 32 + nj * 16 + c0;
            float v[8];
#pragma unroll
            for (int c = 0; c < 8; c++) v[c] = epi[r * 16 + c0 + c] + bias[n + c];
            float* dst = dstm + (size_t)m * D + n;
            *(float4*)(dst)     = make_float4(v[0], v[1], v[2], v[3]);
            *(float4*)(dst + 4) = make_float4(v[4], v[5], v[6], v[7]);
            __syncwarp();
        }
    }
}

// ---------------- exact row stats: tq = sum(qm^2) + sum(raw qc) ------------
__global__ void u_rownorm()
{
    const int row  = blockIdx.x * 8 + (threadIdx.x >> 5);
    const int lane = threadIdx.x & 31;
    const __half* ph = (blockIdx.y ? g_Kh : g_Qh) + (size_t)row * 128;
    const __half* pl = (blockIdx.y ? g_Kl : g_Ql) + (size_t)row * 128;
    const float* pc = (blockIdx.y ? g_rawKc : g_rawQc) + (size_t)row * DK;
    const float a0 = __half2float(ph[lane])      + __half2float(pl[lane]);
    const float a1 = __half2float(ph[lane + 32]) + __half2float(pl[lane + 32]);
    const float c0 = pc[lane], c1 = pc[lane + 32];
    float v = a0 * a0 + a1 * a1 + c0 + c1;
#pragma unroll
    for (int o = 16; o; o >>= 1) v += __shfl_xor_sync(~0u, v, o);
    if (lane == 0) (blockIdx.y ? g_tk : g_tq)[row] = v;
}

// ---------------- WMMA scores: 128x128 causal tiles, 2-term (drop Q-lo) ----
__global__ void __launch_bounds__(256, 2) u_scores_wmma()
{
    __shared__ __align__(16) __half buf[2][4][128 * GP];  // 48 KB
    const int bh = blockIdx.y;
    int tq = (int)((sqrtf(8.f * blockIdx.x + 1.f) - 1.f) * 0.5f);
    while ((tq + 1) * (tq + 2) / 2 <= (int)blockIdx.x) tq++;
    while (tq * (tq + 1) / 2 > (int)blockIdx.x) tq--;
    const int tk = blockIdx.x - tq * (tq + 1) / 2;
    const int qb = tq * 128, kb = tk * 128;

    const int tid = threadIdx.x, wid = tid >> 5, lane = tid & 31;
    const int warp_m = wid >> 2, warp_n = wid & 3;
    const int m0 = 0, n0 = 0;
    const __half* Qh = g_Qh + ((size_t)bh * S + qb) * 128;
    const __half* Ql = g_Ql + ((size_t)bh * S + qb) * 128;
    const __half* Kh = g_Kh + ((size_t)bh * S + kb) * 128;
    const __half* Kl = g_Kl + ((size_t)bh * S + kb) * 128;

    GEMM_MAINLOOP(Qh, Ql, Kh, Kl, 128, 8, 2)

    float* att = g_att + (size_t)bh * S * S;
    const float* tqv = g_tq + bh * S;
    const float* tkv = g_tk + bh * S;

    float* epi = (float*)buf + wid * 256;
#pragma unroll
    for (int mi = 0; mi < 4; mi++) {
#pragma unroll
        for (int nj = 0; nj < 2; nj++) {
            wmma::store_matrix_sync(epi, acc[mi][nj], 16, wmma::mem_row_major);
            __syncwarp();
            const int r  = lane >> 1;
            const int c0 = (lane & 1) * 8;
            const int q  = qb + warp_m * 64 + mi * 16 + r;
            const int k  = kb + warp_n * 32 + nj * 16 + c0;
            const float tq2 = tqv[q];
            float v[8];
#pragma unroll
            for (int c = 0; c < 8; c++)
                v[c] = 0.25f * epi[r * 16 + c0 + c] - 0.125f * (tq2 + tkv[k + c]);
            float* dst = att + (size_t)q * S + k;
            *(float4*)(dst)     = make_float4(v[0], v[1], v[2], v[3]);
            *(float4*)(dst + 4) = make_float4(v[4], v[5], v[6], v[7]);
            __syncwarp();
        }
    }
}

// ---------------- block reduction helpers ----------------------------------
__device__ __forceinline__ float u_blkmax(float v, float* red)
{
    const int lane = threadIdx.x & 31, wid = threadIdx.x >> 5;
#pragma unroll
    for (int o = 16; o; o >>= 1) v = fmaxf(v, __shfl_xor_sync(~0u, v, o));
    __syncthreads();
    if (lane == 0) red[wid] = v;
    __syncthreads();
    float r = red[0];
#pragma unroll
    for (int i = 1; i < 8; i++) r = fmaxf(r, red[i]);
    return r;
}
__device__ __forceinline__ float u_blksum(float v, float* red)
{
    const int lane = threadIdx.x & 31, wid = threadIdx.x >> 5;
#pragma unroll
    for (int o = 16; o; o >>= 1) v += __shfl_xor_sync(~0u, v, o);
    __syncthreads();
    if (lane == 0) red[wid] = v;
    __syncthreads();
    float r = red[0];
#pragma unroll
    for (int i = 1; i < 8; i++) r += red[i];
    return r;
}

// ---------------- fused softmax -> cumsum -> decay -> softmax --------------
__global__ void __launch_bounds__(256) u_decay(const float* __restrict__ gammas)
{
    const int q  = blockIdx.x;
    const int bh = blockIdx.y;
    const int L  = q + 1;
    const int Lr = (L + 127) & ~127;
    const int tid  = threadIdx.x;
    const int lane = tid & 31, wid = tid >> 5;
    const float* row = g_att + ((size_t)bh * S + q) * S;

    const float g = gammas[bh & (H - 1)];
    const float gamma = -log1pf(expf(g));

    __shared__ float red[8];
    __shared__ float wsum[8];
    __shared__ float shtot;

    const int base = tid * 4;
    float s[4] = {0.f, 0.f, 0.f, 0.f};
    if (base < L) {
        const float4 sv = *(const float4*)(row + base);
        s[0] = sv.x; s[1] = sv.y; s[2] = sv.z; s[3] = sv.w;
    }
    bool valid[4];
#pragma unroll
    for (int i = 0; i < 4; i++) valid[i] = (base + i) < L;

    float m = -3.402823466e+38f;
#pragma unroll
    for (int i = 0; i < 4; i++) if (valid[i]) m = fmaxf(m, s[i]);
    m = u_blkmax(m, red);

    float p[4], c[4];
    float run = 0.f;
#pragma unroll
    for (int i = 0; i < 4; i++) {
        p[i] = valid[i] ? expf(s[i] - m) : 0.f;
        run += p[i];
        c[i] = run;
    }

    float x = run;
#pragma unroll
    for (int o = 1; o < 32; o <<= 1) {
        const float y = __shfl_up_sync(~0u, x, o);
        if (lane >= o) x += y;
    }
    const float texcl = x - run;
    if (lane == 31) wsum[wid] = x;
    __syncthreads();
    if (wid == 0 && lane < 8) {
        float w = wsum[lane];
#pragma unroll
        for (int o = 1; o < 8; o <<= 1) {
            const float y = __shfl_up_sync(0xffu, w, o);
            if (lane >= o) w += y;
        }
        wsum[lane] = w;
        if (lane == 7) shtot = w;
    }
    __syncthreads();
    const float off  = texcl + (wid ? wsum[wid - 1] : 0.f);
    const float invT = 1.f / shtot;

    float l[4];
#pragma unroll
    for (int i = 0; i < 4; i++) {
        const float cum  = (c[i] + off) * invT;
        const float tail = fmaxf(1.f - cum, 0.f);
        const float pos  = (float)(q - (base + i));
        const float dist = sqrtf(tail * pos);
        float eff = expf(gamma * dist);
        eff = fminf(fmaxf(eff, 1e-5f), 1e5f);
        l[i] = s[i] * eff;
    }

    float m2 = -3.402823466e+38f;
#pragma unroll
    for (int i = 0; i < 4; i++) if (valid[i]) m2 = fmaxf(m2, l[i]);
    m2 = u_blkmax(m2, red);

    float e[4];
    float es = 0.f;
#pragma unroll
    for (int i = 0; i < 4; i++) {
        e[i] = valid[i] ? expf(l[i] - m2) : 0.f;
        es += e[i];
    }
    es = u_blksum(es, red);
    const float invE = 1.f / es;

    if (base < Lr) {
        __align__(8) unsigned short hh[4], ll[4], h2[4], l2[4];
#pragma unroll
        for (int i = 0; i < 4; i++) {
            const float pv = (q == 0) ? 0.f : e[i] * invE;
            const __half ph = __float2half_rn(pv);
            hh[i] = __half_as_ushort(ph);
            ll[i] = __half_as_ushort(__float2half_rn(pv - __half2float(ph)));
            const float p2 = pv * pv;
            const __half qh2 = __float2half_rn(p2);
            h2[i] = __half_as_ushort(qh2);
            l2[i] = __half_as_ushort(__float2half_rn(p2 - __half2float(qh2)));
        }
        const size_t pidx = ((size_t)bh * S + q) * S + base;
        *(uint2*)(g_sch + pidx) = *(uint2*)hh;
        *(uint2*)(g_scl + pidx) = *(uint2*)ll;
        *(uint2*)(g_s2h + pidx) = *(uint2*)h2;
        *(uint2*)(g_s2l + pidx) = *(uint2*)l2;
    }
}

// ---------------- WMMA AV (2-term): mean = (ph+pl)@Vm, cov = (p2h+p2l)@Vc --
constexpr int AP  = 24;
constexpr int BPp = 72;
constexpr int AV_SA_ELEMS = 128 * AP;
constexpr int AV_SB_ELEMS = 16 * BPp;
constexpr int AV_SMEM = (2 * 4 * AV_SA_ELEMS + 2 * 2 * AV_SB_ELEMS) * 2;  // 58368 B

__global__ void __launch_bounds__(256, 2) u_av_wmma()
{
    extern __shared__ __align__(16) __half dynsm[];
    __half* sA[2][4];
    __half* sB[2][2];
#pragma unroll
    for (int st = 0; st < 2; st++)
#pragma unroll
        for (int pl = 0; pl < 4; pl++)
            sA[st][pl] = dynsm + (st * 4 + pl) * AV_SA_ELEMS;
    __half* sbbase = dynsm + 8 * AV_SA_ELEMS;
#pragma unroll
    for (int st = 0; st < 2; st++)
#pragma unroll
        for (int mt = 0; mt < 2; mt++)
            sB[st][mt] = sbbase + (st * 2 + mt) * AV_SB_ELEMS;

    const int bh = blockIdx.y;
    const int qb = (7 - blockIdx.x) * 128;
    const int tid = threadIdx.x, wid = tid >> 5, lane = tid & 31;
    const int wg = wid >> 2, w4 = wid & 3;

    const size_t aoff = ((size_t)bh * S + qb) * S;
    const size_t vb   = (size_t)bh * S * DK;
    const __half* Ap[4] = {g_sch + aoff, g_scl + aoff, g_s2h + aoff, g_s2l + aoff};
    const __half* Vp[2] = {g_Vm + vb, g_Vc + vb};

    wmma::fragment<wmma::accumulator, 16, 16, 16, float> acc[2][4];
#pragma unroll
    for (int mi = 0; mi < 2; mi++)
#pragma unroll
        for (int nj = 0; nj < 4; nj++) wmma::fill_fragment(acc[mi][nj], 0.f);

    const int NITER = (qb + 128) / 16;

#define AV_PREFETCH(bufi, kb)                                                  \
    _Pragma("unroll")                                                          \
    for (int i = 0; i < 4; i++) {                                              \
        const int c = tid + i * 256;                                           \
        const int pl = c >> 8, idx = c & 255;                                  \
        const int rr = idx >> 1, col8 = (idx & 1) * 8;                         \
        CP16(sA[bufi][pl] + rr * AP + col8, Ap[pl] + (size_t)rr * S + (kb) + col8); \
    }                                                                          \
    {                                                                          \
        const int mtx = tid >> 7, idx = tid & 127;                             \
        const int rr = idx >> 3, col8 = (idx & 7) * 8;                         \
        CP16(sB[bufi][mtx] + rr * BPp + col8, Vp[mtx] + (size_t)((kb) + rr) * DK + col8); \
    }

    AV_PREFETCH(0, 0)
    CP_COMMIT();

    for (int kt = 0; kt < NITER; kt++) {
        CP_WAIT(0);
        __syncthreads();
        if (kt + 1 < NITER) {
            const int bn = (kt + 1) & 1;
            AV_PREFETCH(bn, (kt + 1) * 16)
            CP_COMMIT();
        }
        const int cur = kt & 1;
        const __half* aHp = sA[cur][wg * 2];
        const __half* aLp = sA[cur][wg * 2 + 1];
        const __half* bVp = sB[cur][wg];

        wmma::fragment<wmma::matrix_a, 16, 16, 16, __half, wmma::row_major> aH[2], aL[2];
#pragma unroll
        for (int mi = 0; mi < 2; mi++) {
            const int row = w4 * 32 + mi * 16;
            wmma::load_matrix_sync(aH[mi], aHp + row * AP, AP);
            wmma::load_matrix_sync(aL[mi], aLp + row * AP, AP);
        }
#pragma unroll
        for (int nj = 0; nj < 4; nj++) {
            wmma::fragment<wmma::matrix_b, 16, 16, 16, __half, wmma::row_major> bV;
            wmma::load_matrix_sync(bV, bVp + nj * 16, BPp);
#pragma unroll
            for (int mi = 0; mi < 2; mi++) {
                wmma::mma_sync(acc[mi][nj], aH[mi], bV, acc[mi][nj]);
                wmma::mma_sync(acc[mi][nj], aL[mi], bV, acc[mi][nj]);
            }
        }
    }
    __syncthreads();

    const int b = bh >> 3, h = bh & 7;
    __half* dh = wg ? g_cch : g_cmh;
    __half* dl = wg ? g_ccl : g_cml;
    float* epi = (float*)dynsm + wid * 256;
#pragma unroll
    for (int mi = 0; mi < 2; mi++) {
#pragma unroll
        for (int nj = 0; nj < 4; nj++) {
            wmma::store_matrix_sync(epi, acc[mi][nj], 16, wmma::mem_row_major);
            __syncwarp();
            const int r  = lane >> 1;
            const int c0 = (lane & 1) * 8;
            const int s  = qb + w4 * 32 + mi * 16 + r;
            const int d  = nj * 16 + c0;
            float v[8];
#pragma unroll
            for (int c = 0; c < 8; c++) v[c] = epi[r * 16 + c0 + c];
            uint4 uh, ul;
            pack8h(v, uh, ul);
            const size_t o = ((size_t)(b * S + s)) * D + h * DK + d;
            *(uint4*)(dh + o) = uh;
            *(uint4*)(dl + o) = ul;
            __syncwarp();
        }
    }
#undef AV_PREFETCH
}

// ---------------- host launcher --------------------------------------------
extern "C" void kernel_launch(void* const* d_in, const int* in_sizes, int n_in,
                              void* d_out, int out_size)
{
    const float* q_mean = (const float*)d_in[0];
    const float* q_cov  = (const float*)d_in[1];
    const float* k_mean = (const float*)d_in[2];
    const float* k_cov  = (const float*)d_in[3];
    const float* v_mean = (const float*)d_in[4];
    const float* v_cov  = (const float*)d_in[5];
    const float* Wqm = (const float*)d_in[6];  const float* bqm = (const float*)d_in[7];
    const float* Wqc = (const float*)d_in[8];  const float* bqc = (const float*)d_in[9];
    const float* Wkm = (const float*)d_in[10]; const float* bkm = (const float*)d_in[11];
    const float* Wkc = (const float*)d_in[12]; const float* bkc = (const float*)d_in[13];
    const float* Wvm = (const float*)d_in[14]; const float* bvm = (const float*)d_in[15];
    const float* Wvc = (const float*)d_in[16]; const float* bvc = (const float*)d_in[17];
    const float* Wom = (const float*)d_in[18]; const float* bom = (const float*)d_in[19];
    const float* Woc = (const float*)d_in[20]; const float* boc = (const float*)d_in[21];
    const float* gammas = (const float*)d_in[22];

    float* out = (float*)d_out;

    static bool attr_set = false;
    if (!attr_set) {
        cudaFuncSetAttribute(u_av_wmma, cudaFuncAttributeMaxDynamicSharedMemorySize, AV_SMEM);
        attr_set = true;
    }

    Ptr6f xs;   xs.p[0] = q_mean; xs.p[1] = q_cov; xs.p[2] = k_mean;
                xs.p[3] = k_cov;  xs.p[4] = v_mean; xs.p[5] = v_cov;
    Ptr8f ws;   ws.p[0] = Wqm; ws.p[1] = Wqc; ws.p[2] = Wkm; ws.p[3] = Wkc;
                ws.p[4] = Wvm; ws.p[5] = Wvc; ws.p[6] = Wom; ws.p[7] = Woc;
    Ptr6f bs;   bs.p[0] = bqm; bs.p[1] = bqc; bs.p[2] = bkm;
                bs.p[3] = bkc; bs.p[4] = bvm; bs.p[5] = bvc;

    u_split6  <<<dim3(MR * D / 1024, 1, 6), 256>>>(xs);
    u_splitWt8<<<dim3(D / 32, D / 32, 8), 256>>>(ws);
    u_gemm_proj<<<dim3(D / 128, MR / 128, 6), 256>>>(bs);
    u_rownorm <<<dim3(BHS / 8, 2), 256>>>();
    u_scores_wmma<<<dim3(36, BH), 256>>>();
    u_decay   <<<dim3(S, BH), 256>>>(gammas);
    u_av_wmma <<<dim3(S / 128, BH), 256, AV_SMEM>>>();
    u_gemm_out<<<dim3(D / 128, MR / 128, 2), 256>>>(bom, boc, out);
}

// round 13
// speedup vs baseline: 2.5875x; 1.0818x over previous
#include <cuda_runtime.h>
#include <cuda_fp16.h>
#include <mma.h>
#include <math.h>
#include <stdint.h>

using namespace nvcuda;

constexpr int B  = 8;
constexpr int S  = 1024;
constexpr int H  = 8;
constexpr int DK = 64;
constexpr int D  = 512;
constexpr int BH  = B * H;     // 64
constexpr int BHS = BH * S;    // 65536
constexpr int MR  = B * S;     // 8192

// ---------------- device scratch ----------------
__device__ float g_att[(size_t)BH * S * S];                 // raw scores
__device__ __half g_sch[(size_t)BH * S * S];                // prob (single plane)
__device__ __half g_s2h[(size_t)BH * S * S];                // prob^2 (single plane)
__device__ __half g_Qh[(size_t)BHS * 128];
__device__ __half g_Ql[(size_t)BHS * 128];
__device__ __half g_Kh[(size_t)BHS * 128];
__device__ __half g_Kl[(size_t)BHS * 128];
__device__ __half g_Vm[(size_t)BHS * DK];                   // single-plane V
__device__ __half g_Vc[(size_t)BHS * DK];
__device__ __half g_A6h[(size_t)6 * MR * D];
__device__ __half g_A6l[(size_t)6 * MR * D];
__device__ __half g_W8h[8 * D * D];
__device__ __half g_W8l[8 * D * D];
__device__ __half g_cmh[(size_t)MR * D];
__device__ __half g_cml[(size_t)MR * D];
__device__ __half g_cch[(size_t)MR * D];
__device__ __half g_ccl[(size_t)MR * D];
// raw fp32 covariance projections (pre-sqrt) for exact tq/tk
__device__ float g_rawQc[(size_t)BHS * DK];
__device__ float g_rawKc[(size_t)BHS * DK];
__device__ float g_tq[BHS];
__device__ float g_tk[BHS];

// ---------------- cp.async helpers ----------------
#define CP16(dst, src) asm volatile( \
    "cp.async.cg.shared.global [%0], [%1], 16;" \
    :: "r"((uint32_t)__cvta_generic_to_shared(dst)), "l"(src))
#define CP_COMMIT() asm volatile("cp.async.commit_group;")
#define CP_WAIT(n)  asm volatile("cp.async.wait_group %0;" :: "n"(n))

struct Ptr6f { const float* p[6]; };
struct Ptr8f { const float* p[8]; };

// ---------------- pack 8 fp32 -> fp16 hi/lo uint4 pair --------------------
__device__ __forceinline__ void pack8h(const float* v, uint4& uh, uint4& ul)
{
    __align__(16) unsigned short hh[8];
    __align__(16) unsigned short ll[8];
#pragma unroll
    for (int c = 0; c < 8; c++) {
        const __half x = __float2half_rn(v[c]);
        hh[c] = __half_as_ushort(x);
        ll[c] = __half_as_ushort(__float2half_rn(v[c] - __half2float(x)));
    }
    uh = *(uint4*)hh;
    ul = *(uint4*)ll;
}

// ---------------- batched fp32 -> fp16 hi/lo split (inputs) ----------------
__global__ void u_split6(Ptr6f xs)
{
    const size_t zo = (size_t)blockIdx.z * MR * D;
    const int i = (blockIdx.x * 256 + threadIdx.x) * 4;
    const float4 fv = *(const float4*)(xs.p[blockIdx.z] + i);
    const float v[4] = {fv.x, fv.y, fv.z, fv.w};
    __align__(8) unsigned short hh[4], ll[4];
#pragma unroll
    for (int c = 0; c < 4; c++) {
        const __half x = __float2half_rn(v[c]);
        hh[c] = __half_as_ushort(x);
        ll[c] = __half_as_ushort(__float2half_rn(v[c] - __half2float(x)));
    }
    *(uint2*)(g_A6h + zo + i) = *(uint2*)hh;
    *(uint2*)(g_A6l + zo + i) = *(uint2*)ll;
}

// ---------------- batched W[K,N] -> W^T[N,K] fp16 hi/lo --------------------
__global__ void u_splitWt8(Ptr8f ws)
{
    __shared__ float tile[32][33];
    const size_t zo = (size_t)blockIdx.z * D * D;
    const float* W = ws.p[blockIdx.z];
    const int k0 = blockIdx.y * 32, n0 = blockIdx.x * 32;
    const int tx = threadIdx.x & 31, tw = threadIdx.x >> 5;
    for (int r = tw; r < 32; r += 8)
        tile[r][tx] = W[(size_t)(k0 + r) * D + n0 + tx];
    __syncthreads();
    for (int r = tw; r < 32; r += 8) {
        const float v = tile[tx][r];
        const __half hv = __float2half_rn(v);
        const size_t o = zo + (size_t)(n0 + r) * D + k0 + tx;
        g_W8h[o] = hv;
        g_W8l[o] = __float2half_rn(v - __half2float(hv));
    }
}

// ===================  double-buffered WMMA GEMM core  ======================
// MODE 0: aH*bH + aH*bL + aL*bH (3-term)
// MODE 1: aH*bH + aL*bH        (2-term, drop B-lo)
// MODE 2: aH*bH + aH*bL        (2-term, drop A-lo)
constexpr int GP = 24;   // smem pitch (16 + 8 pad)

#define GEMM_PREFETCH(dstbuf, koff)                                            \
    _Pragma("unroll")                                                          \
    for (int i = 0; i < 4; i++) {                                              \
        const int c = tid + i * 256;                                           \
        const int mtx = c >> 8, rr = (c & 255) >> 1, col8 = (c & 1) * 8;       \
        CP16(&buf[dstbuf][mtx][rr * GP + col8],                                \
             srcs[mtx] + (size_t)(baserow[mtx] + rr) * ldv + (koff) + col8);   \
    }

#define GEMM_MAINLOOP(Ah, Al, Bh, Bl, LD, NITER, MODE)                         \
    const __half* srcs[4] = {Ah, Al, Bh, Bl};                                  \
    const int baserow[4] = {m0, m0, n0, n0};                                   \
    const int ldv = (LD);                                                      \
    const int mode = (MODE);                                                   \
    wmma::fragment<wmma::accumulator, 16, 16, 16, float> acc[4][2];            \
    _Pragma("unroll")                                                          \
    for (int mi = 0; mi < 4; mi++)                                             \
        _Pragma("unroll")                                                      \
        for (int nj = 0; nj < 2; nj++) wmma::fill_fragment(acc[mi][nj], 0.f);  \
    GEMM_PREFETCH(0, 0)                                                        \
    CP_COMMIT();                                                               \
    for (int kt = 0; kt < (NITER); kt++) {                                     \
        CP_WAIT(0);                                                            \
        __syncthreads();                                                       \
        if (kt + 1 < (NITER)) {                                                \
            const int bn = (kt + 1) & 1;                                       \
            GEMM_PREFETCH(bn, (kt + 1) * 16)                                   \
            CP_COMMIT();                                                       \
        }                                                                      \
        const __half* sAh = buf[kt & 1][0];                                    \
        const __half* sAl = buf[kt & 1][1];                                    \
        const __half* sBh = buf[kt & 1][2];                                    \
        const __half* sBl = buf[kt & 1][3];                                    \
        wmma::fragment<wmma::matrix_a, 16, 16, 16, __half, wmma::row_major> aH[4], aL[4]; \
        _Pragma("unroll")                                                      \
        for (int mi = 0; mi < 4; mi++) {                                       \
            const int row = warp_m * 64 + mi * 16;                             \
            wmma::load_matrix_sync(aH[mi], sAh + row * GP, GP);                \
            if (mode != 2) wmma::load_matrix_sync(aL[mi], sAl + row * GP, GP); \
        }                                                                      \
        _Pragma("unroll")                                                      \
        for (int nj = 0; nj < 2; nj++) {                                       \
            const int col = warp_n * 32 + nj * 16;                             \
            wmma::fragment<wmma::matrix_b, 16, 16, 16, __half, wmma::col_major> bH, bL; \
            wmma::load_matrix_sync(bH, sBh + col * GP, GP);                    \
            if (mode != 1) wmma::load_matrix_sync(bL, sBl + col * GP, GP);     \
            _Pragma("unroll")                                                  \
            for (int mi = 0; mi < 4; mi++) {                                   \
                wmma::mma_sync(acc[mi][nj], aH[mi], bH, acc[mi][nj]);          \
                if (mode != 1) wmma::mma_sync(acc[mi][nj], aH[mi], bL, acc[mi][nj]); \
                if (mode != 2) wmma::mma_sync(acc[mi][nj], aL[mi], bH, acc[mi][nj]); \
            }                                                                  \
        }                                                                      \
    }                                                                          \
    __syncthreads();

// ---------------- projection GEMM (z = 0..5), fused epilogue ---------------
// z: 0 qm, 1 qc(sqrt), 2 km, 3 kc(sqrt) (3-term); 4 vm, 5 vc (2-term)
__global__ void __launch_bounds__(256, 2) u_gemm_proj(Ptr6f biases)
{
    __shared__ __align__(16) __half buf[2][4][128 * GP];  // 48 KB
    const int z = blockIdx.z;
    const __half* Ah = g_A6h + (size_t)z * MR * D;
    const __half* Al = g_A6l + (size_t)z * MR * D;
    const __half* Bh = g_W8h + (size_t)z * D * D;
    const __half* Bl = g_W8l + (size_t)z * D * D;
    const float* bias = biases.p[z];
    const int tid = threadIdx.x, wid = tid >> 5, lane = tid & 31;
    const int m0 = blockIdx.y * 128, n0 = blockIdx.x * 128;
    const int warp_m = wid >> 2, warp_n = wid & 3;

    GEMM_MAINLOOP(Ah, Al, Bh, Bl, D, 32, (z < 4) ? 0 : 1)

    float* epi = (float*)buf + wid * 256;
#pragma unroll
    for (int mi = 0; mi < 4; mi++) {
#pragma unroll
        for (int nj = 0; nj < 2; nj++) {
            wmma::store_matrix_sync(epi, acc[mi][nj], 16, wmma::mem_row_major);
            __syncwarp();
            const int r  = lane >> 1;
            const int c0 = (lane & 1) * 8;
            const int m  = m0 + warp_m * 64 + mi * 16 + r;
            const int n  = n0 + warp_n * 32 + nj * 16 + c0;
            float v[8];
#pragma unroll
            for (int c = 0; c < 8; c++) v[c] = epi[r * 16 + c0 + c] + bias[n + c];
            const int b = m >> 10, s = m & (S - 1);
            const int h = n >> 6, d = n & 63;
            if (z < 4) {
                if (z & 1) {
                    float* raw = (z == 1) ? g_rawQc : g_rawKc;
                    const size_t ro = (((size_t)(b * H + h)) * S + s) * 64 + d;
                    *(float4*)(raw + ro)     = make_float4(v[0], v[1], v[2], v[3]);
                    *(float4*)(raw + ro + 4) = make_float4(v[4], v[5], v[6], v[7]);
#pragma unroll
                    for (int c = 0; c < 8; c++) v[c] = sqrtf(fmaxf(v[c], 1e-24f));
                }
                __half* dh = (z < 2) ? g_Qh : g_Kh;
                __half* dl = (z < 2) ? g_Ql : g_Kl;
                const size_t o = (((size_t)(b * H + h)) * S + s) * 128 + (z & 1) * 64 + d;
                uint4 uh, ul;
                pack8h(v, uh, ul);
                *(uint4*)(dh + o) = uh;
                *(uint4*)(dl + o) = ul;
            } else {
                __half* dv = (z == 4) ? g_Vm : g_Vc;
                __align__(16) unsigned short t[8];
#pragma unroll
                for (int c = 0; c < 8; c++) t[c] = __half_as_ushort(__float2half_rn(v[c]));
                const size_t o = (((size_t)(b * H + h)) * S + s) * 64 + d;
                *(uint4*)(dv + o) = *(uint4*)t;
            }
            __syncwarp();
        }
    }
}

// ---------------- output GEMM (z = 0 mean, 1 cov), 2-term ------------------
__global__ void __launch_bounds__(256, 2) u_gemm_out(const float* bias0, const float* bias1,
                                                     float* out)
{
    __shared__ __align__(16) __half buf[2][4][128 * GP];
    const int z = blockIdx.z;
    const __half* Ah = z ? g_cch : g_cmh;
    const __half* Al = z ? g_ccl : g_cml;
    const __half* Bh = g_W8h + (size_t)(6 + z) * D * D;
    const __half* Bl = g_W8l + (size_t)(6 + z) * D * D;
    const float* bias = z ? bias1 : bias0;
    const int tid = threadIdx.x, wid = tid >> 5, lane = tid & 31;
    const int m0 = blockIdx.y * 128, n0 = blockIdx.x * 128;
    const int warp_m = wid >> 2, warp_n = wid & 3;

    GEMM_MAINLOOP(Ah, Al, Bh, Bl, D, 32, 1)

    float* epi = (float*)buf + wid * 256;
    float* dstm = out + (size_t)z * MR * D;
#pragma unroll
    for (int mi = 0; mi < 4; mi++) {
#pragma unroll
        for (int nj = 0; nj < 2; nj++) {
            wmma::store_matrix_sync(epi, acc[mi][nj], 16, wmma::mem_row_major);
            __syncwarp();
            const int r  = lane >> 1;
            const int c0 = (lane & 1) * 8;
            const int m  = m0 + warp_m * 64 + mi * 16 + r;
            const int n  = n0 + warp_n * 32 + nj * 16 + c0;
            float v[8];
#pragma unroll
            for (int c = 0; c < 8; c++) v[c] = epi[r * 16 + c0 + c] + bias[n + c];
            float* dst = dstm + (size_t)m * D + n;
            *(float4*)(dst)     = make_float4(v[0], v[1], v[2], v[3]);
            *(float4*)(dst + 4) = make_float4(v[4], v[5], v[6], v[7]);
            __syncwarp();
        }
    }
}

// ---------------- exact row stats: tq = sum(qm^2) + sum(raw qc) ------------
__global__ void u_rownorm()
{
    const int row  = blockIdx.x * 8 + (threadIdx.x >> 5);
    const int lane = threadIdx.x & 31;
    const __half* ph = (blockIdx.y ? g_Kh : g_Qh) + (size_t)row * 128;
    const __half* pl = (blockIdx.y ? g_Kl : g_Ql) + (size_t)row * 128;
    const float* pc = (blockIdx.y ? g_rawKc : g_rawQc) + (size_t)row * DK;
    const float a0 = __half2float(ph[lane])      + __half2float(pl[lane]);
    const float a1 = __half2float(ph[lane + 32]) + __half2float(pl[lane + 32]);
    const float c0 = pc[lane], c1 = pc[lane + 32];
    float v = a0 * a0 + a1 * a1 + c0 + c1;
#pragma unroll
    for (int o = 16; o; o >>= 1) v += __shfl_xor_sync(~0u, v, o);
    if (lane == 0) (blockIdx.y ? g_tk : g_tq)[row] = v;
}

// ---------------- WMMA scores: 128x128 causal tiles, 2-term (drop Q-lo) ----
__global__ void __launch_bounds__(256, 2) u_scores_wmma()
{
    __shared__ __align__(16) __half buf[2][4][128 * GP];  // 48 KB
    const int bh = blockIdx.y;
    int tq = (int)((sqrtf(8.f * blockIdx.x + 1.f) - 1.f) * 0.5f);
    while ((tq + 1) * (tq + 2) / 2 <= (int)blockIdx.x) tq++;
    while (tq * (tq + 1) / 2 > (int)blockIdx.x) tq--;
    const int tk = blockIdx.x - tq * (tq + 1) / 2;
    const int qb = tq * 128, kb = tk * 128;

    const int tid = threadIdx.x, wid = tid >> 5, lane = tid & 31;
    const int warp_m = wid >> 2, warp_n = wid & 3;
    const int m0 = 0, n0 = 0;
    const __half* Qh = g_Qh + ((size_t)bh * S + qb) * 128;
    const __half* Ql = g_Ql + ((size_t)bh * S + qb) * 128;
    const __half* Kh = g_Kh + ((size_t)bh * S + kb) * 128;
    const __half* Kl = g_Kl + ((size_t)bh * S + kb) * 128;

    GEMM_MAINLOOP(Qh, Ql, Kh, Kl, 128, 8, 2)

    float* att = g_att + (size_t)bh * S * S;
    const float* tqv = g_tq + bh * S;
    const float* tkv = g_tk + bh * S;

    float* epi = (float*)buf + wid * 256;
#pragma unroll
    for (int mi = 0; mi < 4; mi++) {
#pragma unroll
        for (int nj = 0; nj < 2; nj++) {
            wmma::store_matrix_sync(epi, acc[mi][nj], 16, wmma::mem_row_major);
            __syncwarp();
            const int r  = lane >> 1;
            const int c0 = (lane & 1) * 8;
            const int q  = qb + warp_m * 64 + mi * 16 + r;
            const int k  = kb + warp_n * 32 + nj * 16 + c0;
            const float tq2 = tqv[q];
            float v[8];
#pragma unroll
            for (int c = 0; c < 8; c++)
                v[c] = 0.25f * epi[r * 16 + c0 + c] - 0.125f * (tq2 + tkv[k + c]);
            float* dst = att + (size_t)q * S + k;
            *(float4*)(dst)     = make_float4(v[0], v[1], v[2], v[3]);
            *(float4*)(dst + 4) = make_float4(v[4], v[5], v[6], v[7]);
            __syncwarp();
        }
    }
}

// ---------------- block reduction helpers ----------------------------------
__device__ __forceinline__ float u_blkmax(float v, float* red)
{
    const int lane = threadIdx.x & 31, wid = threadIdx.x >> 5;
#pragma unroll
    for (int o = 16; o; o >>= 1) v = fmaxf(v, __shfl_xor_sync(~0u, v, o));
    __syncthreads();
    if (lane == 0) red[wid] = v;
    __syncthreads();
    float r = red[0];
#pragma unroll
    for (int i = 1; i < 8; i++) r = fmaxf(r, red[i]);
    return r;
}
__device__ __forceinline__ float u_blksum(float v, float* red)
{
    const int lane = threadIdx.x & 31, wid = threadIdx.x >> 5;
#pragma unroll
    for (int o = 16; o; o >>= 1) v += __shfl_xor_sync(~0u, v, o);
    __syncthreads();
    if (lane == 0) red[wid] = v;
    __syncthreads();
    float r = red[0];
#pragma unroll
    for (int i = 1; i < 8; i++) r += red[i];
    return r;
}

// ---------------- fused softmax -> cumsum -> decay -> softmax --------------
// Writes prob and prob^2 as SINGLE fp16 planes.
__global__ void __launch_bounds__(256) u_decay(const float* __restrict__ gammas)
{
    const int q  = blockIdx.x;
    const int bh = blockIdx.y;
    const int L  = q + 1;
    const int Lr = (L + 127) & ~127;
    const int tid  = threadIdx.x;
    const int lane = tid & 31, wid = tid >> 5;
    const float* row = g_att + ((size_t)bh * S + q) * S;

    const float g = gammas[bh & (H - 1)];
    const float gamma = -log1pf(expf(g));

    __shared__ float red[8];
    __shared__ float wsum[8];
    __shared__ float shtot;

    const int base = tid * 4;
    float s[4] = {0.f, 0.f, 0.f, 0.f};
    if (base < L) {
        const float4 sv = *(const float4*)(row + base);
        s[0] = sv.x; s[1] = sv.y; s[2] = sv.z; s[3] = sv.w;
    }
    bool valid[4];
#pragma unroll
    for (int i = 0; i < 4; i++) valid[i] = (base + i) < L;

    float m = -3.402823466e+38f;
#pragma unroll
    for (int i = 0; i < 4; i++) if (valid[i]) m = fmaxf(m, s[i]);
    m = u_blkmax(m, red);

    float p[4], c[4];
    float run = 0.f;
#pragma unroll
    for (int i = 0; i < 4; i++) {
        p[i] = valid[i] ? expf(s[i] - m) : 0.f;
        run += p[i];
        c[i] = run;
    }

    float x = run;
#pragma unroll
    for (int o = 1; o < 32; o <<= 1) {
        const float y = __shfl_up_sync(~0u, x, o);
        if (lane >= o) x += y;
    }
    const float texcl = x - run;
    if (lane == 31) wsum[wid] = x;
    __syncthreads();
    if (wid == 0 && lane < 8) {
        float w = wsum[lane];
#pragma unroll
        for (int o = 1; o < 8; o <<= 1) {
            const float y = __shfl_up_sync(0xffu, w, o);
            if (lane >= o) w += y;
        }
        wsum[lane] = w;
        if (lane == 7) shtot = w;
    }
    __syncthreads();
    const float off  = texcl + (wid ? wsum[wid - 1] : 0.f);
    const float invT = 1.f / shtot;

    float l[4];
#pragma unroll
    for (int i = 0; i < 4; i++) {
        const float cum  = (c[i] + off) * invT;
        const float tail = fmaxf(1.f - cum, 0.f);
        const float pos  = (float)(q - (base + i));
        const float dist = sqrtf(tail * pos);
        float eff = expf(gamma * dist);
        eff = fminf(fmaxf(eff, 1e-5f), 1e5f);
        l[i] = s[i] * eff;
    }

    float m2 = -3.402823466e+38f;
#pragma unroll
    for (int i = 0; i < 4; i++) if (valid[i]) m2 = fmaxf(m2, l[i]);
    m2 = u_blkmax(m2, red);

    float e[4];
    float es = 0.f;
#pragma unroll
    for (int i = 0; i < 4; i++) {
        e[i] = valid[i] ? expf(l[i] - m2) : 0.f;
        es += e[i];
    }
    es = u_blksum(es, red);
    const float invE = 1.f / es;

    if (base < Lr) {
        __align__(8) unsigned short hh[4], h2[4];
#pragma unroll
        for (int i = 0; i < 4; i++) {
            const float pv = (q == 0) ? 0.f : e[i] * invE;
            hh[i] = __half_as_ushort(__float2half_rn(pv));
            h2[i] = __half_as_ushort(__float2half_rn(pv * pv));
        }
        const size_t pidx = ((size_t)bh * S + q) * S + base;
        *(uint2*)(g_sch + pidx) = *(uint2*)hh;
        *(uint2*)(g_s2h + pidx) = *(uint2*)h2;
    }
}

// ---------------- WMMA AV (1-term): mean = p@Vm, cov = p2@Vc ---------------
// warps 0-3 mean, warps 4-7 cov. Double-buffered cp.async, one sync per step.
constexpr int AP  = 24;
constexpr int BPp = 72;

__global__ void __launch_bounds__(256, 2) u_av_wmma()
{
    __shared__ __align__(16) __half sA[2][2][128 * AP];   // 2 stages x {p, p2}: 24576 B
    __shared__ __align__(16) __half sB[2][2][16 * BPp];   // 2 stages x {Vm, Vc}: 9216 B

    const int bh = blockIdx.y;
    const int qb = (7 - blockIdx.x) * 128;
    const int tid = threadIdx.x, wid = tid >> 5, lane = tid & 31;
    const int wg = wid >> 2, w4 = wid & 3;

    const size_t aoff = ((size_t)bh * S + qb) * S;
    const size_t vb   = (size_t)bh * S * DK;
    const __half* Ap[2] = {g_sch + aoff, g_s2h + aoff};
    const __half* Vp[2] = {g_Vm + vb, g_Vc + vb};

    wmma::fragment<wmma::accumulator, 16, 16, 16, float> acc[2][4];
#pragma unroll
    for (int mi = 0; mi < 2; mi++)
#pragma unroll
        for (int nj = 0; nj < 4; nj++) wmma::fill_fragment(acc[mi][nj], 0.f);

    const int NITER = (qb + 128) / 16;

#define AV_PREFETCH(bufi, kb)                                                  \
    _Pragma("unroll")                                                          \
    for (int i = 0; i < 2; i++) {                                              \
        const int c = tid + i * 256;                                           \
        const int pl = c >> 8, idx = c & 255;                                  \
        const int rr = idx >> 1, col8 = (idx & 1) * 8;                         \
        CP16(&sA[bufi][pl][rr * AP + col8], Ap[pl] + (size_t)rr * S + (kb) + col8); \
    }                                                                          \
    {                                                                          \
        const int mtx = tid >> 7, idx = tid & 127;                             \
        const int rr = idx >> 3, col8 = (idx & 7) * 8;                         \
        CP16(&sB[bufi][mtx][rr * BPp + col8], Vp[mtx] + (size_t)((kb) + rr) * DK + col8); \
    }

    AV_PREFETCH(0, 0)
    CP_COMMIT();

    for (int kt = 0; kt < NITER; kt++) {
        CP_WAIT(0);
        __syncthreads();
        if (kt + 1 < NITER) {
            const int bn = (kt + 1) & 1;
            AV_PREFETCH(bn, (kt + 1) * 16)
            CP_COMMIT();
        }
        const int cur = kt & 1;
        const __half* aPp = sA[cur][wg];
        const __half* bVp = sB[cur][wg];

        wmma::fragment<wmma::matrix_a, 16, 16, 16, __half, wmma::row_major> aP[2];
#pragma unroll
        for (int mi = 0; mi < 2; mi++) {
            const int row = w4 * 32 + mi * 16;
            wmma::load_matrix_sync(aP[mi], aPp + row * AP, AP);
        }
#pragma unroll
        for (int nj = 0; nj < 4; nj++) {
            wmma::fragment<wmma::matrix_b, 16, 16, 16, __half, wmma::row_major> bV;
            wmma::load_matrix_sync(bV, bVp + nj * 16, BPp);
#pragma unroll
            for (int mi = 0; mi < 2; mi++)
                wmma::mma_sync(acc[mi][nj], aP[mi], bV, acc[mi][nj]);
        }
    }
    __syncthreads();

    const int b = bh >> 3, h = bh & 7;
    __half* dh = wg ? g_cch : g_cmh;
    __half* dl = wg ? g_ccl : g_cml;
    float* epi = (float*)sA + wid * 256;
#pragma unroll
    for (int mi = 0; mi < 2; mi++) {
#pragma unroll
        for (int nj = 0; nj < 4; nj++) {
            wmma::store_matrix_sync(epi, acc[mi][nj], 16, wmma::mem_row_major);
            __syncwarp();
            const int r  = lane >> 1;
            const int c0 = (lane & 1) * 8;
            const int s  = qb + w4 * 32 + mi * 16 + r;
            const int d  = nj * 16 + c0;
            float v[8];
#pragma unroll
            for (int c = 0; c < 8; c++) v[c] = epi[r * 16 + c0 + c];
            uint4 uh, ul;
            pack8h(v, uh, ul);
            const size_t o = ((size_t)(b * S + s)) * D + h * DK + d;
            *(uint4*)(dh + o) = uh;
            *(uint4*)(dl + o) = ul;
            __syncwarp();
        }
    }
#undef AV_PREFETCH
}

// ---------------- host launcher --------------------------------------------
extern "C" void kernel_launch(void* const* d_in, const int* in_sizes, int n_in,
                              void* d_out, int out_size)
{
    const float* q_mean = (const float*)d_in[0];
    const float* q_cov  = (const float*)d_in[1];
    const float* k_mean = (const float*)d_in[2];
    const float* k_cov  = (const float*)d_in[3];
    const float* v_mean = (const float*)d_in[4];
    const float* v_cov  = (const float*)d_in[5];
    const float* Wqm = (const float*)d_in[6];  const float* bqm = (const float*)d_in[7];
    const float* Wqc = (const float*)d_in[8];  const float* bqc = (const float*)d_in[9];
    const float* Wkm = (const float*)d_in[10]; const float* bkm = (const float*)d_in[11];
    const float* Wkc = (const float*)d_in[12]; const float* bkc = (const float*)d_in[13];
    const float* Wvm = (const float*)d_in[14]; const float* bvm = (const float*)d_in[15];
    const float* Wvc = (const float*)d_in[16]; const float* bvc = (const float*)d_in[17];
    const float* Wom = (const float*)d_in[18]; const float* bom = (const float*)d_in[19];
    const float* Woc = (const float*)d_in[20]; const float* boc = (const float*)d_in[21];
    const float* gammas = (const float*)d_in[22];

    float* out = (float*)d_out;

    Ptr6f xs;   xs.p[0] = q_mean; xs.p[1] = q_cov; xs.p[2] = k_mean;
                xs.p[3] = k_cov;  xs.p[4] = v_mean; xs.p[5] = v_cov;
    Ptr8f ws;   ws.p[0] = Wqm; ws.p[1] = Wqc; ws.p[2] = Wkm; ws.p[3] = Wkc;
                ws.p[4] = Wvm; ws.p[5] = Wvc; ws.p[6] = Wom; ws.p[7] = Woc;
    Ptr6f bs;   bs.p[0] = bqm; bs.p[1] = bqc; bs.p[2] = bkm;
                bs.p[3] = bkc; bs.p[4] = bvm; bs.p[5] = bvc;

    u_split6  <<<dim3(MR * D / 1024, 1, 6), 256>>>(xs);
    u_splitWt8<<<dim3(D / 32, D / 32, 8), 256>>>(ws);
    u_gemm_proj<<<dim3(D / 128, MR / 128, 6), 256>>>(bs);
    u_rownorm <<<dim3(BHS / 8, 2), 256>>>();
    u_scores_wmma<<<dim3(36, BH), 256>>>();
    u_decay   <<<dim3(S, BH), 256>>>(gammas);
    u_av_wmma <<<dim3(S / 128, BH), 256>>>();
    u_gemm_out<<<dim3(D / 128, MR / 128, 2), 256>>>(bom, boc, out);
}

// round 14
// speedup vs baseline: 2.8975x; 1.1198x over previous
#include <cuda_runtime.h>
#include <cuda_fp16.h>
#include <mma.h>
#include <math.h>
#include <stdint.h>

using namespace nvcuda;

constexpr int B  = 8;
constexpr int S  = 1024;
constexpr int H  = 8;
constexpr int DK = 64;
constexpr int D  = 512;
constexpr int BH  = B * H;     // 64
constexpr int BHS = BH * S;    // 65536
constexpr int MR  = B * S;     // 8192

// ---------------- device scratch ----------------
__device__ float g_att[(size_t)BH * S * S];                 // raw scores
__device__ __half g_sch[(size_t)BH * S * S];                // prob (single plane)
__device__ __half g_s2h[(size_t)BH * S * S];                // prob^2 (single plane)
__device__ __half g_Qh[(size_t)BHS * 128];
__device__ __half g_Ql[(size_t)BHS * 128];
__device__ __half g_Kh[(size_t)BHS * 128];
__device__ __half g_Kl[(size_t)BHS * 128];
__device__ __half g_Vm[(size_t)BHS * DK];                   // single-plane V
__device__ __half g_Vc[(size_t)BHS * DK];
__device__ __half g_A6h[(size_t)6 * MR * D];
__device__ __half g_A6l[(size_t)6 * MR * D];
__device__ __half g_W8h[8 * D * D];
__device__ __half g_W8l[8 * D * D];
__device__ __half g_cmh[(size_t)MR * D];
__device__ __half g_cml[(size_t)MR * D];
__device__ __half g_cch[(size_t)MR * D];
__device__ __half g_ccl[(size_t)MR * D];
// raw fp32 covariance projections (pre-sqrt) for exact tq/tk
__device__ float g_rawQc[(size_t)BHS * DK];
__device__ float g_rawKc[(size_t)BHS * DK];
__device__ float g_tq[BHS];
__device__ float g_tk[BHS];

// ---------------- cp.async helpers ----------------
#define CP16(dst, src) asm volatile( \
    "cp.async.cg.shared.global [%0], [%1], 16;" \
    :: "r"((uint32_t)__cvta_generic_to_shared(dst)), "l"(src))
#define CP_COMMIT() asm volatile("cp.async.commit_group;")
#define CP_WAIT(n)  asm volatile("cp.async.wait_group %0;" :: "n"(n))

struct Ptr6f { const float* p[6]; };
struct Ptr8f { const float* p[8]; };

// ---------------- pack 8 fp32 -> fp16 hi/lo uint4 pair --------------------
__device__ __forceinline__ void pack8h(const float* v, uint4& uh, uint4& ul)
{
    __align__(16) unsigned short hh[8];
    __align__(16) unsigned short ll[8];
#pragma unroll
    for (int c = 0; c < 8; c++) {
        const __half x = __float2half_rn(v[c]);
        hh[c] = __half_as_ushort(x);
        ll[c] = __half_as_ushort(__float2half_rn(v[c] - __half2float(x)));
    }
    uh = *(uint4*)hh;
    ul = *(uint4*)ll;
}

// ---------------- batched fp32 -> fp16 hi/lo split (inputs) ----------------
__global__ void u_split6(Ptr6f xs)
{
    const size_t zo = (size_t)blockIdx.z * MR * D;
    const int i = (blockIdx.x * 256 + threadIdx.x) * 4;
    const float4 fv = *(const float4*)(xs.p[blockIdx.z] + i);
    const float v[4] = {fv.x, fv.y, fv.z, fv.w};
    __align__(8) unsigned short hh[4], ll[4];
#pragma unroll
    for (int c = 0; c < 4; c++) {
        const __half x = __float2half_rn(v[c]);
        hh[c] = __half_as_ushort(x);
        ll[c] = __half_as_ushort(__float2half_rn(v[c] - __half2float(x)));
    }
    *(uint2*)(g_A6h + zo + i) = *(uint2*)hh;
    *(uint2*)(g_A6l + zo + i) = *(uint2*)ll;
}

// ---------------- batched W[K,N] -> W^T[N,K] fp16 hi/lo --------------------
__global__ void u_splitWt8(Ptr8f ws)
{
    __shared__ float tile[32][33];
    const size_t zo = (size_t)blockIdx.z * D * D;
    const float* W = ws.p[blockIdx.z];
    const int k0 = blockIdx.y * 32, n0 = blockIdx.x * 32;
    const int tx = threadIdx.x & 31, tw = threadIdx.x >> 5;
    for (int r = tw; r < 32; r += 8)
        tile[r][tx] = W[(size_t)(k0 + r) * D + n0 + tx];
    __syncthreads();
    for (int r = tw; r < 32; r += 8) {
        const float v = tile[tx][r];
        const __half hv = __float2half_rn(v);
        const size_t o = zo + (size_t)(n0 + r) * D + k0 + tx;
        g_W8h[o] = hv;
        g_W8l[o] = __float2half_rn(v - __half2float(hv));
    }
}

// ===================  double-buffered WMMA GEMM core  ======================
// MODE 1: aH*bH + aL*bH (2-term, drop B-lo; skips Bl prefetch)
// MODE 2: aH*bH + aH*bL (2-term, drop A-lo; skips Al prefetch)
constexpr int GP = 24;   // smem pitch (16 + 8 pad)

#define GEMM_PREFETCH(dstbuf, koff)                                            \
    _Pragma("unroll")                                                          \
    for (int i = 0; i < 4; i++) {                                              \
        const int c = tid + i * 256;                                           \
        const int mtx = c >> 8, rr = (c & 255) >> 1, col8 = (c & 1) * 8;       \
        const bool skip = (mode == 1 && mtx == 3) || (mode == 2 && mtx == 1);  \
        if (!skip)                                                             \
            CP16(&buf[dstbuf][mtx][rr * GP + col8],                            \
                 srcs[mtx] + (size_t)(baserow[mtx] + rr) * ldv + (koff) + col8); \
    }

#define GEMM_MAINLOOP(Ah, Al, Bh, Bl, LD, NITER, MODE)                         \
    const __half* srcs[4] = {Ah, Al, Bh, Bl};                                  \
    const int baserow[4] = {m0, m0, n0, n0};                                   \
    const int ldv = (LD);                                                      \
    const int mode = (MODE);                                                   \
    wmma::fragment<wmma::accumulator, 16, 16, 16, float> acc[4][2];            \
    _Pragma("unroll")                                                          \
    for (int mi = 0; mi < 4; mi++)                                             \
        _Pragma("unroll")                                                      \
        for (int nj = 0; nj < 2; nj++) wmma::fill_fragment(acc[mi][nj], 0.f);  \
    GEMM_PREFETCH(0, 0)                                                        \
    CP_COMMIT();                                                               \
    for (int kt = 0; kt < (NITER); kt++) {                                     \
        CP_WAIT(0);                                                            \
        __syncthreads();                                                       \
        if (kt + 1 < (NITER)) {                                                \
            const int bn = (kt + 1) & 1;                                       \
            GEMM_PREFETCH(bn, (kt + 1) * 16)                                   \
            CP_COMMIT();                                                       \
        }                                                                      \
        const __half* sAh = buf[kt & 1][0];                                    \
        const __half* sAl = buf[kt & 1][1];                                    \
        const __half* sBh = buf[kt & 1][2];                                    \
        const __half* sBl = buf[kt & 1][3];                                    \
        wmma::fragment<wmma::matrix_a, 16, 16, 16, __half, wmma::row_major> aH[4], aL[4]; \
        _Pragma("unroll")                                                      \
        for (int mi = 0; mi < 4; mi++) {                                       \
            const int row = warp_m * 64 + mi * 16;                             \
            wmma::load_matrix_sync(aH[mi], sAh + row * GP, GP);                \
            if (mode != 2) wmma::load_matrix_sync(aL[mi], sAl + row * GP, GP); \
        }                                                                      \
        _Pragma("unroll")                                                      \
        for (int nj = 0; nj < 2; nj++) {                                       \
            const int col = warp_n * 32 + nj * 16;                             \
            wmma::fragment<wmma::matrix_b, 16, 16, 16, __half, wmma::col_major> bH, bL; \
            wmma::load_matrix_sync(bH, sBh + col * GP, GP);                    \
            if (mode != 1) wmma::load_matrix_sync(bL, sBl + col * GP, GP);     \
            _Pragma("unroll")                                                  \
            for (int mi = 0; mi < 4; mi++) {                                   \
                wmma::mma_sync(acc[mi][nj], aH[mi], bH, acc[mi][nj]);          \
                if (mode != 1) wmma::mma_sync(acc[mi][nj], aH[mi], bL, acc[mi][nj]); \
                if (mode != 2) wmma::mma_sync(acc[mi][nj], aL[mi], bH, acc[mi][nj]); \
            }                                                                  \
        }                                                                      \
    }                                                                          \
    __syncthreads();

// ---------------- projection GEMM (z = 0..5), fused epilogue, all 2-term ----
// z: 0 qm, 1 qc(sqrt), 2 km, 3 kc(sqrt), 4 vm, 5 vc
__global__ void __launch_bounds__(256, 2) u_gemm_proj(Ptr6f biases)
{
    __shared__ __align__(16) __half buf[2][4][128 * GP];  // 48 KB
    const int z = blockIdx.z;
    const __half* Ah = g_A6h + (size_t)z * MR * D;
    const __half* Al = g_A6l + (size_t)z * MR * D;
    const __half* Bh = g_W8h + (size_t)z * D * D;
    const __half* Bl = g_W8l + (size_t)z * D * D;
    const float* bias = biases.p[z];
    const int tid = threadIdx.x, wid = tid >> 5, lane = tid & 31;
    const int m0 = blockIdx.y * 128, n0 = blockIdx.x * 128;
    const int warp_m = wid >> 2, warp_n = wid & 3;

    GEMM_MAINLOOP(Ah, Al, Bh, Bl, D, 32, 1)

    float* epi = (float*)buf + wid * 256;
#pragma unroll
    for (int mi = 0; mi < 4; mi++) {
#pragma unroll
        for (int nj = 0; nj < 2; nj++) {
            wmma::store_matrix_sync(epi, acc[mi][nj], 16, wmma::mem_row_major);
            __syncwarp();
            const int r  = lane >> 1;
            const int c0 = (lane & 1) * 8;
            const int m  = m0 + warp_m * 64 + mi * 16 + r;
            const int n  = n0 + warp_n * 32 + nj * 16 + c0;
            float v[8];
#pragma unroll
            for (int c = 0; c < 8; c++) v[c] = epi[r * 16 + c0 + c] + bias[n + c];
            const int b = m >> 10, s = m & (S - 1);
            const int h = n >> 6, d = n & 63;
            if (z < 4) {
                if (z & 1) {
                    float* raw = (z == 1) ? g_rawQc : g_rawKc;
                    const size_t ro = (((size_t)(b * H + h)) * S + s) * 64 + d;
                    *(float4*)(raw + ro)     = make_float4(v[0], v[1], v[2], v[3]);
                    *(float4*)(raw + ro + 4) = make_float4(v[4], v[5], v[6], v[7]);
#pragma unroll
                    for (int c = 0; c < 8; c++) v[c] = sqrtf(fmaxf(v[c], 1e-24f));
                }
                __half* dh = (z < 2) ? g_Qh : g_Kh;
                __half* dl = (z < 2) ? g_Ql : g_Kl;
                const size_t o = (((size_t)(b * H + h)) * S + s) * 128 + (z & 1) * 64 + d;
                uint4 uh, ul;
                pack8h(v, uh, ul);
                *(uint4*)(dh + o) = uh;
                *(uint4*)(dl + o) = ul;
            } else {
                __half* dv = (z == 4) ? g_Vm : g_Vc;
                __align__(16) unsigned short t[8];
#pragma unroll
                for (int c = 0; c < 8; c++) t[c] = __half_as_ushort(__float2half_rn(v[c]));
                const size_t o = (((size_t)(b * H + h)) * S + s) * 64 + d;
                *(uint4*)(dv + o) = *(uint4*)t;
            }
            __syncwarp();
        }
    }
}

// ---------------- output GEMM (z = 0 mean, 1 cov), 2-term ------------------
__global__ void __launch_bounds__(256, 2) u_gemm_out(const float* bias0, const float* bias1,
                                                     float* out)
{
    __shared__ __align__(16) __half buf[2][4][128 * GP];
    const int z = blockIdx.z;
    const __half* Ah = z ? g_cch : g_cmh;
    const __half* Al = z ? g_ccl : g_cml;
    const __half* Bh = g_W8h + (size_t)(6 + z) * D * D;
    const __half* Bl = g_W8l + (size_t)(6 + z) * D * D;
    const float* bias = z ? bias1 : bias0;
    const int tid = threadIdx.x, wid = tid >> 5, lane = tid & 31;
    const int m0 = blockIdx.y * 128, n0 = blockIdx.x * 128;
    const int warp_m = wid >> 2, warp_n = wid & 3;

    GEMM_MAINLOOP(Ah, Al, Bh, Bl, D, 32, 1)

    float* epi = (float*)buf + wid * 256;
    float* dstm = out + (size_t)z * MR * D;
#pragma unroll
    for (int mi = 0; mi < 4; mi++) {
#pragma unroll
        for (int nj = 0; nj < 2; nj++) {
            wmma::store_matrix_sync(epi, acc[mi][nj], 16, wmma::mem_row_major);
            __syncwarp();
            const int r  = lane >> 1;
            const int c0 = (lane & 1) * 8;
            const int m  = m0 + warp_m * 64 + mi * 16 + r;
            const int n  = n0 + warp_n * 32 + nj * 16 + c0;
            float v[8];
#pragma unroll
            for (int c = 0; c < 8; c++) v[c] = epi[r * 16 + c0 + c] + bias[n + c];
            float* dst = dstm + (size_t)m * D + n;
            *(float4*)(dst)     = make_float4(v[0], v[1], v[2], v[3]);
            *(float4*)(dst + 4) = make_float4(v[4], v[5], v[6], v[7]);
            __syncwarp();
        }
    }
}

// ---------------- exact row stats: tq = sum(qm^2) + sum(raw qc) ------------
__global__ void u_rownorm()
{
    const int row  = blockIdx.x * 8 + (threadIdx.x >> 5);
    const int lane = threadIdx.x & 31;
    const __half* ph = (blockIdx.y ? g_Kh : g_Qh) + (size_t)row * 128;
    const __half* pl = (blockIdx.y ? g_Kl : g_Ql) + (size_t)row * 128;
    const float* pc = (blockIdx.y ? g_rawKc : g_rawQc) + (size_t)row * DK;
    const float a0 = __half2float(ph[lane])      + __half2float(pl[lane]);
    const float a1 = __half2float(ph[lane + 32]) + __half2float(pl[lane + 32]);
    const float c0 = pc[lane], c1 = pc[lane + 32];
    float v = a0 * a0 + a1 * a1 + c0 + c1;
#pragma unroll
    for (int o = 16; o; o >>= 1) v += __shfl_xor_sync(~0u, v, o);
    if (lane == 0) (blockIdx.y ? g_tk : g_tq)[row] = v;
}

// ---------------- WMMA scores: 128x128 causal tiles, 2-term (drop Q-lo) ----
__global__ void __launch_bounds__(256, 2) u_scores_wmma()
{
    __shared__ __align__(16) __half buf[2][4][128 * GP];  // 48 KB
    const int bh = blockIdx.y;
    int tq = (int)((sqrtf(8.f * blockIdx.x + 1.f) - 1.f) * 0.5f);
    while ((tq + 1) * (tq + 2) / 2 <= (int)blockIdx.x) tq++;
    while (tq * (tq + 1) / 2 > (int)blockIdx.x) tq--;
    const int tk = blockIdx.x - tq * (tq + 1) / 2;
    const int qb = tq * 128, kb = tk * 128;

    const int tid = threadIdx.x, wid = tid >> 5, lane = tid & 31;
    const int warp_m = wid >> 2, warp_n = wid & 3;
    const int m0 = 0, n0 = 0;
    const __half* Qh = g_Qh + ((size_t)bh * S + qb) * 128;
    const __half* Ql = g_Ql + ((size_t)bh * S + qb) * 128;
    const __half* Kh = g_Kh + ((size_t)bh * S + kb) * 128;
    const __half* Kl = g_Kl + ((size_t)bh * S + kb) * 128;

    GEMM_MAINLOOP(Qh, Ql, Kh, Kl, 128, 8, 2)

    float* att = g_att + (size_t)bh * S * S;
    const float* tqv = g_tq + bh * S;
    const float* tkv = g_tk + bh * S;

    float* epi = (float*)buf + wid * 256;
#pragma unroll
    for (int mi = 0; mi < 4; mi++) {
#pragma unroll
        for (int nj = 0; nj < 2; nj++) {
            wmma::store_matrix_sync(epi, acc[mi][nj], 16, wmma::mem_row_major);
            __syncwarp();
            const int r  = lane >> 1;
            const int c0 = (lane & 1) * 8;
            const int q  = qb + warp_m * 64 + mi * 16 + r;
            const int k  = kb + warp_n * 32 + nj * 16 + c0;
            const float tq2 = tqv[q];
            float v[8];
#pragma unroll
            for (int c = 0; c < 8; c++)
                v[c] = 0.25f * epi[r * 16 + c0 + c] - 0.125f * (tq2 + tkv[k + c]);
            float* dst = att + (size_t)q * S + k;
            *(float4*)(dst)     = make_float4(v[0], v[1], v[2], v[3]);
            *(float4*)(dst + 4) = make_float4(v[4], v[5], v[6], v[7]);
            __syncwarp();
        }
    }
}

// ---------------- block reduction helpers ----------------------------------
__device__ __forceinline__ float u_blkmax(float v, float* red)
{
    const int lane = threadIdx.x & 31, wid = threadIdx.x >> 5;
#pragma unroll
    for (int o = 16; o; o >>= 1) v = fmaxf(v, __shfl_xor_sync(~0u, v, o));
    __syncthreads();
    if (lane == 0) red[wid] = v;
    __syncthreads();
    float r = red[0];
#pragma unroll
    for (int i = 1; i < 8; i++) r = fmaxf(r, red[i]);
    return r;
}
__device__ __forceinline__ float u_blksum(float v, float* red)
{
    const int lane = threadIdx.x & 31, wid = threadIdx.x >> 5;
#pragma unroll
    for (int o = 16; o; o >>= 1) v += __shfl_xor_sync(~0u, v, o);
    __syncthreads();
    if (lane == 0) red[wid] = v;
    __syncthreads();
    float r = red[0];
#pragma unroll
    for (int i = 1; i < 8; i++) r += red[i];
    return r;
}

// ---------------- fused softmax -> cumsum -> decay -> softmax --------------
// Writes prob and prob^2 as SINGLE fp16 planes.
__global__ void __launch_bounds__(256) u_decay(const float* __restrict__ gammas)
{
    const int q  = blockIdx.x;
    const int bh = blockIdx.y;
    const int L  = q + 1;
    const int Lr = (L + 127) & ~127;
    const int tid  = threadIdx.x;
    const int lane = tid & 31, wid = tid >> 5;
    const float* row = g_att + ((size_t)bh * S + q) * S;

    const float g = gammas[bh & (H - 1)];
    const float gamma = -log1pf(expf(g));

    __shared__ float red[8];
    __shared__ float wsum[8];
    __shared__ float shtot;

    const int base = tid * 4;
    float s[4] = {0.f, 0.f, 0.f, 0.f};
    if (base < L) {
        const float4 sv = *(const float4*)(row + base);
        s[0] = sv.x; s[1] = sv.y; s[2] = sv.z; s[3] = sv.w;
    }
    bool valid[4];
#pragma unroll
    for (int i = 0; i < 4; i++) valid[i] = (base + i) < L;

    float m = -3.402823466e+38f;
#pragma unroll
    for (int i = 0; i < 4; i++) if (valid[i]) m = fmaxf(m, s[i]);
    m = u_blkmax(m, red);

    float p[4], c[4];
    float run = 0.f;
#pragma unroll
    for (int i = 0; i < 4; i++) {
        p[i] = valid[i] ? expf(s[i] - m) : 0.f;
        run += p[i];
        c[i] = run;
    }

    float x = run;
#pragma unroll
    for (int o = 1; o < 32; o <<= 1) {
        const float y = __shfl_up_sync(~0u, x, o);
        if (lane >= o) x += y;
    }
    const float texcl = x - run;
    if (lane == 31) wsum[wid] = x;
    __syncthreads();
    if (wid == 0 && lane < 8) {
        float w = wsum[lane];
#pragma unroll
        for (int o = 1; o < 8; o <<= 1) {
            const float y = __shfl_up_sync(0xffu, w, o);
            if (lane >= o) w += y;
        }
        wsum[lane] = w;
        if (lane == 7) shtot = w;
    }
    __syncthreads();
    const float off  = texcl + (wid ? wsum[wid - 1] : 0.f);
    const float invT = 1.f / shtot;

    float l[4];
#pragma unroll
    for (int i = 0; i < 4; i++) {
        const float cum  = (c[i] + off) * invT;
        const float tail = fmaxf(1.f - cum, 0.f);
        const float pos  = (float)(q - (base + i));
        const float dist = sqrtf(tail * pos);
        float eff = expf(gamma * dist);
        eff = fminf(fmaxf(eff, 1e-5f), 1e5f);
        l[i] = s[i] * eff;
    }

    float m2 = -3.402823466e+38f;
#pragma unroll
    for (int i = 0; i < 4; i++) if (valid[i]) m2 = fmaxf(m2, l[i]);
    m2 = u_blkmax(m2, red);

    float e[4];
    float es = 0.f;
#pragma unroll
    for (int i = 0; i < 4; i++) {
        e[i] = valid[i] ? expf(l[i] - m2) : 0.f;
        es += e[i];
    }
    es = u_blksum(es, red);
    const float invE = 1.f / es;

    if (base < Lr) {
        __align__(8) unsigned short hh[4], h2[4];
#pragma unroll
        for (int i = 0; i < 4; i++) {
            const float pv = (q == 0) ? 0.f : e[i] * invE;
            hh[i] = __half_as_ushort(__float2half_rn(pv));
            h2[i] = __half_as_ushort(__float2half_rn(pv * pv));
        }
        const size_t pidx = ((size_t)bh * S + q) * S + base;
        *(uint2*)(g_sch + pidx) = *(uint2*)hh;
        *(uint2*)(g_s2h + pidx) = *(uint2*)h2;
    }
}

// ---------------- WMMA AV (1-term): mean = p@Vm, cov = p2@Vc ---------------
constexpr int AP  = 24;
constexpr int BPp = 72;

__global__ void __launch_bounds__(256, 2) u_av_wmma()
{
    __shared__ __align__(16) __half sA[2][2][128 * AP];
    __shared__ __align__(16) __half sB[2][2][16 * BPp];

    const int bh = blockIdx.y;
    const int qb = (7 - blockIdx.x) * 128;
    const int tid = threadIdx.x, wid = tid >> 5, lane = tid & 31;
    const int wg = wid >> 2, w4 = wid & 3;

    const size_t aoff = ((size_t)bh * S + qb) * S;
    const size_t vb   = (size_t)bh * S * DK;
    const __half* Ap[2] = {g_sch + aoff, g_s2h + aoff};
    const __half* Vp[2] = {g_Vm + vb, g_Vc + vb};

    wmma::fragment<wmma::accumulator, 16, 16, 16, float> acc[2][4];
#pragma unroll
    for (int mi = 0; mi < 2; mi++)
#pragma unroll
        for (int nj = 0; nj < 4; nj++) wmma::fill_fragment(acc[mi][nj], 0.f);

    const int NITER = (qb + 128) / 16;

#define AV_PREFETCH(bufi, kb)                                                  \
    _Pragma("unroll")                                                          \
    for (int i = 0; i < 2; i++) {                                              \
        const int c = tid + i * 256;                                           \
        const int pl = c >> 8, idx = c & 255;                                  \
        const int rr = idx >> 1, col8 = (idx & 1) * 8;                         \
        CP16(&sA[bufi][pl][rr * AP + col8], Ap[pl] + (size_t)rr * S + (kb) + col8); \
    }                                                                          \
    {                                                                          \
        const int mtx = tid >> 7, idx = tid & 127;                             \
        const int rr = idx >> 3, col8 = (idx & 7) * 8;                         \
        CP16(&sB[bufi][mtx][rr * BPp + col8], Vp[mtx] + (size_t)((kb) + rr) * DK + col8); \
    }

    AV_PREFETCH(0, 0)
    CP_COMMIT();

    for (int kt = 0; kt < NITER; kt++) {
        CP_WAIT(0);
        __syncthreads();
        if (kt + 1 < NITER) {
            const int bn = (kt + 1) & 1;
            AV_PREFETCH(bn, (kt + 1) * 16)
            CP_COMMIT();
        }
        const int cur = kt & 1;
        const __half* aPp = sA[cur][wg];
        const __half* bVp = sB[cur][wg];

        wmma::fragment<wmma::matrix_a, 16, 16, 16, __half, wmma::row_major> aP[2];
#pragma unroll
        for (int mi = 0; mi < 2; mi++) {
            const int row = w4 * 32 + mi * 16;
            wmma::load_matrix_sync(aP[mi], aPp + row * AP, AP);
        }
#pragma unroll
        for (int nj = 0; nj < 4; nj++) {
            wmma::fragment<wmma::matrix_b, 16, 16, 16, __half, wmma::row_major> bV;
            wmma::load_matrix_sync(bV, bVp + nj * 16, BPp);
#pragma unroll
            for (int mi = 0; mi < 2; mi++)
                wmma::mma_sync(acc[mi][nj], aP[mi], bV, acc[mi][nj]);
        }
    }
    __syncthreads();

    const int b = bh >> 3, h = bh & 7;
    __half* dh = wg ? g_cch : g_cmh;
    __half* dl = wg ? g_ccl : g_cml;
    float* epi = (float*)sA + wid * 256;
#pragma unroll
    for (int mi = 0; mi < 2; mi++) {
#pragma unroll
        for (int nj = 0; nj < 4; nj++) {
            wmma::store_matrix_sync(epi, acc[mi][nj], 16, wmma::mem_row_major);
            __syncwarp();
            const int r  = lane >> 1;
            const int c0 = (lane & 1) * 8;
            const int s  = qb + w4 * 32 + mi * 16 + r;
            const int d  = nj * 16 + c0;
            float v[8];
#pragma unroll
            for (int c = 0; c < 8; c++) v[c] = epi[r * 16 + c0 + c];
            uint4 uh, ul;
            pack8h(v, uh, ul);
            const size_t o = ((size_t)(b * S + s)) * D + h * DK + d;
            *(uint4*)(dh + o) = uh;
            *(uint4*)(dl + o) = ul;
            __syncwarp();
        }
    }
#undef AV_PREFETCH
}

// ---------------- host launcher --------------------------------------------
extern "C" void kernel_launch(void* const* d_in, const int* in_sizes, int n_in,
                              void* d_out, int out_size)
{
    const float* q_mean = (const float*)d_in[0];
    const float* q_cov  = (const float*)d_in[1];
    const float* k_mean = (const float*)d_in[2];
    const float* k_cov  = (const float*)d_in[3];
    const float* v_mean = (const float*)d_in[4];
    const float* v_cov  = (const float*)d_in[5];
    const float* Wqm = (const float*)d_in[6];  const float* bqm = (const float*)d_in[7];
    const float* Wqc = (const float*)d_in[8];  const float* bqc = (const float*)d_in[9];
    const float* Wkm = (const float*)d_in[10]; const float* bkm = (const float*)d_in[11];
    const float* Wkc = (const float*)d_in[12]; const float* bkc = (const float*)d_in[13];
    const float* Wvm = (const float*)d_in[14]; const float* bvm = (const float*)d_in[15];
    const float* Wvc = (const float*)d_in[16]; const float* bvc = (const float*)d_in[17];
    const float* Wom = (const float*)d_in[18]; const float* bom = (const float*)d_in[19];
    const float* Woc = (const float*)d_in[20]; const float* boc = (const float*)d_in[21];
    const float* gammas = (const float*)d_in[22];

    float* out = (float*)d_out;

    Ptr6f xs;   xs.p[0] = q_mean; xs.p[1] = q_cov; xs.p[2] = k_mean;
                xs.p[3] = k_cov;  xs.p[4] = v_mean; xs.p[5] = v_cov;
    Ptr8f ws;   ws.p[0] = Wqm; ws.p[1] = Wqc; ws.p[2] = Wkm; ws.p[3] = Wkc;
                ws.p[4] = Wvm; ws.p[5] = Wvc; ws.p[6] = Wom; ws.p[7] = Woc;
    Ptr6f bs;   bs.p[0] = bqm; bs.p[1] = bqc; bs.p[2] = bkm;
                bs.p[3] = bkc; bs.p[4] = bvm; bs.p[5] = bvc;

    u_split6  <<<dim3(MR * D / 1024, 1, 6), 256>>>(xs);
    u_splitWt8<<<dim3(D / 32, D / 32, 8), 256>>>(ws);
    u_gemm_proj<<<dim3(D / 128, MR / 128, 6), 256>>>(bs);
    u_rownorm <<<dim3(BHS / 8, 2), 256>>>();
    u_scores_wmma<<<dim3(36, BH), 256>>>();
    u_decay   <<<dim3(S, BH), 256>>>(gammas);
    u_av_wmma <<<dim3(S / 128, BH), 256>>>();
    u_gemm_out<<<dim3(D / 128, MR / 128, 2), 256>>>(bom, boc, out);
}